// round 1
// baseline (speedup 1.0000x reference)
#include <cuda_runtime.h>
#include <cstdint>

// ---------------- problem constants ----------------
#define NBR 4            // branches
#define BB  8            // batch
#define CC  8            // channels
#define NAA 128          // N*A
#define T0  200
#define T1  100
#define DD  200          // feature dim = 25 * 8
#define VV  8192         // codebook size
#define NQ  8            // rvq steps
#define ROWS (BB*NAA)    // 1024 rows per branch

#define N_Y1  (NBR*BB*CC*NAA*T0)   // 6,553,600
#define N_Y2  (NBR*BB*CC*NAA*T1)   // 3,276,800
#define N_FT  (NBR*ROWS*DD)        // 819,200
#define N_IDX (NBR*NQ*ROWS)        // 32,768

// ---------------- scratch (device globals: no allocation allowed) ----------------
__device__ float g_y1[N_Y1];
__device__ float g_y2[N_Y2];
__device__ float g_y3[N_Y2];
__device__ float g_stats1[NBR*BB*4*2];   // mean, rstd per (br,b,group)
__device__ float g_stats2[NBR*BB*4*2];
__device__ float g_feats[N_FT];
__device__ float g_res[N_FT];
__device__ float g_quant[N_FT];
__device__ float g_cnorm[NBR*NQ*VV];
__device__ unsigned long long g_best[NBR*ROWS];
__device__ int   g_idx[N_IDX];

// ---------------- helpers ----------------
__device__ __forceinline__ float gelu_exact(float v) {
    return 0.5f * v * (1.0f + erff(v * 0.70710678118654752440f));
}

__device__ __forceinline__ unsigned fkey(float f) {
    unsigned u = __float_as_uint(f);
    return (u & 0x80000000u) ? ~u : (u | 0x80000000u);
}

// ---------------- stage 1: conv1 (1 -> C, K taps along T, same pad) ----------------
__global__ void conv1_kernel(const float* __restrict__ x,
                             const float* __restrict__ w0, const float* __restrict__ w1,
                             const float* __restrict__ w2, const float* __restrict__ w3,
                             const float* __restrict__ b1,
                             int k0, int k1, int k2, int k3)
{
    int i = blockIdx.x * 256 + threadIdx.x;
    if (i >= N_Y1) return;
    int t  = i % T0;
    int na = (i / T0) % NAA;
    int c  = (i / (T0 * NAA)) % CC;
    int b  = (i / (T0 * NAA * CC)) % BB;
    int br = i / (T0 * NAA * CC * BB);

    const float* w; int K;
    if (br == 0)      { w = w0; K = k0; }
    else if (br == 1) { w = w1; K = k1; }
    else if (br == 2) { w = w2; K = k2; }
    else              { w = w3; K = k3; }
    int pad = (K - 1) >> 1;

    const float* xr = x + (size_t)(b * NAA + na) * T0;
    const float* wr = w + c * K;
    float acc = b1[br * CC + c];
    for (int k = 0; k < K; ++k) {
        int tt = t + k - pad;
        if (tt >= 0 && tt < T0) acc += xr[tt] * wr[k];
    }
    g_y1[i] = acc;
}

// ---------------- group norm stats (which=0 over y1/T0, which=1 over y3/T1) ----------------
__global__ void gn_stats_kernel(int which)
{
    int blk = blockIdx.x;               // (br*B + b)*4 + group
    int tid = threadIdx.x;
    int Tl = which ? T1 : T0;
    const float* src = which ? g_y3 : g_y1;
    float* stats = which ? g_stats2 : g_stats1;

    int gq = blk % 4;
    int bb = (blk / 4) % BB;
    int br = blk / (4 * BB);
    size_t base = ((size_t)((br * BB + bb) * CC) + 2 * gq) * NAA * Tl;
    int n = 2 * NAA * Tl;

    float s = 0.f, s2 = 0.f;
    for (int j = tid; j < n; j += 256) {
        float v = src[base + j];
        s += v; s2 += v * v;
    }
    __shared__ float sha[256], shb[256];
    sha[tid] = s; shb[tid] = s2;
    __syncthreads();
    for (int o = 128; o; o >>= 1) {
        if (tid < o) { sha[tid] += sha[tid + o]; shb[tid] += shb[tid + o]; }
        __syncthreads();
    }
    if (tid == 0) {
        float m = sha[0] / (float)n;
        float var = shb[0] / (float)n - m * m;
        stats[blk * 2]     = m;
        stats[blk * 2 + 1] = rsqrtf(var + 1e-5f);
    }
}

// ---------------- GN apply + gelu + avgpool(2) -> y2 ----------------
__global__ void act1_kernel(const float* __restrict__ g1, const float* __restrict__ be1)
{
    int i = blockIdx.x * 256 + threadIdx.x;
    if (i >= N_Y2) return;
    int t  = i % T1;
    int na = (i / T1) % NAA;
    int c  = (i / (T1 * NAA)) % CC;
    int b  = (i / (T1 * NAA * CC)) % BB;
    int br = i / (T1 * NAA * CC * BB);

    int sb = (br * BB + b) * 4 + (c >> 1);
    float m = g_stats1[sb * 2], r = g_stats1[sb * 2 + 1];
    float sc = r * g1[br * CC + c];
    float sh = be1[br * CC + c] - m * sc;

    size_t base = ((size_t)((br * BB + b) * CC + c) * NAA + na) * T0 + 2 * t;
    float a0 = gelu_exact(g_y1[base]     * sc + sh);
    float a1 = gelu_exact(g_y1[base + 1] * sc + sh);
    g_y2[i] = 0.5f * (a0 + a1);
}

// ---------------- conv2 (C -> C) ----------------
__global__ void conv2_kernel(const float* __restrict__ w0, const float* __restrict__ w1,
                             const float* __restrict__ w2, const float* __restrict__ w3,
                             const float* __restrict__ b2,
                             int k0, int k1, int k2, int k3)
{
    int i = blockIdx.x * 256 + threadIdx.x;
    if (i >= N_Y2) return;
    int t  = i % T1;
    int na = (i / T1) % NAA;
    int co = (i / (T1 * NAA)) % CC;
    int b  = (i / (T1 * NAA * CC)) % BB;
    int br = i / (T1 * NAA * CC * BB);

    const float* w; int K;
    if (br == 0)      { w = w0; K = k0; }
    else if (br == 1) { w = w1; K = k1; }
    else if (br == 2) { w = w2; K = k2; }
    else              { w = w3; K = k3; }
    int pad = (K - 1) >> 1;

    const float* y2b = g_y2 + (size_t)((br * BB + b) * CC) * NAA * T1;
    float acc = b2[br * CC + co];
    for (int ci = 0; ci < CC; ++ci) {
        const float* row = y2b + (size_t)(ci * NAA + na) * T1;
        const float* wr = w + (co * CC + ci) * K;
        for (int k = 0; k < K; ++k) {
            int tt = t + k - pad;
            if (tt >= 0 && tt < T1) acc += row[tt] * wr[k];
        }
    }
    g_y3[i] = acc;
}

// ---------------- GN2 apply + gelu + avgpool(4) + transpose -> feats/res, quant=0 ----------------
__global__ void feats_kernel(const float* __restrict__ g2, const float* __restrict__ be2)
{
    int i = blockIdx.x * 256 + threadIdx.x;
    if (i >= N_FT) return;
    int d  = i % DD;
    int na = (i / DD) % NAA;
    int b  = (i / (DD * NAA)) % BB;
    int br = i / (DD * NAA * BB);
    int t = d >> 3;
    int c = d & 7;

    int sb = (br * BB + b) * 4 + (c >> 1);
    float m = g_stats2[sb * 2], r = g_stats2[sb * 2 + 1];
    float sc = r * g2[br * CC + c];
    float sh = be2[br * CC + c] - m * sc;

    size_t base = ((size_t)((br * BB + b) * CC + c) * NAA + na) * T1 + 4 * t;
    float v = 0.25f * (gelu_exact(g_y3[base]     * sc + sh) +
                       gelu_exact(g_y3[base + 1] * sc + sh) +
                       gelu_exact(g_y3[base + 2] * sc + sh) +
                       gelu_exact(g_y3[base + 3] * sc + sh));
    g_feats[i] = v;
    g_res[i]   = v;
    g_quant[i] = 0.0f;
}

// ---------------- codebook squared norms (warp per code, coalesced) ----------------
__global__ void cnorm_kernel(const float* __restrict__ cbAll)
{
    int w = (blockIdx.x * 256 + threadIdx.x) >> 5;
    int lane = threadIdx.x & 31;
    if (w >= NBR * NQ * VV) return;
    const float* c = cbAll + (size_t)w * DD;
    float s = 0.f;
    for (int d = lane; d < DD; d += 32) { float v = c[d]; s += v * v; }
    #pragma unroll
    for (int o = 16; o; o >>= 1) s += __shfl_xor_sync(0xffffffffu, s, o);
    if (lane == 0) g_cnorm[w] = s;
}

__global__ void init_best_kernel()
{
    int i = blockIdx.x * 256 + threadIdx.x;
    if (i < NBR * ROWS) g_best[i] = 0xFFFFFFFFFFFFFFFFull;
}

// ---------------- distance GEMM + argmin ----------------
// 128x128 tile, BK=8, 256 threads, 8x8 per thread via f32x2 packed FMA.
// acc[p][j] holds rows (ty*8+2p, ty*8+2p+1) x col (colBase+tx+16j).
__global__ void __launch_bounds__(256, 2) dist_kernel(const float* __restrict__ cbAll, int step)
{
    int br = blockIdx.z;
    const float* __restrict__ cb = cbAll + (size_t)(br * NQ + step) * VV * DD;
    const float* __restrict__ cn = g_cnorm + (size_t)(br * NQ + step) * VV;
    const float* __restrict__ A  = g_res + (size_t)br * ROWS * DD;

    int rowBase = blockIdx.y * 128;
    int colBase = blockIdx.x * 128;

    __shared__ __align__(16) float As[8][128];
    __shared__ unsigned long long Bs[8][128];   // broadcast-duplicated pairs {b,b}

    int tid = threadIdx.x;
    int tx = tid & 15, ty = tid >> 4;
    int lr = tid >> 1;              // 0..127 (row/code within tile for loading)
    int lk = (tid & 1) * 4;         // 0 or 4

    unsigned long long acc[4][8];
    #pragma unroll
    for (int p = 0; p < 4; ++p)
        #pragma unroll
        for (int j = 0; j < 8; ++j) acc[p][j] = 0ull;

    const float* aPtr = A  + (size_t)(rowBase + lr) * DD + lk;
    const float* bPtr = cb + (size_t)(colBase + lr) * DD + lk;

    for (int kb = 0; kb < DD; kb += 8) {
        float4 av = *(const float4*)(aPtr + kb);
        float4 bv = *(const float4*)(bPtr + kb);
        __syncthreads();
        As[lk + 0][lr] = av.x;
        As[lk + 1][lr] = av.y;
        As[lk + 2][lr] = av.z;
        As[lk + 3][lr] = av.w;
        unsigned u;
        u = __float_as_uint(bv.x); Bs[lk + 0][lr] = ((unsigned long long)u << 32) | u;
        u = __float_as_uint(bv.y); Bs[lk + 1][lr] = ((unsigned long long)u << 32) | u;
        u = __float_as_uint(bv.z); Bs[lk + 2][lr] = ((unsigned long long)u << 32) | u;
        u = __float_as_uint(bv.w); Bs[lk + 3][lr] = ((unsigned long long)u << 32) | u;
        __syncthreads();
        #pragma unroll
        for (int k = 0; k < 8; ++k) {
            unsigned long long ap[4], bq[8];
            #pragma unroll
            for (int p = 0; p < 4; ++p)
                ap[p] = *(const unsigned long long*)&As[k][ty * 8 + 2 * p];
            #pragma unroll
            for (int j = 0; j < 8; ++j)
                bq[j] = Bs[k][tx + 16 * j];
            #pragma unroll
            for (int p = 0; p < 4; ++p)
                #pragma unroll
                for (int j = 0; j < 8; ++j)
                    asm("fma.rn.f32x2 %0, %1, %2, %0;"
                        : "+l"(acc[p][j]) : "l"(ap[p]), "l"(bq[j]));
        }
    }

    // dist = ||c||^2 - 2 * (r . c)   (||r||^2 is constant per row -> argmin unchanged)
    unsigned long long bestk[8];
    #pragma unroll
    for (int i = 0; i < 8; ++i) bestk[i] = 0xFFFFFFFFFFFFFFFFull;

    #pragma unroll
    for (int j = 0; j < 8; ++j) {
        int col = colBase + tx + 16 * j;
        float cnv = cn[col];
        #pragma unroll
        for (int p = 0; p < 4; ++p) {
            unsigned lo = (unsigned)(acc[p][j] & 0xFFFFFFFFull);
            unsigned hi = (unsigned)(acc[p][j] >> 32);
            float d0 = cnv - 2.0f * __uint_as_float(lo);
            float d1 = cnv - 2.0f * __uint_as_float(hi);
            unsigned long long k0 = ((unsigned long long)fkey(d0) << 32) | (unsigned)col;
            unsigned long long k1 = ((unsigned long long)fkey(d1) << 32) | (unsigned)col;
            if (k0 < bestk[2 * p])     bestk[2 * p]     = k0;
            if (k1 < bestk[2 * p + 1]) bestk[2 * p + 1] = k1;
        }
    }

    // reduce across the 16 tx lanes sharing the same 8 rows (width-16 butterfly)
    #pragma unroll
    for (int off = 8; off > 0; off >>= 1) {
        #pragma unroll
        for (int i = 0; i < 8; ++i) {
            unsigned long long o = __shfl_xor_sync(0xffffffffu, bestk[i], off, 16);
            if (o < bestk[i]) bestk[i] = o;
        }
    }
    if (tx == 0) {
        #pragma unroll
        for (int i = 0; i < 8; ++i)
            atomicMin(&g_best[br * ROWS + rowBase + ty * 8 + i], bestk[i]);
    }
}

// ---------------- gather winner, update residual/quant, record index ----------------
__global__ void update_kernel(const float* __restrict__ cbAll, int step)
{
    int row = blockIdx.x;
    int br  = blockIdx.y;
    unsigned long long best = g_best[br * ROWS + row];
    int idx = (int)(unsigned)(best & 0xFFFFFFFFull);
    const float* q = cbAll + ((size_t)(br * NQ + step) * VV + idx) * DD;
    size_t base = (size_t)(br * ROWS + row) * DD;
    for (int d = threadIdx.x; d < DD; d += 256) {
        float qv = q[d];
        g_res[base + d]   -= qv;
        g_quant[base + d] += qv;
    }
    if (threadIdx.x == 0) g_idx[(br * NQ + step) * ROWS + row] = idx;
}

// ---------------- final output: out = feats + (quant - feats), then idxs ----------------
__global__ void final_kernel(float* __restrict__ out, int n)
{
    int i = blockIdx.x * 256 + threadIdx.x;
    if (i >= n) return;
    if (i < N_FT) {
        float f = g_feats[i];
        out[i] = f + (g_quant[i] - f);
    } else {
        int j = i - N_FT;
        out[i] = (j < N_IDX) ? (float)g_idx[j] : 0.0f;
    }
}

// ---------------- launch ----------------
extern "C" void kernel_launch(void* const* d_in, const int* in_sizes, int n_in,
                              void* d_out, int out_size)
{
    const float* x   = (const float*)d_in[0];
    const float* w11 = (const float*)d_in[1];
    const float* w12 = (const float*)d_in[2];
    const float* w13 = (const float*)d_in[3];
    const float* w14 = (const float*)d_in[4];
    const float* b1  = (const float*)d_in[5];
    const float* g1  = (const float*)d_in[6];
    const float* be1 = (const float*)d_in[7];
    const float* w21 = (const float*)d_in[8];
    const float* w22 = (const float*)d_in[9];
    const float* w23 = (const float*)d_in[10];
    const float* w24 = (const float*)d_in[11];
    const float* b2  = (const float*)d_in[12];
    const float* g2  = (const float*)d_in[13];
    const float* be2 = (const float*)d_in[14];
    const float* cb  = (const float*)d_in[15];

    int K1a = in_sizes[1] / CC,  K1b = in_sizes[2] / CC;
    int K1c = in_sizes[3] / CC,  K1d = in_sizes[4] / CC;
    int K2a = in_sizes[8] / (CC * CC),  K2b = in_sizes[9] / (CC * CC);
    int K2c = in_sizes[10] / (CC * CC), K2d = in_sizes[11] / (CC * CC);

    conv1_kernel<<<(N_Y1 + 255) / 256, 256>>>(x, w11, w12, w13, w14, b1, K1a, K1b, K1c, K1d);
    gn_stats_kernel<<<NBR * BB * 4, 256>>>(0);
    act1_kernel<<<(N_Y2 + 255) / 256, 256>>>(g1, be1);
    conv2_kernel<<<(N_Y2 + 255) / 256, 256>>>(w21, w22, w23, w24, b2, K2a, K2b, K2c, K2d);
    gn_stats_kernel<<<NBR * BB * 4, 256>>>(1);
    feats_kernel<<<(N_FT + 255) / 256, 256>>>(g2, be2);

    cnorm_kernel<<<(NBR * NQ * VV * 32 + 255) / 256, 256>>>(cb);

    for (int s = 0; s < NQ; ++s) {
        init_best_kernel<<<(NBR * ROWS + 255) / 256, 256>>>();
        dim3 gdist(VV / 128, ROWS / 128, NBR);
        dist_kernel<<<gdist, 256>>>(cb, s);
        update_kernel<<<dim3(ROWS, NBR), 256>>>(cb, s);
    }

    final_kernel<<<(out_size + 255) / 256, 256>>>((float*)d_out, out_size);
}

// round 3
// speedup vs baseline: 1.1667x; 1.1667x over previous
#include <cuda_runtime.h>
#include <cstdint>

// ---------------- problem constants ----------------
#define NBR 4            // branches
#define BB  8            // batch
#define CC  8            // channels
#define NAA 128          // N*A
#define T0  200
#define T1  100
#define DD  200          // feature dim = 25 * 8
#define VV  8192         // codebook size
#define NQ  8            // rvq steps
#define ROWS (BB*NAA)    // 1024 rows per branch

#define N_Y1  (NBR*BB*CC*NAA*T0)   // 6,553,600
#define N_Y3  (NBR*BB*CC*NAA*T1)   // 3,276,800
#define N_FT  (NBR*ROWS*DD)        // 819,200
#define N_IDX (NBR*NQ*ROWS)        // 32,768

// ---------------- scratch (device globals: no allocation allowed) ----------------
__device__ float g_y1[N_Y1];
__device__ float g_y3[N_Y3];
__device__ float g_stats1[NBR*BB*4*2];   // mean, rstd per (br,b,group)
__device__ float g_stats2[NBR*BB*4*2];
__device__ float g_feats[N_FT];
__device__ float g_res[N_FT];
__device__ float g_quant[N_FT];
__device__ float g_cnorm[NBR*NQ*VV];
__device__ unsigned long long g_best[NBR*ROWS];
__device__ int   g_idx[N_IDX];

// ---------------- helpers ----------------
__device__ __forceinline__ float gelu_exact(float v) {
    return 0.5f * v * (1.0f + erff(v * 0.70710678118654752440f));
}

__device__ __forceinline__ unsigned fkey(float f) {
    unsigned u = __float_as_uint(f);
    return (u & 0x80000000u) ? ~u : (u | 0x80000000u);
}

// ---------------- codebook squared norms (warp per code) ----------------
__global__ void cnorm_kernel(const float* __restrict__ cbAll)
{
    int w = (blockIdx.x * 256 + threadIdx.x) >> 5;
    int lane = threadIdx.x & 31;
    if (w >= NBR * NQ * VV) return;
    const float* c = cbAll + (size_t)w * DD;
    float s = 0.f;
    for (int d = lane; d < DD; d += 32) { float v = c[d]; s += v * v; }
    #pragma unroll
    for (int o = 16; o; o >>= 1) s += __shfl_xor_sync(0xffffffffu, s, o);
    if (lane == 0) g_cnorm[w] = s;
}

// ---------------- conv1: one block per (br,b,na), no idiv ----------------
__global__ void conv1_kernel(const float* __restrict__ x,
                             const float* __restrict__ w0, const float* __restrict__ w1,
                             const float* __restrict__ w2, const float* __restrict__ w3,
                             const float* __restrict__ b1,
                             int k0, int k1, int k2, int k3)
{
    int na = blockIdx.x, b = blockIdx.y, br = blockIdx.z;
    int tid = threadIdx.x;

    const float* w; int K;
    if (br == 0)      { w = w0; K = k0; }
    else if (br == 1) { w = w1; K = k1; }
    else if (br == 2) { w = w2; K = k2; }
    else              { w = w3; K = k3; }
    int pad = (K - 1) >> 1;

    __shared__ float xs[T0];
    __shared__ float ws[CC * 24];
    if (tid < T0) xs[tid] = x[(size_t)(b * NAA + na) * T0 + tid];
    if (tid < CC * K) ws[tid] = w[tid];
    __syncthreads();

    if (tid >= T0) return;
    int t = tid;
    size_t outBase = (((size_t)(br * BB + b) * CC) * NAA + na) * T0 + t;
    #pragma unroll
    for (int c = 0; c < CC; ++c) {
        float acc = b1[br * CC + c];
        const float* wr = ws + c * K;
        for (int k = 0; k < K; ++k) {
            int tt = t + k - pad;
            if (tt >= 0 && tt < T0) acc += xs[tt] * wr[k];
        }
        g_y1[outBase + (size_t)c * NAA * T0] = acc;
    }
}

// ---------------- group norm stats ----------------
__global__ void gn_stats_kernel(int which)
{
    int blk = blockIdx.x;               // (br*B + b)*4 + group
    int tid = threadIdx.x;
    int Tl = which ? T1 : T0;
    const float* src = which ? g_y3 : g_y1;
    float* stats = which ? g_stats2 : g_stats1;

    int gq = blk & 3;
    int bb = (blk >> 2) & 7;
    int br = blk >> 5;
    size_t base = ((size_t)((br * BB + bb) * CC) + 2 * gq) * NAA * Tl;
    int n = 2 * NAA * Tl;

    float s = 0.f, s2 = 0.f;
    for (int j = tid; j < n; j += 256) {
        float v = src[base + j];
        s += v; s2 += v * v;
    }
    __shared__ float sha[256], shb[256];
    sha[tid] = s; shb[tid] = s2;
    __syncthreads();
    for (int o = 128; o; o >>= 1) {
        if (tid < o) { sha[tid] += sha[tid + o]; shb[tid] += shb[tid + o]; }
        __syncthreads();
    }
    if (tid == 0) {
        float m = sha[0] / (float)n;
        float var = shb[0] / (float)n - m * m;
        stats[blk * 2]     = m;
        stats[blk * 2 + 1] = rsqrtf(var + 1e-5f);
    }
}

// ---------------- conv2 fused with GN1+gelu+pool2; one block per (br,b,na) ----------------
__global__ void conv2_kernel(const float* __restrict__ w0, const float* __restrict__ w1,
                             const float* __restrict__ w2, const float* __restrict__ w3,
                             const float* __restrict__ b2,
                             const float* __restrict__ g1, const float* __restrict__ be1,
                             int k0, int k1, int k2, int k3)
{
    int na = blockIdx.x, b = blockIdx.y, br = blockIdx.z;
    int tid = threadIdx.x;

    const float* w; int K;
    if (br == 0)      { w = w0; K = k0; }
    else if (br == 1) { w = w1; K = k1; }
    else if (br == 2) { w = w2; K = k2; }
    else              { w = w3; K = k3; }
    int pad = (K - 1) >> 1;

    __shared__ float yin[CC][T1];
    __shared__ float ws[CC * CC * 12];

    for (int i = tid; i < CC * CC * K; i += 256) ws[i] = w[i];

    // stage A: GN1 + gelu + pool2 of y1 -> yin
    int hi = (tid >= 100) ? 1 : 0;
    int t  = tid - 100 * hi;
    bool act = (tid < 200);
    #pragma unroll
    for (int it = 0; it < 4; ++it) {
        int ci = 2 * it + hi;
        if (act) {
            int sb = (br * BB + b) * 4 + (ci >> 1);
            float m = g_stats1[sb * 2], r = g_stats1[sb * 2 + 1];
            float sc = r * g1[br * CC + ci];
            float sh = be1[br * CC + ci] - m * sc;
            size_t base = (((size_t)(br * BB + b) * CC + ci) * NAA + na) * T0 + 2 * t;
            float a0 = gelu_exact(g_y1[base]     * sc + sh);
            float a1 = gelu_exact(g_y1[base + 1] * sc + sh);
            yin[ci][t] = 0.5f * (a0 + a1);
        }
    }
    __syncthreads();

    // stage B: conv C->C
    #pragma unroll
    for (int it = 0; it < 4; ++it) {
        int co = 2 * it + hi;
        if (act) {
            float acc = b2[br * CC + co];
            for (int ci = 0; ci < CC; ++ci) {
                const float* wr = ws + (co * CC + ci) * K;
                for (int k = 0; k < K; ++k) {
                    int tt = t + k - pad;
                    if (tt >= 0 && tt < T1) acc += yin[ci][tt] * wr[k];
                }
            }
            g_y3[(((size_t)(br * BB + b) * CC + co) * NAA + na) * T1 + t] = acc;
        }
    }
}

// ---------------- GN2 + gelu + pool4 + transpose -> feats/res; init quant & best ----------------
__global__ void feats_kernel(const float* __restrict__ g2, const float* __restrict__ be2)
{
    int i = blockIdx.x * 256 + threadIdx.x;
    if (i >= N_FT) return;
    int d  = i % DD;
    int na = (i / DD) & (NAA - 1);
    int b  = (i / (DD * NAA)) & (BB - 1);
    int br = i / (DD * NAA * BB);
    int t = d >> 3;
    int c = d & 7;

    int sb = (br * BB + b) * 4 + (c >> 1);
    float m = g_stats2[sb * 2], r = g_stats2[sb * 2 + 1];
    float sc = r * g2[br * CC + c];
    float sh = be2[br * CC + c] - m * sc;

    size_t base = (((size_t)(br * BB + b) * CC + c) * NAA + na) * T1 + 4 * t;
    float v = 0.25f * (gelu_exact(g_y3[base]     * sc + sh) +
                       gelu_exact(g_y3[base + 1] * sc + sh) +
                       gelu_exact(g_y3[base + 2] * sc + sh) +
                       gelu_exact(g_y3[base + 3] * sc + sh));
    g_feats[i] = v;
    g_res[i]   = v;
    g_quant[i] = 0.0f;
    if (i < NBR * ROWS) g_best[i] = 0xFFFFFFFFFFFFFFFFull;
}

// ---------------- distance GEMM + argmin ----------------
// 128x128 tile, BK=8, 256 threads, 8x8 per thread via f32x2 packed FMA.
// Double-buffered smem with register-staged prefetch; ONE syncthreads per K-block.
// acc[p][j] holds rows (ty*8+2p, ty*8+2p+1) x col (colBase+tx+16j).
__global__ void __launch_bounds__(256, 2) dist_kernel(const float* __restrict__ cbAll, int step)
{
    int br = blockIdx.z;
    const float* __restrict__ cb = cbAll + (size_t)(br * NQ + step) * VV * DD;
    const float* __restrict__ cn = g_cnorm + (size_t)(br * NQ + step) * VV;
    const float* __restrict__ A  = g_res + (size_t)br * ROWS * DD;

    int rowBase = blockIdx.y * 128;
    int colBase = blockIdx.x * 128;

    __shared__ __align__(16) float As[2][8][128];
    __shared__ __align__(16) float Bs[2][8][128];

    int tid = threadIdx.x;
    int tx = tid & 15, ty = tid >> 4;
    int lr = tid >> 1;              // 0..127 tile row/code for loading
    int lk = (tid & 1) * 4;         // 0 or 4

    const float* aPtr = A  + (size_t)(rowBase + lr) * DD + lk;
    const float* bPtr = cb + (size_t)(colBase + lr) * DD + lk;

    // prologue: fill buffer 0
    {
        float4 av = *(const float4*)aPtr;
        float4 bv = *(const float4*)bPtr;
        As[0][lk + 0][lr] = av.x; As[0][lk + 1][lr] = av.y;
        As[0][lk + 2][lr] = av.z; As[0][lk + 3][lr] = av.w;
        Bs[0][lk + 0][lr] = bv.x; Bs[0][lk + 1][lr] = bv.y;
        Bs[0][lk + 2][lr] = bv.z; Bs[0][lk + 3][lr] = bv.w;
    }

    unsigned long long acc[4][8];
    #pragma unroll
    for (int p = 0; p < 4; ++p)
        #pragma unroll
        for (int j = 0; j < 8; ++j) acc[p][j] = 0ull;

    #pragma unroll 1
    for (int kb = 0; kb < 25; ++kb) {
        int buf = kb & 1;
        float4 av, bv;
        bool has = (kb + 1 < 25);
        if (has) {
            av = *(const float4*)(aPtr + (kb + 1) * 8);
            bv = *(const float4*)(bPtr + (kb + 1) * 8);
        }
        __syncthreads();
        #pragma unroll
        for (int k = 0; k < 8; ++k) {
            unsigned long long ap[4];
            #pragma unroll
            for (int p = 0; p < 4; ++p)
                ap[p] = *(const unsigned long long*)&As[buf][k][ty * 8 + 2 * p];
            #pragma unroll
            for (int jh = 0; jh < 2; ++jh) {
                unsigned long long bq[4];
                #pragma unroll
                for (int j4 = 0; j4 < 4; ++j4) {
                    unsigned u = __float_as_uint(Bs[buf][k][tx + 16 * (jh * 4 + j4)]);
                    bq[j4] = ((unsigned long long)u << 32) | u;
                }
                #pragma unroll
                for (int p = 0; p < 4; ++p)
                    #pragma unroll
                    for (int j4 = 0; j4 < 4; ++j4)
                        asm("fma.rn.f32x2 %0, %1, %2, %0;"
                            : "+l"(acc[p][jh * 4 + j4]) : "l"(ap[p]), "l"(bq[j4]));
            }
        }
        if (has) {
            int nb = buf ^ 1;
            As[nb][lk + 0][lr] = av.x; As[nb][lk + 1][lr] = av.y;
            As[nb][lk + 2][lr] = av.z; As[nb][lk + 3][lr] = av.w;
            Bs[nb][lk + 0][lr] = bv.x; Bs[nb][lk + 1][lr] = bv.y;
            Bs[nb][lk + 2][lr] = bv.z; Bs[nb][lk + 3][lr] = bv.w;
        }
    }

    // dist = ||c||^2 - 2 * (r . c)   (||r||^2 constant per row -> argmin unchanged)
    unsigned long long bestk[8];
    #pragma unroll
    for (int i = 0; i < 8; ++i) bestk[i] = 0xFFFFFFFFFFFFFFFFull;

    #pragma unroll
    for (int j = 0; j < 8; ++j) {
        int col = colBase + tx + 16 * j;
        float cnv = cn[col];
        #pragma unroll
        for (int p = 0; p < 4; ++p) {
            unsigned lo = (unsigned)(acc[p][j] & 0xFFFFFFFFull);
            unsigned hi = (unsigned)(acc[p][j] >> 32);
            float d0 = cnv - 2.0f * __uint_as_float(lo);
            float d1 = cnv - 2.0f * __uint_as_float(hi);
            unsigned long long k0 = ((unsigned long long)fkey(d0) << 32) | (unsigned)col;
            unsigned long long k1 = ((unsigned long long)fkey(d1) << 32) | (unsigned)col;
            if (k0 < bestk[2 * p])     bestk[2 * p]     = k0;
            if (k1 < bestk[2 * p + 1]) bestk[2 * p + 1] = k1;
        }
    }

    #pragma unroll
    for (int off = 8; off > 0; off >>= 1) {
        #pragma unroll
        for (int i = 0; i < 8; ++i) {
            unsigned long long o = __shfl_xor_sync(0xffffffffu, bestk[i], off, 16);
            if (o < bestk[i]) bestk[i] = o;
        }
    }
    if (tx == 0) {
        #pragma unroll
        for (int i = 0; i < 8; ++i)
            atomicMin(&g_best[br * ROWS + rowBase + ty * 8 + i], bestk[i]);
    }
}

// ---------------- gather winner, update residual/quant, record index, reset best ----------------
__global__ void update_kernel(const float* __restrict__ cbAll, int step)
{
    int row = blockIdx.x;
    int br  = blockIdx.y;
    unsigned long long best = g_best[br * ROWS + row];
    int idx = (int)(unsigned)(best & 0xFFFFFFFFull);
    const float* q = cbAll + ((size_t)(br * NQ + step) * VV + idx) * DD;
    size_t base = (size_t)(br * ROWS + row) * DD;
    int d = threadIdx.x;
    if (d < DD) {
        float qv = q[d];
        g_res[base + d]   -= qv;
        g_quant[base + d] += qv;
    }
    if (threadIdx.x == 0) {
        g_idx[(br * NQ + step) * ROWS + row] = idx;
        g_best[br * ROWS + row] = 0xFFFFFFFFFFFFFFFFull;   // ready for next step
    }
}

// ---------------- final output: out = feats + (quant - feats), then idxs ----------------
__global__ void final_kernel(float* __restrict__ out, int n)
{
    int i = blockIdx.x * 256 + threadIdx.x;
    if (i >= n) return;
    if (i < N_FT) {
        float f = g_feats[i];
        out[i] = f + (g_quant[i] - f);
    } else {
        int j = i - N_FT;
        out[i] = (j < N_IDX) ? (float)g_idx[j] : 0.0f;
    }
}

// ---------------- launch ----------------
extern "C" void kernel_launch(void* const* d_in, const int* in_sizes, int n_in,
                              void* d_out, int out_size)
{
    const float* x   = (const float*)d_in[0];
    const float* w11 = (const float*)d_in[1];
    const float* w12 = (const float*)d_in[2];
    const float* w13 = (const float*)d_in[3];
    const float* w14 = (const float*)d_in[4];
    const float* b1  = (const float*)d_in[5];
    const float* g1  = (const float*)d_in[6];
    const float* be1 = (const float*)d_in[7];
    const float* w21 = (const float*)d_in[8];
    const float* w22 = (const float*)d_in[9];
    const float* w23 = (const float*)d_in[10];
    const float* w24 = (const float*)d_in[11];
    const float* b2  = (const float*)d_in[12];
    const float* g2  = (const float*)d_in[13];
    const float* be2 = (const float*)d_in[14];
    const float* cb  = (const float*)d_in[15];

    int K1a = in_sizes[1] / CC,  K1b = in_sizes[2] / CC;
    int K1c = in_sizes[3] / CC,  K1d = in_sizes[4] / CC;
    int K2a = in_sizes[8] / (CC * CC),  K2b = in_sizes[9] / (CC * CC);
    int K2c = in_sizes[10] / (CC * CC), K2d = in_sizes[11] / (CC * CC);

    cnorm_kernel<<<(NBR * NQ * VV) / 8, 256>>>(cb);

    conv1_kernel<<<dim3(NAA, BB, NBR), 256>>>(x, w11, w12, w13, w14, b1, K1a, K1b, K1c, K1d);
    gn_stats_kernel<<<NBR * BB * 4, 256>>>(0);
    conv2_kernel<<<dim3(NAA, BB, NBR), 256>>>(w21, w22, w23, w24, b2, g1, be1, K2a, K2b, K2c, K2d);
    gn_stats_kernel<<<NBR * BB * 4, 256>>>(1);
    feats_kernel<<<(N_FT + 255) / 256, 256>>>(g2, be2);

    for (int s = 0; s < NQ; ++s) {
        dim3 gdist(VV / 128, ROWS / 128, NBR);
        dist_kernel<<<gdist, 256>>>(cb, s);
        update_kernel<<<dim3(ROWS, NBR), 224>>>(cb, s);
    }

    final_kernel<<<(out_size + 255) / 256, 256>>>((float*)d_out, out_size);
}

// round 5
// speedup vs baseline: 1.4247x; 1.2211x over previous
#include <cuda_runtime.h>
#include <cuda_bf16.h>
#include <cstdint>

// ---------------- problem constants ----------------
#define NBR 4
#define BB  8
#define CC  8
#define NAA 128
#define T0  200
#define T1  100
#define DD  200
#define VV  8192
#define NQ  8
#define ROWS (BB*NAA)        // 1024

#define N_Y1  (NBR*BB*CC*NAA*T0)
#define N_Y3  (NBR*BB*CC*NAA*T1)
#define N_FT  (NBR*ROWS*DD)
#define N_IDX (NBR*NQ*ROWS)

#define KPAD 256             // padded K (bf16)
#define KC   32              // K chunk
#define NCH  (KPAD/KC)       // 8 chunks
#define NT   128             // codes per col tile
#define NTILES (VV/NT)       // 64
#define RERANK_DELTA 0.05f

// smem slab: one array = 128 rows x 32 bf16, padded to 40 bf16 (80B) per row
#define SLAB_B 10240         // 128*80
#define BUF_B  (4*SLAB_B)    // a_hi, a_lo, b_hi, b_lo
#define DSMEM  (2*BUF_B)     // double buffered = 81920

// ---------------- scratch ----------------
__device__ float g_y1[N_Y1];
__device__ float g_y3[N_Y3];
__device__ float g_stats1[NBR*BB*4*2];
__device__ float g_stats2[NBR*BB*4*2];
__device__ float g_feats[N_FT];
__device__ float g_res[N_FT];
__device__ float g_quant[N_FT];
__device__ float g_cnorm[NBR*NQ*VV];
__device__ int   g_idx[N_IDX];
__device__ uint32_t g_cbh[(size_t)NBR*NQ*VV*(KPAD/2)];   // bf16 hi image, row-major [code][KPAD]
__device__ uint32_t g_cbl[(size_t)NBR*NQ*VV*(KPAD/2)];   // bf16 lo image
__device__ __nv_bfloat16 g_res_hi[NBR*ROWS*KPAD];        // zero-init pads stay zero
__device__ __nv_bfloat16 g_res_lo[NBR*ROWS*KPAD];
__device__ unsigned long long g_cand[(size_t)NBR*ROWS*NTILES*2];

// ---------------- helpers ----------------
__device__ __forceinline__ float gelu_exact(float v) {
    return 0.5f * v * (1.0f + erff(v * 0.70710678118654752440f));
}
__device__ __forceinline__ unsigned fkey(float f) {
    unsigned u = __float_as_uint(f);
    return (u & 0x80000000u) ? ~u : (u | 0x80000000u);
}
__device__ __forceinline__ float fkey_inv(unsigned k) {
    unsigned u = (k & 0x80000000u) ? (k & 0x7FFFFFFFu) : ~k;
    return __uint_as_float(u);
}
__device__ __forceinline__ uint32_t smem_u32(const void* p) {
    uint32_t a;
    asm("{ .reg .u64 t; cvta.to.shared.u64 t, %1; cvt.u32.u64 %0, t; }" : "=r"(a) : "l"(p));
    return a;
}
#define CP_ASYNC16(dst, src) \
    asm volatile("cp.async.cg.shared.global [%0], [%1], 16;" :: "r"(dst), "l"(src))
#define CP_COMMIT() asm volatile("cp.async.commit_group;" ::: "memory")
#define CP_WAIT(n)  asm volatile("cp.async.wait_group %0;" :: "n"(n) : "memory")

__device__ __forceinline__ void mma_bf16(float* c,
    uint32_t a0, uint32_t a1, uint32_t a2, uint32_t a3, uint32_t b0, uint32_t b1)
{
    asm volatile("mma.sync.aligned.m16n8k16.row.col.f32.bf16.bf16.f32 "
        "{%0,%1,%2,%3}, {%4,%5,%6,%7}, {%8,%9}, {%0,%1,%2,%3};"
        : "+f"(c[0]), "+f"(c[1]), "+f"(c[2]), "+f"(c[3])
        : "r"(a0), "r"(a1), "r"(a2), "r"(a3), "r"(b0), "r"(b1));
}

// ---------------- codebook norms ----------------
__global__ void cnorm_kernel(const float* __restrict__ cbAll)
{
    int w = (blockIdx.x * 256 + threadIdx.x) >> 5;
    int lane = threadIdx.x & 31;
    if (w >= NBR * NQ * VV) return;
    const float* c = cbAll + (size_t)w * DD;
    float s = 0.f;
    for (int d = lane; d < DD; d += 32) { float v = c[d]; s += v * v; }
    #pragma unroll
    for (int o = 16; o; o >>= 1) s += __shfl_xor_sync(0xffffffffu, s, o);
    if (lane == 0) g_cnorm[w] = s;
}

// ---------------- pack codebooks to bf16 hi/lo (plain row-major, K padded) ----------------
__global__ void pack_cb_kernel(const float* __restrict__ cbAll)
{
    unsigned u = blockIdx.x * 256 + threadIdx.x;      // one u32 (2 bf16) output
    int kk = (u & 127) * 2;
    unsigned cg = u >> 7;                             // (br*NQ+q)*VV + code

    float v0 = 0.f, v1 = 0.f;
    if (kk < DD) {
        const float* s = cbAll + (size_t)cg * DD + kk;
        v0 = s[0]; v1 = s[1];
    }
    __nv_bfloat16 h0 = __float2bfloat16(v0), h1 = __float2bfloat16(v1);
    __nv_bfloat16 l0 = __float2bfloat16(v0 - __bfloat162float(h0));
    __nv_bfloat16 l1 = __float2bfloat16(v1 - __bfloat162float(h1));
    g_cbh[u] = ((uint32_t)__bfloat16_as_ushort(h1) << 16) | __bfloat16_as_ushort(h0);
    g_cbl[u] = ((uint32_t)__bfloat16_as_ushort(l1) << 16) | __bfloat16_as_ushort(l0);
}

// ---------------- conv1 ----------------
__global__ void conv1_kernel(const float* __restrict__ x,
                             const float* __restrict__ w0, const float* __restrict__ w1,
                             const float* __restrict__ w2, const float* __restrict__ w3,
                             const float* __restrict__ b1,
                             int k0, int k1, int k2, int k3)
{
    int na = blockIdx.x, b = blockIdx.y, br = blockIdx.z;
    int tid = threadIdx.x;

    const float* w; int K;
    if (br == 0)      { w = w0; K = k0; }
    else if (br == 1) { w = w1; K = k1; }
    else if (br == 2) { w = w2; K = k2; }
    else              { w = w3; K = k3; }
    int pad = (K - 1) >> 1;

    __shared__ float xs[T0];
    __shared__ float ws[CC * 24];
    if (tid < T0) xs[tid] = x[(size_t)(b * NAA + na) * T0 + tid];
    if (tid < CC * K) ws[tid] = w[tid];
    __syncthreads();

    if (tid >= T0) return;
    int t = tid;
    size_t outBase = (((size_t)(br * BB + b) * CC) * NAA + na) * T0 + t;
    #pragma unroll
    for (int c = 0; c < CC; ++c) {
        float acc = b1[br * CC + c];
        const float* wr = ws + c * K;
        for (int k = 0; k < K; ++k) {
            int tt = t + k - pad;
            if (tt >= 0 && tt < T0) acc += xs[tt] * wr[k];
        }
        g_y1[outBase + (size_t)c * NAA * T0] = acc;
    }
}

// ---------------- group norm stats ----------------
__global__ void gn_stats_kernel(int which)
{
    int blk = blockIdx.x;
    int tid = threadIdx.x;
    int Tl = which ? T1 : T0;
    const float* src = which ? g_y3 : g_y1;
    float* stats = which ? g_stats2 : g_stats1;

    int gq = blk & 3;
    int bb = (blk >> 2) & 7;
    int br = blk >> 5;
    size_t base = ((size_t)((br * BB + bb) * CC) + 2 * gq) * NAA * Tl;
    int n = 2 * NAA * Tl;

    float s = 0.f, s2 = 0.f;
    for (int j = tid; j < n; j += 256) {
        float v = src[base + j];
        s += v; s2 += v * v;
    }
    __shared__ float sha[256], shb[256];
    sha[tid] = s; shb[tid] = s2;
    __syncthreads();
    for (int o = 128; o; o >>= 1) {
        if (tid < o) { sha[tid] += sha[tid + o]; shb[tid] += shb[tid + o]; }
        __syncthreads();
    }
    if (tid == 0) {
        float m = sha[0] / (float)n;
        float var = shb[0] / (float)n - m * m;
        stats[blk * 2]     = m;
        stats[blk * 2 + 1] = rsqrtf(var + 1e-5f);
    }
}

// ---------------- conv2 fused with GN1+gelu+pool2 ----------------
__global__ void conv2_kernel(const float* __restrict__ w0, const float* __restrict__ w1,
                             const float* __restrict__ w2, const float* __restrict__ w3,
                             const float* __restrict__ b2,
                             const float* __restrict__ g1, const float* __restrict__ be1,
                             int k0, int k1, int k2, int k3)
{
    int na = blockIdx.x, b = blockIdx.y, br = blockIdx.z;
    int tid = threadIdx.x;

    const float* w; int K;
    if (br == 0)      { w = w0; K = k0; }
    else if (br == 1) { w = w1; K = k1; }
    else if (br == 2) { w = w2; K = k2; }
    else              { w = w3; K = k3; }
    int pad = (K - 1) >> 1;

    __shared__ float yin[CC][T1];
    __shared__ float ws[CC * CC * 12];

    for (int i = tid; i < CC * CC * K; i += 256) ws[i] = w[i];

    int hi = (tid >= 100) ? 1 : 0;
    int t  = tid - 100 * hi;
    bool act = (tid < 200);
    #pragma unroll
    for (int it = 0; it < 4; ++it) {
        int ci = 2 * it + hi;
        if (act) {
            int sb = (br * BB + b) * 4 + (ci >> 1);
            float m = g_stats1[sb * 2], r = g_stats1[sb * 2 + 1];
            float sc = r * g1[br * CC + ci];
            float sh = be1[br * CC + ci] - m * sc;
            size_t base = (((size_t)(br * BB + b) * CC + ci) * NAA + na) * T0 + 2 * t;
            float a0 = gelu_exact(g_y1[base]     * sc + sh);
            float a1 = gelu_exact(g_y1[base + 1] * sc + sh);
            yin[ci][t] = 0.5f * (a0 + a1);
        }
    }
    __syncthreads();

    #pragma unroll
    for (int it = 0; it < 4; ++it) {
        int co = 2 * it + hi;
        if (act) {
            float acc = b2[br * CC + co];
            for (int ci = 0; ci < CC; ++ci) {
                const float* wr = ws + (co * CC + ci) * K;
                for (int k = 0; k < K; ++k) {
                    int tt = t + k - pad;
                    if (tt >= 0 && tt < T1) acc += yin[ci][tt] * wr[k];
                }
            }
            g_y3[(((size_t)(br * BB + b) * CC + co) * NAA + na) * T1 + t] = acc;
        }
    }
}

// ---------------- feats: GN2+gelu+pool4+transpose; init res/quant + bf16 hi/lo ----------------
__global__ void feats_kernel(const float* __restrict__ g2, const float* __restrict__ be2)
{
    int i = blockIdx.x * 256 + threadIdx.x;
    if (i >= N_FT) return;
    int d  = i % DD;
    int na = (i / DD) & (NAA - 1);
    int b  = (i / (DD * NAA)) & (BB - 1);
    int br = i / (DD * NAA * BB);
    int t = d >> 3;
    int c = d & 7;

    int sb = (br * BB + b) * 4 + (c >> 1);
    float m = g_stats2[sb * 2], r = g_stats2[sb * 2 + 1];
    float sc = r * g2[br * CC + c];
    float sh = be2[br * CC + c] - m * sc;

    size_t base = (((size_t)(br * BB + b) * CC + c) * NAA + na) * T1 + 4 * t;
    float v = 0.25f * (gelu_exact(g_y3[base]     * sc + sh) +
                       gelu_exact(g_y3[base + 1] * sc + sh) +
                       gelu_exact(g_y3[base + 2] * sc + sh) +
                       gelu_exact(g_y3[base + 3] * sc + sh));
    g_feats[i] = v;
    g_res[i]   = v;
    g_quant[i] = 0.0f;

    int row = b * NAA + na;
    __nv_bfloat16 h = __float2bfloat16(v);
    __nv_bfloat16 l = __float2bfloat16(v - __bfloat162float(h));
    size_t pb = ((size_t)((br << 10) + row)) * KPAD + d;
    g_res_hi[pb] = h;
    g_res_lo[pb] = l;
}

// ---------------- mma.sync distance GEMM + per-tile top-2 epilogue ----------------
// grid (8 rowtiles, 4 br, 64 coltiles), block 256 (8 warps, warpM x warpN = 2x4),
// warp tile 64x32, K streamed in 8 chunks of 32 via cp.async double buffering.
__global__ void __launch_bounds__(256) gemm_step_kernel(int step)
{
    extern __shared__ char dsm[];
    __shared__ float cns[NT];

    int tid = threadIdx.x;
    int lane = tid & 31;
    int wid = tid >> 5;
    int warpM = wid & 1;      // 0..1
    int warpN = wid >> 1;     // 0..3
    int g  = lane >> 2;       // 0..7
    int tig = lane & 3;       // 0..3

    int rowBase = blockIdx.x * 128;
    int br = blockIdx.y;
    int ct = blockIdx.z;
    int brq = br * NQ + step;

    const __nv_bfloat16* aH = g_res_hi + (size_t)((br << 10) + rowBase) * KPAD;
    const __nv_bfloat16* aL = g_res_lo + (size_t)((br << 10) + rowBase) * KPAD;
    const __nv_bfloat16* bH = (const __nv_bfloat16*)g_cbh + ((size_t)brq * VV + (size_t)ct * NT) * KPAD;
    const __nv_bfloat16* bL = (const __nv_bfloat16*)g_cbl + ((size_t)brq * VV + (size_t)ct * NT) * KPAD;

    if (tid < NT) cns[tid] = g_cnorm[(size_t)brq * VV + ct * NT + tid];

    // async load of one chunk (4 slabs) into buffer buf
    auto load_chunk = [&](int buf, int k0) {
        char* base = dsm + buf * BUF_B;
        #pragma unroll
        for (int s = 0; s < 4; ++s) {
            const __nv_bfloat16* gp = (s == 0) ? aH : (s == 1) ? aL : (s == 2) ? bH : bL;
            char* sb = base + s * SLAB_B;
            #pragma unroll
            for (int h = 0; h < 2; ++h) {
                int i = tid + h * 256;
                int row = i >> 2, seg = i & 3;
                uint32_t dst = smem_u32(sb + row * 80 + seg * 16);
                const void* src = gp + (size_t)row * KPAD + k0 + seg * 8;
                CP_ASYNC16(dst, src);
            }
        }
        CP_COMMIT();
    };

    float acc[4][4][4];
    #pragma unroll
    for (int t = 0; t < 4; ++t)
        #pragma unroll
        for (int n = 0; n < 4; ++n)
            #pragma unroll
            for (int e = 0; e < 4; ++e) acc[t][n][e] = 0.f;

    load_chunk(0, 0);

    #pragma unroll 1
    for (int c = 0; c < NCH; ++c) {
        if (c + 1 < NCH) { load_chunk((c + 1) & 1, (c + 1) * KC); CP_WAIT(1); }
        else             { CP_WAIT(0); }
        __syncthreads();

        const char* base = dsm + (c & 1) * BUF_B;
        const char* aHs = base;
        const char* aLs = base + SLAB_B;
        const char* bHs = base + 2 * SLAB_B;
        const char* bLs = base + 3 * SLAB_B;

        #pragma unroll
        for (int k16 = 0; k16 < 2; ++k16) {
            uint32_t ah[4][4], al[4][4];
            #pragma unroll
            for (int t = 0; t < 4; ++t) {
                int r0 = warpM * 64 + t * 16 + g;
                const char* pa = aHs + r0 * 80 + k16 * 32 + tig * 4;
                ah[t][0] = *(const uint32_t*)pa;
                ah[t][1] = *(const uint32_t*)(pa + 8 * 80);
                ah[t][2] = *(const uint32_t*)(pa + 16);
                ah[t][3] = *(const uint32_t*)(pa + 8 * 80 + 16);
                const char* pb = aLs + r0 * 80 + k16 * 32 + tig * 4;
                al[t][0] = *(const uint32_t*)pb;
                al[t][1] = *(const uint32_t*)(pb + 8 * 80);
                al[t][2] = *(const uint32_t*)(pb + 16);
                al[t][3] = *(const uint32_t*)(pb + 8 * 80 + 16);
            }
            uint32_t bh[4][2], bl[4][2];
            #pragma unroll
            for (int n = 0; n < 4; ++n) {
                int c0 = warpN * 32 + n * 8 + g;
                const char* pb = bHs + c0 * 80 + k16 * 32 + tig * 4;
                bh[n][0] = *(const uint32_t*)pb;
                bh[n][1] = *(const uint32_t*)(pb + 16);
                const char* pc = bLs + c0 * 80 + k16 * 32 + tig * 4;
                bl[n][0] = *(const uint32_t*)pc;
                bl[n][1] = *(const uint32_t*)(pc + 16);
            }
            #pragma unroll
            for (int t = 0; t < 4; ++t)
                #pragma unroll
                for (int n = 0; n < 4; ++n) {
                    mma_bf16(acc[t][n], ah[t][0], ah[t][1], ah[t][2], ah[t][3], bh[n][0], bh[n][1]);
                    mma_bf16(acc[t][n], al[t][0], al[t][1], al[t][2], al[t][3], bh[n][0], bh[n][1]);
                    mma_bf16(acc[t][n], ah[t][0], ah[t][1], ah[t][2], ah[t][3], bl[n][0], bl[n][1]);
                }
        }
        __syncthreads();
    }

    // ---- epilogue: per-row top-2 across the 128-code tile ----
    unsigned long long* red = (unsigned long long*)dsm;   // [128][4][2], reuses buffer 0 region

    #pragma unroll
    for (int t = 0; t < 4; ++t) {
        #pragma unroll
        for (int rs = 0; rs < 2; ++rs) {
            unsigned long long k1 = ~0ull, k2 = ~0ull;
            #pragma unroll
            for (int n = 0; n < 4; ++n) {
                int lc = warpN * 32 + n * 8 + tig * 2;
                int gc = ct * NT + lc;
                float d0 = cns[lc]     - 2.0f * acc[t][n][rs * 2 + 0];
                float d1 = cns[lc + 1] - 2.0f * acc[t][n][rs * 2 + 1];
                unsigned long long ka = ((unsigned long long)fkey(d0) << 32) | (unsigned)gc;
                unsigned long long kb = ((unsigned long long)fkey(d1) << 32) | (unsigned)(gc + 1);
                if (ka < k1) { k2 = k1; k1 = ka; } else if (ka < k2) k2 = ka;
                if (kb < k1) { k2 = k1; k1 = kb; } else if (kb < k2) k2 = kb;
            }
            // reduce across the 4 lanes of the quad (same row, different cols)
            #pragma unroll
            for (int off = 1; off <= 2; off <<= 1) {
                unsigned long long o1 = __shfl_xor_sync(0xffffffffu, k1, off);
                unsigned long long o2 = __shfl_xor_sync(0xffffffffu, k2, off);
                unsigned long long n1 = (k1 < o1) ? k1 : o1;
                unsigned long long mx = (k1 < o1) ? o1 : k1;
                unsigned long long mn2 = (k2 < o2) ? k2 : o2;
                k1 = n1;
                k2 = (mx < mn2) ? mx : mn2;
            }
            if (tig == 0) {
                int row = warpM * 64 + t * 16 + rs * 8 + g;
                red[(row * 4 + warpN) * 2 + 0] = k1;
                red[(row * 4 + warpN) * 2 + 1] = k2;
            }
        }
    }
    __syncthreads();

    if (tid < 128) {
        unsigned long long b1 = ~0ull, b2 = ~0ull;
        #pragma unroll
        for (int w = 0; w < 4; ++w)
            #pragma unroll
            for (int e = 0; e < 2; ++e) {
                unsigned long long k = red[(tid * 4 + w) * 2 + e];
                if (k < b1) { b2 = b1; b1 = k; } else if (k < b2) b2 = k;
            }
        size_t ci = ((size_t)((br << 10) + rowBase + tid)) * (NTILES * 2) + ct * 2;
        g_cand[ci] = b1;
        g_cand[ci + 1] = b2;
    }
}

// ---------------- rerank (exact fp32 within delta) + update ----------------
__global__ void rerank_update_kernel(const float* __restrict__ cbAll, int step)
{
    int row = blockIdx.x, br = blockIdx.y;
    int tid = threadIdx.x, lane = tid & 31, w = tid >> 5;

    __shared__ float rsm[DD];
    __shared__ unsigned long long keys[NTILES * 2];
    __shared__ unsigned long long sBest, sExact;

    size_t rbase = ((size_t)br * ROWS + row) * DD;
    if (tid < DD) rsm[tid] = g_res[rbase + tid];
    if (tid < NTILES * 2) keys[tid] = g_cand[((size_t)((br << 10) + row)) * (NTILES * 2) + tid];
    if (tid == 0) { sBest = ~0ull; sExact = ~0ull; }
    __syncthreads();
    if (tid < NTILES * 2) atomicMin(&sBest, keys[tid]);
    __syncthreads();

    float bestA = fkey_inv((unsigned)(sBest >> 32));
    const float* cbq = cbAll + (size_t)(br * NQ + step) * VV * DD;
    const float* cnq = g_cnorm + (size_t)(br * NQ + step) * VV;

    for (int c = w; c < NTILES * 2; c += 8) {
        unsigned long long k = keys[c];
        float da = fkey_inv((unsigned)(k >> 32));
        if (da <= bestA + RERANK_DELTA) {
            int code = (int)(k & 0xFFFFFFFFull);
            const float* cr = cbq + (size_t)code * DD;
            float dot = 0.f;
            for (int d = lane; d < DD; d += 32) dot += rsm[d] * cr[d];
            #pragma unroll
            for (int o = 16; o; o >>= 1) dot += __shfl_xor_sync(0xffffffffu, dot, o);
            if (lane == 0) {
                float de = cnq[code] - 2.0f * dot;
                unsigned long long ke = ((unsigned long long)fkey(de) << 32) | (unsigned)code;
                atomicMin(&sExact, ke);
            }
        }
    }
    __syncthreads();

    int idx = (int)(sExact & 0xFFFFFFFFull);
    const float* q = cbq + (size_t)idx * DD;
    if (tid < DD) {
        float qv = q[tid];
        float r = rsm[tid] - qv;
        g_res[rbase + tid] = r;
        g_quant[rbase + tid] += qv;
        __nv_bfloat16 h = __float2bfloat16(r);
        __nv_bfloat16 l = __float2bfloat16(r - __bfloat162float(h));
        size_t pb = ((size_t)((br << 10) + row)) * KPAD + tid;
        g_res_hi[pb] = h;
        g_res_lo[pb] = l;
    }
    if (tid == 0) g_idx[(br * NQ + step) * ROWS + row] = idx;
}

// ---------------- final output ----------------
__global__ void final_kernel(float* __restrict__ out, int n)
{
    int i = blockIdx.x * 256 + threadIdx.x;
    if (i >= n) return;
    if (i < N_FT) {
        float f = g_feats[i];
        out[i] = f + (g_quant[i] - f);
    } else {
        int j = i - N_FT;
        out[i] = (j < N_IDX) ? (float)g_idx[j] : 0.0f;
    }
}

// ---------------- launch ----------------
extern "C" void kernel_launch(void* const* d_in, const int* in_sizes, int n_in,
                              void* d_out, int out_size)
{
    const float* x   = (const float*)d_in[0];
    const float* w11 = (const float*)d_in[1];
    const float* w12 = (const float*)d_in[2];
    const float* w13 = (const float*)d_in[3];
    const float* w14 = (const float*)d_in[4];
    const float* b1  = (const float*)d_in[5];
    const float* g1  = (const float*)d_in[6];
    const float* be1 = (const float*)d_in[7];
    const float* w21 = (const float*)d_in[8];
    const float* w22 = (const float*)d_in[9];
    const float* w23 = (const float*)d_in[10];
    const float* w24 = (const float*)d_in[11];
    const float* b2  = (const float*)d_in[12];
    const float* g2  = (const float*)d_in[13];
    const float* be2 = (const float*)d_in[14];
    const float* cb  = (const float*)d_in[15];

    int K1a = in_sizes[1] / CC,  K1b = in_sizes[2] / CC;
    int K1c = in_sizes[3] / CC,  K1d = in_sizes[4] / CC;
    int K2a = in_sizes[8] / (CC * CC),  K2b = in_sizes[9] / (CC * CC);
    int K2c = in_sizes[10] / (CC * CC), K2d = in_sizes[11] / (CC * CC);

    static bool attrDone = false;
    if (!attrDone) {
        cudaFuncSetAttribute(gemm_step_kernel, cudaFuncAttributeMaxDynamicSharedMemorySize, DSMEM);
        attrDone = true;
    }

    cnorm_kernel<<<(NBR * NQ * VV) / 8, 256>>>(cb);
    pack_cb_kernel<<<(NBR * NQ * VV * (KPAD / 2)) / 256, 256>>>(cb);

    conv1_kernel<<<dim3(NAA, BB, NBR), 256>>>(x, w11, w12, w13, w14, b1, K1a, K1b, K1c, K1d);
    gn_stats_kernel<<<NBR * BB * 4, 256>>>(0);
    conv2_kernel<<<dim3(NAA, BB, NBR), 256>>>(w21, w22, w23, w24, b2, g1, be1, K2a, K2b, K2c, K2d);
    gn_stats_kernel<<<NBR * BB * 4, 256>>>(1);
    feats_kernel<<<(N_FT + 255) / 256, 256>>>(g2, be2);

    for (int s = 0; s < NQ; ++s) {
        gemm_step_kernel<<<dim3(ROWS / 128, NBR, NTILES), 256, DSMEM>>>(s);
        rerank_update_kernel<<<dim3(ROWS, NBR), 256>>>(cb, s);
    }

    final_kernel<<<(out_size + 255) / 256, 256>>>((float*)d_out, out_size);
}

// round 6
// speedup vs baseline: 1.6032x; 1.1253x over previous
#include <cuda_runtime.h>
#include <cuda_bf16.h>
#include <cstdint>

// ---------------- problem constants ----------------
#define NBR 4
#define BB  8
#define CC  8
#define NAA 128
#define T0  200
#define T1  100
#define DD  200
#define VV  8192
#define NQ  8
#define ROWS (BB*NAA)        // 1024

#define N_Y1  (NBR*BB*CC*NAA*T0)
#define N_Y3  (NBR*BB*CC*NAA*T1)
#define N_FT  (NBR*ROWS*DD)
#define N_IDX (NBR*NQ*ROWS)

#define KPAD 224             // padded K (bf16): 200 data + 24 zeros
#define KC   32              // K chunk
#define NCH  (KPAD/KC)       // 7 chunks
#define NT   128             // codes per col tile
#define NTILES (VV/NT)       // 64
#define RERANK_DELTA 0.05f

// smem slab: one array = 128 rows x 32 bf16, padded to 40 bf16 (80B) per row
#define SLAB_B 10240         // 128*80
#define BUF_B  (4*SLAB_B)    // a_hi, a_lo, b_hi, b_lo
#define DSMEM  (2*BUF_B)     // double buffered = 81920

// ---------------- scratch ----------------
__device__ float g_y1[N_Y1];
__device__ float g_y3[N_Y3];
__device__ float g_stats1[NBR*BB*4*2];
__device__ float g_stats2[NBR*BB*4*2];
__device__ float g_feats[N_FT];
__device__ float g_res[N_FT];
__device__ float g_quant[N_FT];
__device__ float g_cnorm[NBR*NQ*VV];
__device__ int   g_idx[N_IDX];
__device__ uint32_t g_cbh[(size_t)NBR*NQ*VV*(KPAD/2)];   // bf16 hi image [code][KPAD]; pads stay 0
__device__ uint32_t g_cbl[(size_t)NBR*NQ*VV*(KPAD/2)];   // bf16 lo image; pads stay 0
__device__ __nv_bfloat16 g_res_hi[NBR*ROWS*KPAD];        // zero-init pads stay zero
__device__ __nv_bfloat16 g_res_lo[NBR*ROWS*KPAD];
__device__ unsigned long long g_cand[(size_t)NBR*ROWS*NTILES*2];

// ---------------- helpers ----------------
__device__ __forceinline__ float gelu_exact(float v) {
    return 0.5f * v * (1.0f + erff(v * 0.70710678118654752440f));
}
__device__ __forceinline__ unsigned fkey(float f) {
    unsigned u = __float_as_uint(f);
    return (u & 0x80000000u) ? ~u : (u | 0x80000000u);
}
__device__ __forceinline__ float fkey_inv(unsigned k) {
    unsigned u = (k & 0x80000000u) ? (k & 0x7FFFFFFFu) : ~k;
    return __uint_as_float(u);
}
__device__ __forceinline__ uint32_t smem_u32(const void* p) {
    uint32_t a;
    asm("{ .reg .u64 t; cvta.to.shared.u64 t, %1; cvt.u32.u64 %0, t; }" : "=r"(a) : "l"(p));
    return a;
}
#define CP_ASYNC16(dst, src) \
    asm volatile("cp.async.cg.shared.global [%0], [%1], 16;" :: "r"(dst), "l"(src))
#define CP_COMMIT() asm volatile("cp.async.commit_group;" ::: "memory")
#define CP_WAIT(n)  asm volatile("cp.async.wait_group %0;" :: "n"(n) : "memory")

__device__ __forceinline__ void mma_bf16(float* c,
    uint32_t a0, uint32_t a1, uint32_t a2, uint32_t a3, uint32_t b0, uint32_t b1)
{
    asm volatile("mma.sync.aligned.m16n8k16.row.col.f32.bf16.bf16.f32 "
        "{%0,%1,%2,%3}, {%4,%5,%6,%7}, {%8,%9}, {%0,%1,%2,%3};"
        : "+f"(c[0]), "+f"(c[1]), "+f"(c[2]), "+f"(c[3])
        : "r"(a0), "r"(a1), "r"(a2), "r"(a3), "r"(b0), "r"(b1));
}

// ---------------- fused codebook pack (bf16 hi/lo) + squared norms; warp per code ----------------
__global__ void pack_cnorm_kernel(const float* __restrict__ cbAll)
{
    int w = (blockIdx.x * 256 + threadIdx.x) >> 5;     // global code id
    int lane = threadIdx.x & 31;
    if (w >= NBR * NQ * VV) return;
    const float* src = cbAll + (size_t)w * DD;
    uint32_t* dh = g_cbh + (size_t)w * (KPAD / 2);
    uint32_t* dl = g_cbl + (size_t)w * (KPAD / 2);

    float s = 0.f;
    #pragma unroll
    for (int p = lane; p < DD / 2; p += 32) {          // 100 u32 per code
        float v0 = src[2 * p], v1 = src[2 * p + 1];
        s += v0 * v0 + v1 * v1;
        __nv_bfloat16 h0 = __float2bfloat16(v0), h1 = __float2bfloat16(v1);
        __nv_bfloat16 l0 = __float2bfloat16(v0 - __bfloat162float(h0));
        __nv_bfloat16 l1 = __float2bfloat16(v1 - __bfloat162float(h1));
        dh[p] = ((uint32_t)__bfloat16_as_ushort(h1) << 16) | __bfloat16_as_ushort(h0);
        dl[p] = ((uint32_t)__bfloat16_as_ushort(l1) << 16) | __bfloat16_as_ushort(l0);
    }
    #pragma unroll
    for (int o = 16; o; o >>= 1) s += __shfl_xor_sync(0xffffffffu, s, o);
    if (lane == 0) g_cnorm[w] = s;
}

// ---------------- conv1: one block per (br,b,na); padded smem, branch-free inner loop ----------------
__global__ void conv1_kernel(const float* __restrict__ x,
                             const float* __restrict__ w0, const float* __restrict__ w1,
                             const float* __restrict__ w2, const float* __restrict__ w3,
                             const float* __restrict__ b1,
                             int k0, int k1, int k2, int k3)
{
    int na = blockIdx.x, b = blockIdx.y, br = blockIdx.z;
    int tid = threadIdx.x;

    const float* w; int K;
    if (br == 0)      { w = w0; K = k0; }
    else if (br == 1) { w = w1; K = k1; }
    else if (br == 2) { w = w2; K = k2; }
    else              { w = w3; K = k3; }
    int pad = (K - 1) >> 1;

    __shared__ float xs[T0 + 32];        // 16-halo each side, zeroed
    __shared__ float ws[CC * 24];
    if (tid < T0) xs[16 + tid] = x[(size_t)(b * NAA + na) * T0 + tid];
    else if (tid < T0 + 16) xs[tid - T0] = 0.f;              // [0,16)
    else if (tid < T0 + 32) xs[tid] = 0.f;                   // [216,232)... covers [T0+16, T0+32)
    if (tid < CC * K) ws[tid] = w[tid];
    __syncthreads();

    if (tid >= T0) return;
    int t = tid;
    int base0 = 16 + t - pad;
    size_t outBase = (((size_t)(br * BB + b) * CC) * NAA + na) * T0 + t;
    #pragma unroll
    for (int c = 0; c < CC; ++c) {
        float acc = b1[br * CC + c];
        const float* wr = ws + c * K;
        for (int k = 0; k < K; ++k) acc += xs[base0 + k] * wr[k];
        g_y1[outBase + (size_t)c * NAA * T0] = acc;
    }
}

// ---------------- group norm stats ----------------
__global__ void gn_stats_kernel(int which)
{
    int blk = blockIdx.x;
    int tid = threadIdx.x;
    int Tl = which ? T1 : T0;
    const float* src = which ? g_y3 : g_y1;
    float* stats = which ? g_stats2 : g_stats1;

    int gq = blk & 3;
    int bb = (blk >> 2) & 7;
    int br = blk >> 5;
    size_t base = ((size_t)((br * BB + bb) * CC) + 2 * gq) * NAA * Tl;
    int n = 2 * NAA * Tl;

    float s = 0.f, s2 = 0.f;
    for (int j = tid; j < n; j += 256) {
        float v = src[base + j];
        s += v; s2 += v * v;
    }
    __shared__ float sha[256], shb[256];
    sha[tid] = s; shb[tid] = s2;
    __syncthreads();
    for (int o = 128; o; o >>= 1) {
        if (tid < o) { sha[tid] += sha[tid + o]; shb[tid] += shb[tid + o]; }
        __syncthreads();
    }
    if (tid == 0) {
        float m = sha[0] / (float)n;
        float var = shb[0] / (float)n - m * m;
        stats[blk * 2]     = m;
        stats[blk * 2 + 1] = rsqrtf(var + 1e-5f);
    }
}

// ---------------- conv2 fused with GN1+gelu+pool2; padded smem, branch-free ----------------
__global__ void conv2_kernel(const float* __restrict__ w0, const float* __restrict__ w1,
                             const float* __restrict__ w2, const float* __restrict__ w3,
                             const float* __restrict__ b2,
                             const float* __restrict__ g1, const float* __restrict__ be1,
                             int k0, int k1, int k2, int k3)
{
    int na = blockIdx.x, b = blockIdx.y, br = blockIdx.z;
    int tid = threadIdx.x;

    const float* w; int K;
    if (br == 0)      { w = w0; K = k0; }
    else if (br == 1) { w = w1; K = k1; }
    else if (br == 2) { w = w2; K = k2; }
    else              { w = w3; K = k3; }
    int pad = (K - 1) >> 1;

    __shared__ float yin[CC][T1 + 16];   // 8-halo each side
    __shared__ float ws[CC * CC * 12];

    for (int i = tid; i < CC * CC * K; i += 256) ws[i] = w[i];

    int hi = (tid >= 100) ? 1 : 0;
    int t  = tid - 100 * hi;
    bool act = (tid < 200);

    // idle threads (200..255) zero the halos: 8 ch x 16 slots = 128
    if (tid >= 200) {
        for (int i = tid - 200; i < 128; i += 56) {
            int ch = i >> 4, j = i & 15;
            yin[ch][(j < 8) ? j : (100 + j)] = 0.f;   // [0,8) and [108,116)
        }
    }
    #pragma unroll
    for (int it = 0; it < 4; ++it) {
        int ci = 2 * it + hi;
        if (act) {
            int sb = (br * BB + b) * 4 + (ci >> 1);
            float m = g_stats1[sb * 2], r = g_stats1[sb * 2 + 1];
            float sc = r * g1[br * CC + ci];
            float sh = be1[br * CC + ci] - m * sc;
            size_t base = (((size_t)(br * BB + b) * CC + ci) * NAA + na) * T0 + 2 * t;
            float a0 = gelu_exact(g_y1[base]     * sc + sh);
            float a1 = gelu_exact(g_y1[base + 1] * sc + sh);
            yin[ci][8 + t] = 0.5f * (a0 + a1);
        }
    }
    __syncthreads();

    int base0 = 8 + t - pad;
    #pragma unroll
    for (int it = 0; it < 4; ++it) {
        int co = 2 * it + hi;
        if (act) {
            float acc = b2[br * CC + co];
            for (int ci = 0; ci < CC; ++ci) {
                const float* wr = ws + (co * CC + ci) * K;
                const float* yr = &yin[ci][base0];
                for (int k = 0; k < K; ++k) acc += yr[k] * wr[k];
            }
            g_y3[(((size_t)(br * BB + b) * CC + co) * NAA + na) * T1 + t] = acc;
        }
    }
}

// ---------------- feats: GN2+gelu+pool4+transpose; init res/quant + bf16 hi/lo ----------------
__global__ void feats_kernel(const float* __restrict__ g2, const float* __restrict__ be2)
{
    int i = blockIdx.x * 256 + threadIdx.x;
    if (i >= N_FT) return;
    int d  = i % DD;
    int na = (i / DD) & (NAA - 1);
    int b  = (i / (DD * NAA)) & (BB - 1);
    int br = i / (DD * NAA * BB);
    int t = d >> 3;
    int c = d & 7;

    int sb = (br * BB + b) * 4 + (c >> 1);
    float m = g_stats2[sb * 2], r = g_stats2[sb * 2 + 1];
    float sc = r * g2[br * CC + c];
    float sh = be2[br * CC + c] - m * sc;

    size_t base = (((size_t)(br * BB + b) * CC + c) * NAA + na) * T1 + 4 * t;
    float v = 0.25f * (gelu_exact(g_y3[base]     * sc + sh) +
                       gelu_exact(g_y3[base + 1] * sc + sh) +
                       gelu_exact(g_y3[base + 2] * sc + sh) +
                       gelu_exact(g_y3[base + 3] * sc + sh));
    g_feats[i] = v;
    g_res[i]   = v;
    g_quant[i] = 0.0f;

    int row = b * NAA + na;
    __nv_bfloat16 h = __float2bfloat16(v);
    __nv_bfloat16 l = __float2bfloat16(v - __bfloat162float(h));
    size_t pb = ((size_t)((br << 10) + row)) * KPAD + d;
    g_res_hi[pb] = h;
    g_res_lo[pb] = l;
}

// ---------------- mma.sync distance GEMM + per-tile top-2 epilogue ----------------
// grid (8 rowtiles, 4 br, 64 coltiles), block 256 (8 warps, warpM x warpN = 2x4),
// warp tile 64x32, K streamed in 7 chunks of 32 via cp.async double buffering.
__global__ void __launch_bounds__(256) gemm_step_kernel(int step)
{
    extern __shared__ char dsm[];
    __shared__ float cns[NT];

    int tid = threadIdx.x;
    int lane = tid & 31;
    int wid = tid >> 5;
    int warpM = wid & 1;      // 0..1
    int warpN = wid >> 1;     // 0..3
    int g  = lane >> 2;       // 0..7
    int tig = lane & 3;       // 0..3

    int rowBase = blockIdx.x * 128;
    int br = blockIdx.y;
    int ct = blockIdx.z;
    int brq = br * NQ + step;

    const __nv_bfloat16* aH = g_res_hi + (size_t)((br << 10) + rowBase) * KPAD;
    const __nv_bfloat16* aL = g_res_lo + (size_t)((br << 10) + rowBase) * KPAD;
    const __nv_bfloat16* bH = (const __nv_bfloat16*)g_cbh + ((size_t)brq * VV + (size_t)ct * NT) * KPAD;
    const __nv_bfloat16* bL = (const __nv_bfloat16*)g_cbl + ((size_t)brq * VV + (size_t)ct * NT) * KPAD;

    if (tid < NT) cns[tid] = g_cnorm[(size_t)brq * VV + ct * NT + tid];

    auto load_chunk = [&](int buf, int k0) {
        char* base = dsm + buf * BUF_B;
        #pragma unroll
        for (int s = 0; s < 4; ++s) {
            const __nv_bfloat16* gp = (s == 0) ? aH : (s == 1) ? aL : (s == 2) ? bH : bL;
            char* sb = base + s * SLAB_B;
            #pragma unroll
            for (int h = 0; h < 2; ++h) {
                int i = tid + h * 256;
                int row = i >> 2, seg = i & 3;
                uint32_t dst = smem_u32(sb + row * 80 + seg * 16);
                const void* src = gp + (size_t)row * KPAD + k0 + seg * 8;
                CP_ASYNC16(dst, src);
            }
        }
        CP_COMMIT();
    };

    float acc[4][4][4];
    #pragma unroll
    for (int t = 0; t < 4; ++t)
        #pragma unroll
        for (int n = 0; n < 4; ++n)
            #pragma unroll
            for (int e = 0; e < 4; ++e) acc[t][n][e] = 0.f;

    load_chunk(0, 0);

    #pragma unroll 1
    for (int c = 0; c < NCH; ++c) {
        if (c + 1 < NCH) { load_chunk((c + 1) & 1, (c + 1) * KC); CP_WAIT(1); }
        else             { CP_WAIT(0); }
        __syncthreads();

        const char* base = dsm + (c & 1) * BUF_B;
        const char* aHs = base;
        const char* aLs = base + SLAB_B;
        const char* bHs = base + 2 * SLAB_B;
        const char* bLs = base + 3 * SLAB_B;

        #pragma unroll
        for (int k16 = 0; k16 < 2; ++k16) {
            uint32_t ah[4][4], al[4][4];
            #pragma unroll
            for (int t = 0; t < 4; ++t) {
                int r0 = warpM * 64 + t * 16 + g;
                const char* pa = aHs + r0 * 80 + k16 * 32 + tig * 4;
                ah[t][0] = *(const uint32_t*)pa;
                ah[t][1] = *(const uint32_t*)(pa + 8 * 80);
                ah[t][2] = *(const uint32_t*)(pa + 16);
                ah[t][3] = *(const uint32_t*)(pa + 8 * 80 + 16);
                const char* pb = aLs + r0 * 80 + k16 * 32 + tig * 4;
                al[t][0] = *(const uint32_t*)pb;
                al[t][1] = *(const uint32_t*)(pb + 8 * 80);
                al[t][2] = *(const uint32_t*)(pb + 16);
                al[t][3] = *(const uint32_t*)(pb + 8 * 80 + 16);
            }
            uint32_t bh[4][2], bl[4][2];
            #pragma unroll
            for (int n = 0; n < 4; ++n) {
                int c0 = warpN * 32 + n * 8 + g;
                const char* pb = bHs + c0 * 80 + k16 * 32 + tig * 4;
                bh[n][0] = *(const uint32_t*)pb;
                bh[n][1] = *(const uint32_t*)(pb + 16);
                const char* pc = bLs + c0 * 80 + k16 * 32 + tig * 4;
                bl[n][0] = *(const uint32_t*)pc;
                bl[n][1] = *(const uint32_t*)(pc + 16);
            }
            #pragma unroll
            for (int t = 0; t < 4; ++t)
                #pragma unroll
                for (int n = 0; n < 4; ++n) {
                    mma_bf16(acc[t][n], ah[t][0], ah[t][1], ah[t][2], ah[t][3], bh[n][0], bh[n][1]);
                    mma_bf16(acc[t][n], al[t][0], al[t][1], al[t][2], al[t][3], bh[n][0], bh[n][1]);
                    mma_bf16(acc[t][n], ah[t][0], ah[t][1], ah[t][2], ah[t][3], bl[n][0], bl[n][1]);
                }
        }
        __syncthreads();
    }

    // ---- epilogue: per-row top-2 across the 128-code tile ----
    unsigned long long* red = (unsigned long long*)dsm;   // [128][4][2]

    #pragma unroll
    for (int t = 0; t < 4; ++t) {
        #pragma unroll
        for (int rs = 0; rs < 2; ++rs) {
            unsigned long long k1 = ~0ull, k2 = ~0ull;
            #pragma unroll
            for (int n = 0; n < 4; ++n) {
                int lc = warpN * 32 + n * 8 + tig * 2;
                int gc = ct * NT + lc;
                float d0 = cns[lc]     - 2.0f * acc[t][n][rs * 2 + 0];
                float d1 = cns[lc + 1] - 2.0f * acc[t][n][rs * 2 + 1];
                unsigned long long ka = ((unsigned long long)fkey(d0) << 32) | (unsigned)gc;
                unsigned long long kb = ((unsigned long long)fkey(d1) << 32) | (unsigned)(gc + 1);
                if (ka < k1) { k2 = k1; k1 = ka; } else if (ka < k2) k2 = ka;
                if (kb < k1) { k2 = k1; k1 = kb; } else if (kb < k2) k2 = kb;
            }
            #pragma unroll
            for (int off = 1; off <= 2; off <<= 1) {
                unsigned long long o1 = __shfl_xor_sync(0xffffffffu, k1, off);
                unsigned long long o2 = __shfl_xor_sync(0xffffffffu, k2, off);
                unsigned long long n1 = (k1 < o1) ? k1 : o1;
                unsigned long long mx = (k1 < o1) ? o1 : k1;
                unsigned long long mn2 = (k2 < o2) ? k2 : o2;
                k1 = n1;
                k2 = (mx < mn2) ? mx : mn2;
            }
            if (tig == 0) {
                int row = warpM * 64 + t * 16 + rs * 8 + g;
                red[(row * 4 + warpN) * 2 + 0] = k1;
                red[(row * 4 + warpN) * 2 + 1] = k2;
            }
        }
    }
    __syncthreads();

    if (tid < 128) {
        unsigned long long b1 = ~0ull, b2 = ~0ull;
        #pragma unroll
        for (int w = 0; w < 4; ++w)
            #pragma unroll
            for (int e = 0; e < 2; ++e) {
                unsigned long long k = red[(tid * 4 + w) * 2 + e];
                if (k < b1) { b2 = b1; b1 = k; } else if (k < b2) b2 = k;
            }
        size_t ci = ((size_t)((br << 10) + rowBase + tid)) * (NTILES * 2) + ct * 2;
        g_cand[ci] = b1;
        g_cand[ci + 1] = b2;
    }
}

// ---------------- rerank (exact fp32 within delta) + update ----------------
__global__ void rerank_update_kernel(const float* __restrict__ cbAll, int step)
{
    int row = blockIdx.x, br = blockIdx.y;
    int tid = threadIdx.x, lane = tid & 31, w = tid >> 5;

    __shared__ float rsm[DD];
    __shared__ unsigned long long keys[NTILES * 2];
    __shared__ unsigned long long sBest, sExact;

    size_t rbase = ((size_t)br * ROWS + row) * DD;
    if (tid < DD) rsm[tid] = g_res[rbase + tid];
    if (tid < NTILES * 2) keys[tid] = g_cand[((size_t)((br << 10) + row)) * (NTILES * 2) + tid];
    if (tid == 0) { sBest = ~0ull; sExact = ~0ull; }
    __syncthreads();
    if (tid < NTILES * 2) atomicMin(&sBest, keys[tid]);
    __syncthreads();

    float bestA = fkey_inv((unsigned)(sBest >> 32));
    const float* cbq = cbAll + (size_t)(br * NQ + step) * VV * DD;
    const float* cnq = g_cnorm + (size_t)(br * NQ + step) * VV;

    for (int c = w; c < NTILES * 2; c += 8) {
        unsigned long long k = keys[c];
        float da = fkey_inv((unsigned)(k >> 32));
        if (da <= bestA + RERANK_DELTA) {
            int code = (int)(k & 0xFFFFFFFFull);
            const float* cr = cbq + (size_t)code * DD;
            float dot = 0.f;
            for (int d = lane; d < DD; d += 32) dot += rsm[d] * cr[d];
            #pragma unroll
            for (int o = 16; o; o >>= 1) dot += __shfl_xor_sync(0xffffffffu, dot, o);
            if (lane == 0) {
                float de = cnq[code] - 2.0f * dot;
                unsigned long long ke = ((unsigned long long)fkey(de) << 32) | (unsigned)code;
                atomicMin(&sExact, ke);
            }
        }
    }
    __syncthreads();

    int idx = (int)(sExact & 0xFFFFFFFFull);
    const float* q = cbq + (size_t)idx * DD;
    if (tid < DD) {
        float qv = q[tid];
        float r = rsm[tid] - qv;
        g_res[rbase + tid] = r;
        g_quant[rbase + tid] += qv;
        __nv_bfloat16 h = __float2bfloat16(r);
        __nv_bfloat16 l = __float2bfloat16(r - __bfloat162float(h));
        size_t pb = ((size_t)((br << 10) + row)) * KPAD + tid;
        g_res_hi[pb] = h;
        g_res_lo[pb] = l;
    }
    if (tid == 0) g_idx[(br * NQ + step) * ROWS + row] = idx;
}

// ---------------- final output ----------------
__global__ void final_kernel(float* __restrict__ out, int n)
{
    int i = blockIdx.x * 256 + threadIdx.x;
    if (i >= n) return;
    if (i < N_FT) {
        float f = g_feats[i];
        out[i] = f + (g_quant[i] - f);
    } else {
        int j = i - N_FT;
        out[i] = (j < N_IDX) ? (float)g_idx[j] : 0.0f;
    }
}

// ---------------- launch ----------------
extern "C" void kernel_launch(void* const* d_in, const int* in_sizes, int n_in,
                              void* d_out, int out_size)
{
    const float* x   = (const float*)d_in[0];
    const float* w11 = (const float*)d_in[1];
    const float* w12 = (const float*)d_in[2];
    const float* w13 = (const float*)d_in[3];
    const float* w14 = (const float*)d_in[4];
    const float* b1  = (const float*)d_in[5];
    const float* g1  = (const float*)d_in[6];
    const float* be1 = (const float*)d_in[7];
    const float* w21 = (const float*)d_in[8];
    const float* w22 = (const float*)d_in[9];
    const float* w23 = (const float*)d_in[10];
    const float* w24 = (const float*)d_in[11];
    const float* b2  = (const float*)d_in[12];
    const float* g2  = (const float*)d_in[13];
    const float* be2 = (const float*)d_in[14];
    const float* cb  = (const float*)d_in[15];

    int K1a = in_sizes[1] / CC,  K1b = in_sizes[2] / CC;
    int K1c = in_sizes[3] / CC,  K1d = in_sizes[4] / CC;
    int K2a = in_sizes[8] / (CC * CC),  K2b = in_sizes[9] / (CC * CC);
    int K2c = in_sizes[10] / (CC * CC), K2d = in_sizes[11] / (CC * CC);

    cudaFuncSetAttribute(gemm_step_kernel, cudaFuncAttributeMaxDynamicSharedMemorySize, DSMEM);

    pack_cnorm_kernel<<<(NBR * NQ * VV) / 8, 256>>>(cb);

    conv1_kernel<<<dim3(NAA, BB, NBR), 256>>>(x, w11, w12, w13, w14, b1, K1a, K1b, K1c, K1d);
    gn_stats_kernel<<<NBR * BB * 4, 256>>>(0);
    conv2_kernel<<<dim3(NAA, BB, NBR), 256>>>(w21, w22, w23, w24, b2, g1, be1, K2a, K2b, K2c, K2d);
    gn_stats_kernel<<<NBR * BB * 4, 256>>>(1);
    feats_kernel<<<(N_FT + 255) / 256, 256>>>(g2, be2);

    for (int s = 0; s < NQ; ++s) {
        gemm_step_kernel<<<dim3(ROWS / 128, NBR, NTILES), 256, DSMEM>>>(s);
        rerank_update_kernel<<<dim3(ROWS, NBR), 256>>>(cb, s);
    }

    final_kernel<<<(out_size + 255) / 256, 256>>>((float*)d_out, out_size);
}

// round 9
// speedup vs baseline: 1.8507x; 1.1544x over previous
#include <cuda_runtime.h>
#include <cuda_bf16.h>
#include <cstdint>

// ---------------- problem constants ----------------
#define NBR 4
#define BB  8
#define CC  8
#define NAA 128
#define T0  200
#define T1  100
#define DD  200
#define VV  8192
#define NQ  8
#define ROWS (BB*NAA)        // 1024

#define N_Y1  (NBR*BB*CC*NAA*T0)
#define N_Y3  (NBR*BB*CC*NAA*T1)
#define N_FT  (NBR*ROWS*DD)
#define N_IDX (NBR*NQ*ROWS)

#define KPAD 208             // padded K (bf16): 200 data + 8 zeros, 13 x 16
#define KC   16              // K chunk (one k16 per chunk)
#define NCH  (KPAD/KC)       // 13
#define NT   128             // codes per col tile
#define NTILES (VV/NT)       // 64
#define RERANK_DELTA 0.05f

// smem slab: 128 rows x 16 bf16 (32B) padded to 48B per row
#define SLAB_B 6144          // 128*48
#define BUF_B  (4*SLAB_B)    // a_hi, a_lo, b_hi, b_lo = 24576
#define DSMEM  (2*BUF_B)     // 49152

// ---------------- scratch ----------------
// NOTE: arrays touched by cp.async / vector loads are force-aligned to 16B —
// cp.async with 16B size faults on misaligned global addresses, and __device__
// array base alignment is otherwise layout-dependent.
__device__ float g_y1[N_Y1];
__device__ float g_y3[N_Y3];
__device__ float g_part1[2*NBR*BB*4*NAA];    // [which][br,b,group][na]
__device__ float g_part2[2*NBR*BB*4*NAA];
__device__ float g_feats[N_FT];
__device__ float g_res[N_FT];
__device__ float g_quant[N_FT];
__device__ float g_cnorm[NBR*NQ*VV];
__device__ int   g_idx[N_IDX];
__device__ __align__(16) uint32_t g_cbh[(size_t)NBR*NQ*VV*(KPAD/2)];  // bf16 hi image; pads stay 0
__device__ __align__(16) uint32_t g_cbl[(size_t)NBR*NQ*VV*(KPAD/2)];  // bf16 lo image; pads stay 0
__device__ __align__(16) __nv_bfloat16 g_res_hi[NBR*ROWS*KPAD];       // zero-init pads stay zero
__device__ __align__(16) __nv_bfloat16 g_res_lo[NBR*ROWS*KPAD];
__device__ __align__(16) unsigned long long g_cand[(size_t)NBR*ROWS*NTILES*2];

// ---------------- helpers ----------------
__device__ __forceinline__ float gelu_exact(float v) {
    return 0.5f * v * (1.0f + erff(v * 0.70710678118654752440f));
}
__device__ __forceinline__ unsigned fkey(float f) {
    unsigned u = __float_as_uint(f);
    return (u & 0x80000000u) ? ~u : (u | 0x80000000u);
}
__device__ __forceinline__ float fkey_inv(unsigned k) {
    unsigned u = (k & 0x80000000u) ? (k & 0x7FFFFFFFu) : ~k;
    return __uint_as_float(u);
}
__device__ __forceinline__ uint32_t smem_u32(const void* p) {
    uint32_t a;
    asm("{ .reg .u64 t; cvta.to.shared.u64 t, %1; cvt.u32.u64 %0, t; }" : "=r"(a) : "l"(p));
    return a;
}
#define CP_ASYNC16(dst, src) \
    asm volatile("cp.async.cg.shared.global [%0], [%1], 16;" :: "r"(dst), "l"(src))
#define CP_COMMIT() asm volatile("cp.async.commit_group;" ::: "memory")
#define CP_WAIT(n)  asm volatile("cp.async.wait_group %0;" :: "n"(n) : "memory")

__device__ __forceinline__ void mma_bf16(float* c,
    uint32_t a0, uint32_t a1, uint32_t a2, uint32_t a3, uint32_t b0, uint32_t b1)
{
    asm volatile("mma.sync.aligned.m16n8k16.row.col.f32.bf16.bf16.f32 "
        "{%0,%1,%2,%3}, {%4,%5,%6,%7}, {%8,%9}, {%0,%1,%2,%3};"
        : "+f"(c[0]), "+f"(c[1]), "+f"(c[2]), "+f"(c[3])
        : "r"(a0), "r"(a1), "r"(a2), "r"(a3), "r"(b0), "r"(b1));
}

// ---------------- conv1: fused group-stat partials; K-specialized ----------------
#define CONV1_BODY(KV) { \
    const int base0 = 16 + t - ((KV - 1) >> 1); \
    _Pragma("unroll") \
    for (int c = 0; c < CC; ++c) { \
        float acc = b1v[c]; \
        const float* wr = ws + c * KV; \
        _Pragma("unroll") \
        for (int k = 0; k < KV; ++k) acc += xs[base0 + k] * wr[k]; \
        y[c] = acc; \
    } }

__global__ void conv1_kernel(const float* __restrict__ x,
                             const float* __restrict__ w0, const float* __restrict__ w1,
                             const float* __restrict__ w2, const float* __restrict__ w3,
                             const float* __restrict__ b1,
                             int k0, int k1, int k2, int k3)
{
    int na = blockIdx.x, b = blockIdx.y, br = blockIdx.z;
    int tid = threadIdx.x, lane = tid & 31, wid = tid >> 5;

    const float* w; int K;
    if (br == 0)      { w = w0; K = k0; }
    else if (br == 1) { w = w1; K = k1; }
    else if (br == 2) { w = w2; K = k2; }
    else              { w = w3; K = k3; }

    __shared__ float xs[T0 + 32];
    __shared__ float ws[CC * 24];
    __shared__ float wred[8][8];

    if (tid < T0) xs[16 + tid] = x[(size_t)(b * NAA + na) * T0 + tid];
    else if (tid < T0 + 16) xs[tid - T0] = 0.f;
    else if (tid < T0 + 32) xs[tid] = 0.f;
    if (tid < CC * K) ws[tid] = w[tid];
    __syncthreads();

    bool act = tid < T0;
    int t = act ? tid : 0;
    const float* b1v = b1 + br * CC;
    float y[CC];
    if (K == 21)      CONV1_BODY(21)
    else if (K == 15) CONV1_BODY(15)
    else if (K == 9)  CONV1_BODY(9)
    else if (K == 5)  CONV1_BODY(5)
    else {
        int pad = (K - 1) >> 1;
        int base0 = 16 + t - pad;
        for (int c = 0; c < CC; ++c) {
            float acc = b1v[c];
            const float* wr = ws + c * K;
            for (int k = 0; k < K; ++k) acc += xs[base0 + k] * wr[k];
            y[c] = acc;
        }
    }
    if (act) {
        size_t outBase = (((size_t)(br * BB + b) * CC) * NAA + na) * T0 + t;
        #pragma unroll
        for (int c = 0; c < CC; ++c) g_y1[outBase + (size_t)c * NAA * T0] = y[c];
    }

    // group partials: pv[0..3]=sum, pv[4..7]=sumsq per group
    float pv[8];
    #pragma unroll
    for (int gq = 0; gq < 4; ++gq) {
        float a0 = act ? y[2 * gq] : 0.f;
        float a1 = act ? y[2 * gq + 1] : 0.f;
        pv[gq]     = a0 + a1;
        pv[4 + gq] = a0 * a0 + a1 * a1;
    }
    #pragma unroll
    for (int v = 0; v < 8; ++v)
        #pragma unroll
        for (int o = 16; o; o >>= 1) pv[v] += __shfl_xor_sync(0xffffffffu, pv[v], o);
    if (lane == 0) {
        #pragma unroll
        for (int v = 0; v < 8; ++v) wred[wid][v] = pv[v];
    }
    __syncthreads();
    if (tid < 8) {
        float s = 0.f;
        #pragma unroll
        for (int ww = 0; ww < 8; ++ww) s += wred[ww][tid];
        int gq = tid & 3, which = tid >> 2;
        g_part1[((which * (NBR * BB) + br * BB + b) * 4 + gq) * NAA + na] = s;
    }
}

// ---------------- conv2: GN1(from partials)+gelu+pool2 + conv + stat2 partials ----------------
#define CONV2_TAPS(KV) { \
    const int base0 = 8 + t - ((KV - 1) >> 1); \
    _Pragma("unroll") \
    for (int it = 0; it < 4; ++it) { \
        int co = 2 * it + hi; \
        float acc = b2[br * CC + co]; \
        _Pragma("unroll") \
        for (int ci = 0; ci < CC; ++ci) { \
            const float* wr = ws + (co * CC + ci) * KV; \
            const float* yr = &yin[ci][base0]; \
            _Pragma("unroll") \
            for (int k = 0; k < KV; ++k) acc += yr[k] * wr[k]; \
        } \
        accv[it] = acc; \
    } }

__global__ void conv2_kernel(const float* __restrict__ w0, const float* __restrict__ w1,
                             const float* __restrict__ w2, const float* __restrict__ w3,
                             const float* __restrict__ b2,
                             const float* __restrict__ g1, const float* __restrict__ be1,
                             int k0, int k1, int k2, int k3)
{
    int na = blockIdx.x, b = blockIdx.y, br = blockIdx.z;
    int tid = threadIdx.x, lane = tid & 31, wid = tid >> 5;

    const float* w; int K;
    if (br == 0)      { w = w0; K = k0; }
    else if (br == 1) { w = w1; K = k1; }
    else if (br == 2) { w = w2; K = k2; }
    else              { w = w3; K = k3; }

    __shared__ float yin[CC][T1 + 16];
    __shared__ float ws[CC * CC * 12];
    __shared__ float2 st[4];
    __shared__ float wred[8][8];

    // GN1 stats from conv1 partials (deterministic fixed-order tree)
    if (wid < 4) {
        float s = 0.f, q = 0.f;
        int b0 = ((br * BB + b) * 4 + wid) * NAA;
        #pragma unroll
        for (int j = 0; j < 4; ++j) {
            s += g_part1[b0 + lane + 32 * j];
            q += g_part1[NBR * BB * 4 * NAA + b0 + lane + 32 * j];
        }
        #pragma unroll
        for (int o = 16; o; o >>= 1) {
            s += __shfl_xor_sync(0xffffffffu, s, o);
            q += __shfl_xor_sync(0xffffffffu, q, o);
        }
        if (lane == 0) {
            float n = 2.0f * NAA * T0;
            float m = s / n;
            float var = q / n - m * m;
            st[wid] = make_float2(m, rsqrtf(var + 1e-5f));
        }
    }
    for (int i = tid; i < CC * CC * K; i += 256) ws[i] = w[i];

    int hi = (tid >= 100) ? 1 : 0;
    int t  = tid - 100 * hi;
    bool act = (tid < 200);
    if (tid >= 200) {
        for (int i = tid - 200; i < 128; i += 56) {
            int ch = i >> 4, j = i & 15;
            yin[ch][(j < 8) ? j : (100 + j)] = 0.f;
        }
    }
    __syncthreads();

    // stage A: GN1 + gelu + pool2
    #pragma unroll
    for (int it = 0; it < 4; ++it) {
        int ci = 2 * it + hi;
        if (act) {
            float m = st[ci >> 1].x, r = st[ci >> 1].y;
            float sc = r * g1[br * CC + ci];
            float sh = be1[br * CC + ci] - m * sc;
            size_t base = (((size_t)(br * BB + b) * CC + ci) * NAA + na) * T0 + 2 * t;
            float a0 = gelu_exact(g_y1[base]     * sc + sh);
            float a1 = gelu_exact(g_y1[base + 1] * sc + sh);
            yin[ci][8 + t] = 0.5f * (a0 + a1);
        }
    }
    __syncthreads();

    // stage B: conv (K-specialized)
    float accv[4] = {0.f, 0.f, 0.f, 0.f};
    if (act) {
        if (K == 9)      CONV2_TAPS(9)
        else if (K == 7) CONV2_TAPS(7)
        else if (K == 5) CONV2_TAPS(5)
        else if (K == 3) CONV2_TAPS(3)
        else {
            int base0 = 8 + t - ((K - 1) >> 1);
            for (int it = 0; it < 4; ++it) {
                int co = 2 * it + hi;
                float acc = b2[br * CC + co];
                for (int ci = 0; ci < CC; ++ci) {
                    const float* wr = ws + (co * CC + ci) * K;
                    const float* yr = &yin[ci][base0];
                    for (int k = 0; k < K; ++k) acc += yr[k] * wr[k];
                }
                accv[it] = acc;
            }
        }
        #pragma unroll
        for (int it = 0; it < 4; ++it) {
            int co = 2 * it + hi;
            g_y3[(((size_t)(br * BB + b) * CC + co) * NAA + na) * T1 + t] = accv[it];
        }
    }

    // stat2 partials: group of co=2it+hi is it
    float pv[8];
    #pragma unroll
    for (int it = 0; it < 4; ++it) {
        float a = act ? accv[it] : 0.f;
        pv[it] = a;
        pv[4 + it] = a * a;
    }
    #pragma unroll
    for (int v = 0; v < 8; ++v)
        #pragma unroll
        for (int o = 16; o; o >>= 1) pv[v] += __shfl_xor_sync(0xffffffffu, pv[v], o);
    if (lane == 0) {
        #pragma unroll
        for (int v = 0; v < 8; ++v) wred[wid][v] = pv[v];
    }
    __syncthreads();
    if (tid < 8) {
        float s = 0.f;
        #pragma unroll
        for (int ww = 0; ww < 8; ++ww) s += wred[ww][tid];
        int gq = tid & 3, which = tid >> 2;
        g_part2[((which * (NBR * BB) + br * BB + b) * 4 + gq) * NAA + na] = s;
    }
}

// ---------------- feats (GN2+gelu+pool4+transpose) fused with codebook pack+cnorm ----------------
__global__ void feats_pack_kernel(const float* __restrict__ cbAll,
                                  const float* __restrict__ g2, const float* __restrict__ be2)
{
    int bx = blockIdx.x, b = blockIdx.y, br = blockIdx.z;
    int tid = threadIdx.x, lane = tid & 31, wid = tid >> 5;

    if (bx >= NAA) {
        // ---- pack part: warp per code ----
        int px = bx - NAA;                          // 0..1023
        int cid = (px * BB + b) * 8 + wid;          // 0..65535 within branch
        size_t gcode = (size_t)br * (NQ * VV) + cid;
        const float* src = cbAll + gcode * DD;
        uint32_t* dh = g_cbh + gcode * (KPAD / 2);
        uint32_t* dl = g_cbl + gcode * (KPAD / 2);
        float s = 0.f;
        #pragma unroll
        for (int p = lane; p < DD / 2; p += 32) {
            float v0 = src[2 * p], v1 = src[2 * p + 1];
            s += v0 * v0 + v1 * v1;
            __nv_bfloat16 h0 = __float2bfloat16(v0), h1 = __float2bfloat16(v1);
            __nv_bfloat16 l0 = __float2bfloat16(v0 - __bfloat162float(h0));
            __nv_bfloat16 l1 = __float2bfloat16(v1 - __bfloat162float(h1));
            dh[p] = ((uint32_t)__bfloat16_as_ushort(h1) << 16) | __bfloat16_as_ushort(h0);
            dl[p] = ((uint32_t)__bfloat16_as_ushort(l1) << 16) | __bfloat16_as_ushort(l0);
        }
        #pragma unroll
        for (int o = 16; o; o >>= 1) s += __shfl_xor_sync(0xffffffffu, s, o);
        if (lane == 0) g_cnorm[gcode] = s;
        return;
    }

    // ---- feats part ----
    int na = bx;
    __shared__ float2 st[4];
    if (wid < 4) {
        float s = 0.f, q = 0.f;
        int b0 = ((br * BB + b) * 4 + wid) * NAA;
        #pragma unroll
        for (int j = 0; j < 4; ++j) {
            s += g_part2[b0 + lane + 32 * j];
            q += g_part2[NBR * BB * 4 * NAA + b0 + lane + 32 * j];
        }
        #pragma unroll
        for (int o = 16; o; o >>= 1) {
            s += __shfl_xor_sync(0xffffffffu, s, o);
            q += __shfl_xor_sync(0xffffffffu, q, o);
        }
        if (lane == 0) {
            float n = 2.0f * NAA * T1;
            float m = s / n;
            float var = q / n - m * m;
            st[wid] = make_float2(m, rsqrtf(var + 1e-5f));
        }
    }
    __syncthreads();

    int d = tid;
    if (d >= DD) return;
    int t = d >> 3;
    int c = d & 7;
    float m = st[c >> 1].x, r = st[c >> 1].y;
    float sc = r * g2[br * CC + c];
    float sh = be2[br * CC + c] - m * sc;

    size_t base = (((size_t)(br * BB + b) * CC + c) * NAA + na) * T1 + 4 * t;
    float v = 0.25f * (gelu_exact(g_y3[base]     * sc + sh) +
                       gelu_exact(g_y3[base + 1] * sc + sh) +
                       gelu_exact(g_y3[base + 2] * sc + sh) +
                       gelu_exact(g_y3[base + 3] * sc + sh));
    int row = b * NAA + na;
    size_t fi = ((size_t)br * ROWS + row) * DD + d;
    g_feats[fi] = v;
    g_res[fi]   = v;
    g_quant[fi] = 0.0f;

    __nv_bfloat16 h = __float2bfloat16(v);
    __nv_bfloat16 l = __float2bfloat16(v - __bfloat162float(h));
    size_t pb = ((size_t)((br << 10) + row)) * KPAD + d;
    g_res_hi[pb] = h;
    g_res_lo[pb] = l;
}

// ---------------- mma.sync distance GEMM + per-tile top-2 epilogue ----------------
// grid (8 rowtiles, 4 br, 64 coltiles), block 256 (8 warps, 2x4), warp tile 64x32,
// K in 13 chunks of 16 via cp.async double buffering; reg budget <=128 for 2 CTA/SM.
__global__ void __launch_bounds__(256, 2) gemm_step_kernel(int step)
{
    extern __shared__ char dsm[];
    __shared__ float cns[NT];

    int tid = threadIdx.x;
    int lane = tid & 31;
    int wid = tid >> 5;
    int warpM = wid & 1;
    int warpN = wid >> 1;
    int g  = lane >> 2;
    int tig = lane & 3;

    int rowBase = blockIdx.x * 128;
    int br = blockIdx.y;
    int ct = blockIdx.z;
    int brq = br * NQ + step;

    const __nv_bfloat16* aH = g_res_hi + (size_t)((br << 10) + rowBase) * KPAD;
    const __nv_bfloat16* aL = g_res_lo + (size_t)((br << 10) + rowBase) * KPAD;
    const __nv_bfloat16* bH = (const __nv_bfloat16*)g_cbh + ((size_t)brq * VV + (size_t)ct * NT) * KPAD;
    const __nv_bfloat16* bL = (const __nv_bfloat16*)g_cbl + ((size_t)brq * VV + (size_t)ct * NT) * KPAD;

    if (tid < NT) cns[tid] = g_cnorm[(size_t)brq * VV + ct * NT + tid];

    auto load_chunk = [&](int buf, int k0) {
        char* base = dsm + buf * BUF_B;
        int row = tid >> 1, seg = tid & 1;
        #pragma unroll
        for (int s = 0; s < 4; ++s) {
            const __nv_bfloat16* gp = (s == 0) ? aH : (s == 1) ? aL : (s == 2) ? bH : bL;
            uint32_t dst = smem_u32(base + s * SLAB_B + row * 48 + seg * 16);
            const void* src = gp + (size_t)row * KPAD + k0 + seg * 8;
            CP_ASYNC16(dst, src);
        }
        CP_COMMIT();
    };

    float acc[4][4][4];
    #pragma unroll
    for (int t = 0; t < 4; ++t)
        #pragma unroll
        for (int n = 0; n < 4; ++n)
            #pragma unroll
            for (int e = 0; e < 4; ++e) acc[t][n][e] = 0.f;

    load_chunk(0, 0);

    #pragma unroll 1
    for (int c = 0; c < NCH; ++c) {
        if (c + 1 < NCH) { load_chunk((c + 1) & 1, (c + 1) * KC); CP_WAIT(1); }
        else             { CP_WAIT(0); }
        __syncthreads();

        const char* base = dsm + (c & 1) * BUF_B;
        const char* aHs = base;
        const char* aLs = base + SLAB_B;
        const char* bHs = base + 2 * SLAB_B;
        const char* bLs = base + 3 * SLAB_B;

        uint32_t bh[4][2], bl[4][2];
        #pragma unroll
        for (int n = 0; n < 4; ++n) {
            int c0 = warpN * 32 + n * 8 + g;
            const char* pb = bHs + c0 * 48 + tig * 4;
            bh[n][0] = *(const uint32_t*)pb;
            bh[n][1] = *(const uint32_t*)(pb + 16);
            const char* pc = bLs + c0 * 48 + tig * 4;
            bl[n][0] = *(const uint32_t*)pc;
            bl[n][1] = *(const uint32_t*)(pc + 16);
        }
        #pragma unroll
        for (int t = 0; t < 4; ++t) {
            int r0 = warpM * 64 + t * 16 + g;
            const char* pa = aHs + r0 * 48 + tig * 4;
            uint32_t a0 = *(const uint32_t*)pa;
            uint32_t a1 = *(const uint32_t*)(pa + 8 * 48);
            uint32_t a2 = *(const uint32_t*)(pa + 16);
            uint32_t a3 = *(const uint32_t*)(pa + 8 * 48 + 16);
            const char* pl = aLs + r0 * 48 + tig * 4;
            uint32_t l0 = *(const uint32_t*)pl;
            uint32_t l1 = *(const uint32_t*)(pl + 8 * 48);
            uint32_t l2 = *(const uint32_t*)(pl + 16);
            uint32_t l3 = *(const uint32_t*)(pl + 8 * 48 + 16);
            #pragma unroll
            for (int n = 0; n < 4; ++n) {
                mma_bf16(acc[t][n], a0, a1, a2, a3, bh[n][0], bh[n][1]);
                mma_bf16(acc[t][n], l0, l1, l2, l3, bh[n][0], bh[n][1]);
                mma_bf16(acc[t][n], a0, a1, a2, a3, bl[n][0], bl[n][1]);
            }
        }
        __syncthreads();
    }

    // ---- epilogue: per-row top-2 across the 128-code tile ----
    unsigned long long* red = (unsigned long long*)dsm;   // [128][4][2]

    #pragma unroll
    for (int t = 0; t < 4; ++t) {
        #pragma unroll
        for (int rs = 0; rs < 2; ++rs) {
            unsigned long long k1 = ~0ull, k2 = ~0ull;
            #pragma unroll
            for (int n = 0; n < 4; ++n) {
                int lc = warpN * 32 + n * 8 + tig * 2;
                int gc = ct * NT + lc;
                float d0 = cns[lc]     - 2.0f * acc[t][n][rs * 2 + 0];
                float d1 = cns[lc + 1] - 2.0f * acc[t][n][rs * 2 + 1];
                unsigned long long ka = ((unsigned long long)fkey(d0) << 32) | (unsigned)gc;
                unsigned long long kb = ((unsigned long long)fkey(d1) << 32) | (unsigned)(gc + 1);
                if (ka < k1) { k2 = k1; k1 = ka; } else if (ka < k2) k2 = ka;
                if (kb < k1) { k2 = k1; k1 = kb; } else if (kb < k2) k2 = kb;
            }
            #pragma unroll
            for (int off = 1; off <= 2; off <<= 1) {
                unsigned long long o1 = __shfl_xor_sync(0xffffffffu, k1, off);
                unsigned long long o2 = __shfl_xor_sync(0xffffffffu, k2, off);
                unsigned long long n1 = (k1 < o1) ? k1 : o1;
                unsigned long long mx = (k1 < o1) ? o1 : k1;
                unsigned long long mn2 = (k2 < o2) ? k2 : o2;
                k1 = n1;
                k2 = (mx < mn2) ? mx : mn2;
            }
            if (tig == 0) {
                int row = warpM * 64 + t * 16 + rs * 8 + g;
                red[(row * 4 + warpN) * 2 + 0] = k1;
                red[(row * 4 + warpN) * 2 + 1] = k2;
            }
        }
    }
    __syncthreads();

    if (tid < 128) {
        unsigned long long b1 = ~0ull, b2 = ~0ull;
        #pragma unroll
        for (int w = 0; w < 4; ++w)
            #pragma unroll
            for (int e = 0; e < 2; ++e) {
                unsigned long long k = red[(tid * 4 + w) * 2 + e];
                if (k < b1) { b2 = b1; b1 = k; } else if (k < b2) b2 = k;
            }
        size_t ci = ((size_t)((br << 10) + rowBase + tid)) * (NTILES * 2) + ct * 2;
        g_cand[ci] = b1;
        g_cand[ci + 1] = b2;
    }
}

// ---------------- rerank (exact fp32 within delta) + update ----------------
__global__ void rerank_update_kernel(const float* __restrict__ cbAll, int step)
{
    int row = blockIdx.x, br = blockIdx.y;
    int tid = threadIdx.x, lane = tid & 31, w = tid >> 5;

    __shared__ float rsm[DD];
    __shared__ unsigned long long keys[NTILES * 2];
    __shared__ unsigned long long sBest, sExact;

    size_t rbase = ((size_t)br * ROWS + row) * DD;
    if (tid < DD) rsm[tid] = g_res[rbase + tid];
    if (tid < NTILES * 2) keys[tid] = g_cand[((size_t)((br << 10) + row)) * (NTILES * 2) + tid];
    if (tid == 0) { sBest = ~0ull; sExact = ~0ull; }
    __syncthreads();
    if (tid < NTILES * 2) atomicMin(&sBest, keys[tid]);
    __syncthreads();

    float bestA = fkey_inv((unsigned)(sBest >> 32));
    const float* cbq = cbAll + (size_t)(br * NQ + step) * VV * DD;
    const float* cnq = g_cnorm + (size_t)(br * NQ + step) * VV;

    for (int c = w; c < NTILES * 2; c += 8) {
        unsigned long long k = keys[c];
        float da = fkey_inv((unsigned)(k >> 32));
        if (da <= bestA + RERANK_DELTA) {
            int code = (int)(k & 0xFFFFFFFFull);
            const float* cr = cbq + (size_t)code * DD;
            float dot = 0.f;
            for (int d = lane; d < DD; d += 32) dot += rsm[d] * cr[d];
            #pragma unroll
            for (int o = 16; o; o >>= 1) dot += __shfl_xor_sync(0xffffffffu, dot, o);
            if (lane == 0) {
                float de = cnq[code] - 2.0f * dot;
                unsigned long long ke = ((unsigned long long)fkey(de) << 32) | (unsigned)code;
                atomicMin(&sExact, ke);
            }
        }
    }
    __syncthreads();

    int idx = (int)(sExact & 0xFFFFFFFFull);
    const float* q = cbq + (size_t)idx * DD;
    if (tid < DD) {
        float qv = q[tid];
        float r = rsm[tid] - qv;
        g_res[rbase + tid] = r;
        g_quant[rbase + tid] += qv;
        __nv_bfloat16 h = __float2bfloat16(r);
        __nv_bfloat16 l = __float2bfloat16(r - __bfloat162float(h));
        size_t pb = ((size_t)((br << 10) + row)) * KPAD + tid;
        g_res_hi[pb] = h;
        g_res_lo[pb] = l;
    }
    if (tid == 0) g_idx[(br * NQ + step) * ROWS + row] = idx;
}

// ---------------- final output ----------------
__global__ void final_kernel(float* __restrict__ out, int n)
{
    int i = blockIdx.x * 256 + threadIdx.x;
    if (i >= n) return;
    if (i < N_FT) {
        float f = g_feats[i];
        out[i] = f + (g_quant[i] - f);
    } else {
        int j = i - N_FT;
        out[i] = (j < N_IDX) ? (float)g_idx[j] : 0.0f;
    }
}

// ---------------- launch ----------------
extern "C" void kernel_launch(void* const* d_in, const int* in_sizes, int n_in,
                              void* d_out, int out_size)
{
    const float* x   = (const float*)d_in[0];
    const float* w11 = (const float*)d_in[1];
    const float* w12 = (const float*)d_in[2];
    const float* w13 = (const float*)d_in[3];
    const float* w14 = (const float*)d_in[4];
    const float* b1  = (const float*)d_in[5];
    const float* g1  = (const float*)d_in[6];
    const float* be1 = (const float*)d_in[7];
    const float* w21 = (const float*)d_in[8];
    const float* w22 = (const float*)d_in[9];
    const float* w23 = (const float*)d_in[10];
    const float* w24 = (const float*)d_in[11];
    const float* b2  = (const float*)d_in[12];
    const float* g2  = (const float*)d_in[13];
    const float* be2 = (const float*)d_in[14];
    const float* cb  = (const float*)d_in[15];

    int K1a = in_sizes[1] / CC,  K1b = in_sizes[2] / CC;
    int K1c = in_sizes[3] / CC,  K1d = in_sizes[4] / CC;
    int K2a = in_sizes[8] / (CC * CC),  K2b = in_sizes[9] / (CC * CC);
    int K2c = in_sizes[10] / (CC * CC), K2d = in_sizes[11] / (CC * CC);

    cudaFuncSetAttribute(gemm_step_kernel, cudaFuncAttributeMaxDynamicSharedMemorySize, DSMEM);

    conv1_kernel<<<dim3(NAA, BB, NBR), 256>>>(x, w11, w12, w13, w14, b1, K1a, K1b, K1c, K1d);
    conv2_kernel<<<dim3(NAA, BB, NBR), 256>>>(w21, w22, w23, w24, b2, g1, be1, K2a, K2b, K2c, K2d);
    feats_pack_kernel<<<dim3(NAA + 1024, BB, NBR), 256>>>(cb, g2, be2);

    for (int s = 0; s < NQ; ++s) {
        gemm_step_kernel<<<dim3(ROWS / 128, NBR, NTILES), 256, DSMEM>>>(s);
        rerank_update_kernel<<<dim3(ROWS, NBR), 256>>>(cb, s);
    }

    final_kernel<<<(out_size + 255) / 256, 256>>>((float*)d_out, out_size);
}

// round 10
// speedup vs baseline: 2.3532x; 1.2715x over previous
#include <cuda_runtime.h>
#include <cuda_bf16.h>
#include <cstdint>

// ---------------- problem constants ----------------
#define NBR 4
#define BB  8
#define CC  8
#define NAA 128
#define T0  200
#define T1  100
#define DD  200
#define VV  8192
#define NQ  8
#define ROWS (BB*NAA)        // 1024

#define N_Y1  (NBR*BB*CC*NAA*T0)
#define N_Y3  (NBR*BB*CC*NAA*T1)
#define N_FT  (NBR*ROWS*DD)
#define N_IDX (NBR*NQ*ROWS)

#define KPAD 208             // padded K (bf16): 200 data + 8 zeros, 13 x 16
#define KC   16              // K chunk (one k16 per chunk)
#define NCH  (KPAD/KC)       // 13
#define NT   128             // codes per col tile
#define NTILES (VV/NT)       // 64
#define RERANK_DELTA 0.08f

// smem slab: 128 rows x 16 bf16 (32B) padded to 48B per row
#define SLAB_B 6144          // 128*48
#define BUF_B  (3*SLAB_B)    // a_hi, b_hi, b_lo = 18432
#define NSTAGE 3
#define DSMEM  (NSTAGE*BUF_B)   // 55296

// ---------------- scratch ----------------
// Arrays touched by cp.async / vector loads are force-aligned to 16B —
// cp.async.16 faults on misaligned global addresses; base alignment of
// __device__ arrays is otherwise layout-dependent (R8 failure mode).
__device__ float g_y1[N_Y1];
__device__ float g_y3[N_Y3];
__device__ float g_part1[2*NBR*BB*4*NAA];    // [which][br,b,group][na]
__device__ float g_part2[2*NBR*BB*4*NAA];
__device__ float g_feats[N_FT];
__device__ float g_res[N_FT];
__device__ float g_quant[N_FT];
__device__ float g_cnorm[NBR*NQ*VV];
__device__ int   g_idx[N_IDX];
__device__ __align__(16) uint32_t g_cbh[(size_t)NBR*NQ*VV*(KPAD/2)];  // bf16 hi image; pads stay 0
__device__ __align__(16) uint32_t g_cbl[(size_t)NBR*NQ*VV*(KPAD/2)];  // bf16 lo image; pads stay 0
__device__ __align__(16) __nv_bfloat16 g_res_hi[NBR*ROWS*KPAD];       // zero-init pads stay zero
__device__ __align__(16) unsigned long long g_cand[(size_t)NBR*ROWS*NTILES*2];

// ---------------- helpers ----------------
__device__ __forceinline__ float gelu_exact(float v) {
    return 0.5f * v * (1.0f + erff(v * 0.70710678118654752440f));
}
__device__ __forceinline__ unsigned fkey(float f) {
    unsigned u = __float_as_uint(f);
    return (u & 0x80000000u) ? ~u : (u | 0x80000000u);
}
__device__ __forceinline__ float fkey_inv(unsigned k) {
    unsigned u = (k & 0x80000000u) ? (k & 0x7FFFFFFFu) : ~k;
    return __uint_as_float(u);
}
__device__ __forceinline__ uint32_t smem_u32(const void* p) {
    uint32_t a;
    asm("{ .reg .u64 t; cvta.to.shared.u64 t, %1; cvt.u32.u64 %0, t; }" : "=r"(a) : "l"(p));
    return a;
}
#define CP_ASYNC16(dst, src) \
    asm volatile("cp.async.cg.shared.global [%0], [%1], 16;" :: "r"(dst), "l"(src))
#define CP_COMMIT() asm volatile("cp.async.commit_group;" ::: "memory")
#define CP_WAIT(n)  asm volatile("cp.async.wait_group %0;" :: "n"(n) : "memory")

__device__ __forceinline__ void mma_bf16(float* c,
    uint32_t a0, uint32_t a1, uint32_t a2, uint32_t a3, uint32_t b0, uint32_t b1)
{
    asm volatile("mma.sync.aligned.m16n8k16.row.col.f32.bf16.bf16.f32 "
        "{%0,%1,%2,%3}, {%4,%5,%6,%7}, {%8,%9}, {%0,%1,%2,%3};"
        : "+f"(c[0]), "+f"(c[1]), "+f"(c[2]), "+f"(c[3])
        : "r"(a0), "r"(a1), "r"(a2), "r"(a3), "r"(b0), "r"(b1));
}

// ---------------- conv1: fused group-stat partials; K-specialized ----------------
#define CONV1_BODY(KV) { \
    const int base0 = 16 + t - ((KV - 1) >> 1); \
    _Pragma("unroll") \
    for (int c = 0; c < CC; ++c) { \
        float acc = b1v[c]; \
        const float* wr = ws + c * KV; \
        _Pragma("unroll") \
        for (int k = 0; k < KV; ++k) acc += xs[base0 + k] * wr[k]; \
        y[c] = acc; \
    } }

__global__ void conv1_kernel(const float* __restrict__ x,
                             const float* __restrict__ w0, const float* __restrict__ w1,
                             const float* __restrict__ w2, const float* __restrict__ w3,
                             const float* __restrict__ b1,
                             int k0, int k1, int k2, int k3)
{
    int na = blockIdx.x, b = blockIdx.y, br = blockIdx.z;
    int tid = threadIdx.x, lane = tid & 31, wid = tid >> 5;

    const float* w; int K;
    if (br == 0)      { w = w0; K = k0; }
    else if (br == 1) { w = w1; K = k1; }
    else if (br == 2) { w = w2; K = k2; }
    else              { w = w3; K = k3; }

    __shared__ float xs[T0 + 32];
    __shared__ float ws[CC * 24];
    __shared__ float wred[8][8];

    if (tid < T0) xs[16 + tid] = x[(size_t)(b * NAA + na) * T0 + tid];
    else if (tid < T0 + 16) xs[tid - T0] = 0.f;
    else if (tid < T0 + 32) xs[tid] = 0.f;
    if (tid < CC * K) ws[tid] = w[tid];
    __syncthreads();

    bool act = tid < T0;
    int t = act ? tid : 0;
    const float* b1v = b1 + br * CC;
    float y[CC];
    if (K == 21)      CONV1_BODY(21)
    else if (K == 15) CONV1_BODY(15)
    else if (K == 9)  CONV1_BODY(9)
    else if (K == 5)  CONV1_BODY(5)
    else {
        int pad = (K - 1) >> 1;
        int base0 = 16 + t - pad;
        for (int c = 0; c < CC; ++c) {
            float acc = b1v[c];
            const float* wr = ws + c * K;
            for (int k = 0; k < K; ++k) acc += xs[base0 + k] * wr[k];
            y[c] = acc;
        }
    }
    if (act) {
        size_t outBase = (((size_t)(br * BB + b) * CC) * NAA + na) * T0 + t;
        #pragma unroll
        for (int c = 0; c < CC; ++c) g_y1[outBase + (size_t)c * NAA * T0] = y[c];
    }

    float pv[8];
    #pragma unroll
    for (int gq = 0; gq < 4; ++gq) {
        float a0 = act ? y[2 * gq] : 0.f;
        float a1 = act ? y[2 * gq + 1] : 0.f;
        pv[gq]     = a0 + a1;
        pv[4 + gq] = a0 * a0 + a1 * a1;
    }
    #pragma unroll
    for (int v = 0; v < 8; ++v)
        #pragma unroll
        for (int o = 16; o; o >>= 1) pv[v] += __shfl_xor_sync(0xffffffffu, pv[v], o);
    if (lane == 0) {
        #pragma unroll
        for (int v = 0; v < 8; ++v) wred[wid][v] = pv[v];
    }
    __syncthreads();
    if (tid < 8) {
        float s = 0.f;
        #pragma unroll
        for (int ww = 0; ww < 8; ++ww) s += wred[ww][tid];
        int gq = tid & 3, which = tid >> 2;
        g_part1[((which * (NBR * BB) + br * BB + b) * 4 + gq) * NAA + na] = s;
    }
}

// ---------------- conv2: GN1(from partials)+gelu+pool2 + conv + stat2 partials ----------------
#define CONV2_TAPS(KV) { \
    const int base0 = 8 + t - ((KV - 1) >> 1); \
    _Pragma("unroll") \
    for (int it = 0; it < 4; ++it) { \
        int co = 2 * it + hi; \
        float acc = b2[br * CC + co]; \
        _Pragma("unroll") \
        for (int ci = 0; ci < CC; ++ci) { \
            const float* wr = ws + (co * CC + ci) * KV; \
            const float* yr = &yin[ci][base0]; \
            _Pragma("unroll") \
            for (int k = 0; k < KV; ++k) acc += yr[k] * wr[k]; \
        } \
        accv[it] = acc; \
    } }

__global__ void conv2_kernel(const float* __restrict__ w0, const float* __restrict__ w1,
                             const float* __restrict__ w2, const float* __restrict__ w3,
                             const float* __restrict__ b2,
                             const float* __restrict__ g1, const float* __restrict__ be1,
                             int k0, int k1, int k2, int k3)
{
    int na = blockIdx.x, b = blockIdx.y, br = blockIdx.z;
    int tid = threadIdx.x, lane = tid & 31, wid = tid >> 5;

    const float* w; int K;
    if (br == 0)      { w = w0; K = k0; }
    else if (br == 1) { w = w1; K = k1; }
    else if (br == 2) { w = w2; K = k2; }
    else              { w = w3; K = k3; }

    __shared__ float yin[CC][T1 + 16];
    __shared__ float ws[CC * CC * 12];
    __shared__ float2 st[4];
    __shared__ float wred[8][8];

    if (wid < 4) {
        float s = 0.f, q = 0.f;
        int b0 = ((br * BB + b) * 4 + wid) * NAA;
        #pragma unroll
        for (int j = 0; j < 4; ++j) {
            s += g_part1[b0 + lane + 32 * j];
            q += g_part1[NBR * BB * 4 * NAA + b0 + lane + 32 * j];
        }
        #pragma unroll
        for (int o = 16; o; o >>= 1) {
            s += __shfl_xor_sync(0xffffffffu, s, o);
            q += __shfl_xor_sync(0xffffffffu, q, o);
        }
        if (lane == 0) {
            float n = 2.0f * NAA * T0;
            float m = s / n;
            float var = q / n - m * m;
            st[wid] = make_float2(m, rsqrtf(var + 1e-5f));
        }
    }
    for (int i = tid; i < CC * CC * K; i += 256) ws[i] = w[i];

    int hi = (tid >= 100) ? 1 : 0;
    int t  = tid - 100 * hi;
    bool act = (tid < 200);
    if (tid >= 200) {
        for (int i = tid - 200; i < 128; i += 56) {
            int ch = i >> 4, j = i & 15;
            yin[ch][(j < 8) ? j : (100 + j)] = 0.f;
        }
    }
    __syncthreads();

    #pragma unroll
    for (int it = 0; it < 4; ++it) {
        int ci = 2 * it + hi;
        if (act) {
            float m = st[ci >> 1].x, r = st[ci >> 1].y;
            float sc = r * g1[br * CC + ci];
            float sh = be1[br * CC + ci] - m * sc;
            size_t base = (((size_t)(br * BB + b) * CC + ci) * NAA + na) * T0 + 2 * t;
            float a0 = gelu_exact(g_y1[base]     * sc + sh);
            float a1 = gelu_exact(g_y1[base + 1] * sc + sh);
            yin[ci][8 + t] = 0.5f * (a0 + a1);
        }
    }
    __syncthreads();

    float accv[4] = {0.f, 0.f, 0.f, 0.f};
    if (act) {
        if (K == 9)      CONV2_TAPS(9)
        else if (K == 7) CONV2_TAPS(7)
        else if (K == 5) CONV2_TAPS(5)
        else if (K == 3) CONV2_TAPS(3)
        else {
            int base0 = 8 + t - ((K - 1) >> 1);
            for (int it = 0; it < 4; ++it) {
                int co = 2 * it + hi;
                float acc = b2[br * CC + co];
                for (int ci = 0; ci < CC; ++ci) {
                    const float* wr = ws + (co * CC + ci) * K;
                    const float* yr = &yin[ci][base0];
                    for (int k = 0; k < K; ++k) acc += yr[k] * wr[k];
                }
                accv[it] = acc;
            }
        }
        #pragma unroll
        for (int it = 0; it < 4; ++it) {
            int co = 2 * it + hi;
            g_y3[(((size_t)(br * BB + b) * CC + co) * NAA + na) * T1 + t] = accv[it];
        }
    }

    float pv[8];
    #pragma unroll
    for (int it = 0; it < 4; ++it) {
        float a = act ? accv[it] : 0.f;
        pv[it] = a;
        pv[4 + it] = a * a;
    }
    #pragma unroll
    for (int v = 0; v < 8; ++v)
        #pragma unroll
        for (int o = 16; o; o >>= 1) pv[v] += __shfl_xor_sync(0xffffffffu, pv[v], o);
    if (lane == 0) {
        #pragma unroll
        for (int v = 0; v < 8; ++v) wred[wid][v] = pv[v];
    }
    __syncthreads();
    if (tid < 8) {
        float s = 0.f;
        #pragma unroll
        for (int ww = 0; ww < 8; ++ww) s += wred[ww][tid];
        int gq = tid & 3, which = tid >> 2;
        g_part2[((which * (NBR * BB) + br * BB + b) * 4 + gq) * NAA + na] = s;
    }
}

// ---------------- feats (GN2+gelu+pool4+transpose) fused with codebook pack+cnorm ----------------
__global__ void feats_pack_kernel(const float* __restrict__ cbAll,
                                  const float* __restrict__ g2, const float* __restrict__ be2)
{
    int bx = blockIdx.x, b = blockIdx.y, br = blockIdx.z;
    int tid = threadIdx.x, lane = tid & 31, wid = tid >> 5;

    if (bx >= NAA) {
        // ---- pack part: warp per code ----
        int px = bx - NAA;
        int cid = (px * BB + b) * 8 + wid;
        size_t gcode = (size_t)br * (NQ * VV) + cid;
        const float* src = cbAll + gcode * DD;
        uint32_t* dh = g_cbh + gcode * (KPAD / 2);
        uint32_t* dl = g_cbl + gcode * (KPAD / 2);
        float s = 0.f;
        #pragma unroll
        for (int p = lane; p < DD / 2; p += 32) {
            float v0 = src[2 * p], v1 = src[2 * p + 1];
            s += v0 * v0 + v1 * v1;
            __nv_bfloat16 h0 = __float2bfloat16(v0), h1 = __float2bfloat16(v1);
            __nv_bfloat16 l0 = __float2bfloat16(v0 - __bfloat162float(h0));
            __nv_bfloat16 l1 = __float2bfloat16(v1 - __bfloat162float(h1));
            dh[p] = ((uint32_t)__bfloat16_as_ushort(h1) << 16) | __bfloat16_as_ushort(h0);
            dl[p] = ((uint32_t)__bfloat16_as_ushort(l1) << 16) | __bfloat16_as_ushort(l0);
        }
        #pragma unroll
        for (int o = 16; o; o >>= 1) s += __shfl_xor_sync(0xffffffffu, s, o);
        if (lane == 0) g_cnorm[gcode] = s;
        return;
    }

    // ---- feats part ----
    int na = bx;
    __shared__ float2 st[4];
    if (wid < 4) {
        float s = 0.f, q = 0.f;
        int b0 = ((br * BB + b) * 4 + wid) * NAA;
        #pragma unroll
        for (int j = 0; j < 4; ++j) {
            s += g_part2[b0 + lane + 32 * j];
            q += g_part2[NBR * BB * 4 * NAA + b0 + lane + 32 * j];
        }
        #pragma unroll
        for (int o = 16; o; o >>= 1) {
            s += __shfl_xor_sync(0xffffffffu, s, o);
            q += __shfl_xor_sync(0xffffffffu, q, o);
        }
        if (lane == 0) {
            float n = 2.0f * NAA * T1;
            float m = s / n;
            float var = q / n - m * m;
            st[wid] = make_float2(m, rsqrtf(var + 1e-5f));
        }
    }
    __syncthreads();

    int d = tid;
    if (d >= DD) return;
    int t = d >> 3;
    int c = d & 7;
    float m = st[c >> 1].x, r = st[c >> 1].y;
    float sc = r * g2[br * CC + c];
    float sh = be2[br * CC + c] - m * sc;

    size_t base = (((size_t)(br * BB + b) * CC + c) * NAA + na) * T1 + 4 * t;
    float v = 0.25f * (gelu_exact(g_y3[base]     * sc + sh) +
                       gelu_exact(g_y3[base + 1] * sc + sh) +
                       gelu_exact(g_y3[base + 2] * sc + sh) +
                       gelu_exact(g_y3[base + 3] * sc + sh));
    int row = b * NAA + na;
    size_t fi = ((size_t)br * ROWS + row) * DD + d;
    g_feats[fi] = v;
    g_res[fi]   = v;
    g_quant[fi] = 0.0f;
    g_res_hi[((size_t)((br << 10) + row)) * KPAD + d] = __float2bfloat16(v);
}

// ---------------- mma.sync distance GEMM + per-tile top-2 epilogue ----------------
// grid (8 rowtiles, 4 br, 64 coltiles), block 256 (8 warps, 2x4), warp tile 64x32.
// Coarse distance uses hi_a·(hi_b + lo_b): 2 MMAs per acc; residual-lo dropped
// (exact fp32 rerank recovers indices). 3-stage cp.async pipeline, 1 sync/chunk.
__global__ void __launch_bounds__(256, 2) gemm_step_kernel(int step)
{
    extern __shared__ char dsm[];
    __shared__ float cns[NT];

    int tid = threadIdx.x;
    int lane = tid & 31;
    int wid = tid >> 5;
    int warpM = wid & 1;
    int warpN = wid >> 1;
    int g  = lane >> 2;
    int tig = lane & 3;

    int rowBase = blockIdx.x * 128;
    int br = blockIdx.y;
    int ct = blockIdx.z;
    int brq = br * NQ + step;

    const __nv_bfloat16* aH = g_res_hi + (size_t)((br << 10) + rowBase) * KPAD;
    const __nv_bfloat16* bH = (const __nv_bfloat16*)g_cbh + ((size_t)brq * VV + (size_t)ct * NT) * KPAD;
    const __nv_bfloat16* bL = (const __nv_bfloat16*)g_cbl + ((size_t)brq * VV + (size_t)ct * NT) * KPAD;

    if (tid < NT) cns[tid] = g_cnorm[(size_t)brq * VV + ct * NT + tid];

    // one 16B cp.async per thread per slab; slabs: aH, bH, bL
    auto load_chunk = [&](int buf, int k0) {
        char* base = dsm + buf * BUF_B;
        int row = tid >> 1, seg = tid & 1;
        uint32_t d0 = smem_u32(base + row * 48 + seg * 16);
        CP_ASYNC16(d0,              aH + (size_t)row * KPAD + k0 + seg * 8);
        CP_ASYNC16(d0 + SLAB_B,     bH + (size_t)row * KPAD + k0 + seg * 8);
        CP_ASYNC16(d0 + 2 * SLAB_B, bL + (size_t)row * KPAD + k0 + seg * 8);
        CP_COMMIT();
    };

    float acc[4][4][4];
    #pragma unroll
    for (int t = 0; t < 4; ++t)
        #pragma unroll
        for (int n = 0; n < 4; ++n)
            #pragma unroll
            for (int e = 0; e < 4; ++e) acc[t][n][e] = 0.f;

    load_chunk(0, 0);
    load_chunk(1, KC);

    #pragma unroll 1
    for (int c = 0; c < NCH; ++c) {
        if (c + 2 < NCH) CP_WAIT(1);   // chunk c done; c+1 may be in flight
        else             CP_WAIT(0);   // drain at the tail
        __syncthreads();               // chunk c visible to all; buf (c+2)%3 free
        if (c + 2 < NCH) load_chunk((c + 2) % NSTAGE, (c + 2) * KC);

        const char* base = dsm + (c % NSTAGE) * BUF_B;
        const char* aHs = base;
        const char* bHs = base + SLAB_B;
        const char* bLs = base + 2 * SLAB_B;

        uint32_t bh[4][2], bl[4][2];
        #pragma unroll
        for (int n = 0; n < 4; ++n) {
            int c0 = warpN * 32 + n * 8 + g;
            const char* pb = bHs + c0 * 48 + tig * 4;
            bh[n][0] = *(const uint32_t*)pb;
            bh[n][1] = *(const uint32_t*)(pb + 16);
            const char* pc = bLs + c0 * 48 + tig * 4;
            bl[n][0] = *(const uint32_t*)pc;
            bl[n][1] = *(const uint32_t*)(pc + 16);
        }
        #pragma unroll
        for (int t = 0; t < 4; ++t) {
            int r0 = warpM * 64 + t * 16 + g;
            const char* pa = aHs + r0 * 48 + tig * 4;
            uint32_t a0 = *(const uint32_t*)pa;
            uint32_t a1 = *(const uint32_t*)(pa + 8 * 48);
            uint32_t a2 = *(const uint32_t*)(pa + 16);
            uint32_t a3 = *(const uint32_t*)(pa + 8 * 48 + 16);
            #pragma unroll
            for (int n = 0; n < 4; ++n) {
                mma_bf16(acc[t][n], a0, a1, a2, a3, bh[n][0], bh[n][1]);
                mma_bf16(acc[t][n], a0, a1, a2, a3, bl[n][0], bl[n][1]);
            }
        }
    }
    __syncthreads();   // all compute done before epilogue reuses smem

    // ---- epilogue: per-row top-2 across the 128-code tile ----
    unsigned long long* red = (unsigned long long*)dsm;   // [128][4][2]

    #pragma unroll
    for (int t = 0; t < 4; ++t) {
        #pragma unroll
        for (int rs = 0; rs < 2; ++rs) {
            unsigned long long k1 = ~0ull, k2 = ~0ull;
            #pragma unroll
            for (int n = 0; n < 4; ++n) {
                int lc = warpN * 32 + n * 8 + tig * 2;
                int gc = ct * NT + lc;
                float d0 = cns[lc]     - 2.0f * acc[t][n][rs * 2 + 0];
                float d1 = cns[lc + 1] - 2.0f * acc[t][n][rs * 2 + 1];
                unsigned long long ka = ((unsigned long long)fkey(d0) << 32) | (unsigned)gc;
                unsigned long long kb = ((unsigned long long)fkey(d1) << 32) | (unsigned)(gc + 1);
                if (ka < k1) { k2 = k1; k1 = ka; } else if (ka < k2) k2 = ka;
                if (kb < k1) { k2 = k1; k1 = kb; } else if (kb < k2) k2 = kb;
            }
            #pragma unroll
            for (int off = 1; off <= 2; off <<= 1) {
                unsigned long long o1 = __shfl_xor_sync(0xffffffffu, k1, off);
                unsigned long long o2 = __shfl_xor_sync(0xffffffffu, k2, off);
                unsigned long long n1 = (k1 < o1) ? k1 : o1;
                unsigned long long mx = (k1 < o1) ? o1 : k1;
                unsigned long long mn2 = (k2 < o2) ? k2 : o2;
                k1 = n1;
                k2 = (mx < mn2) ? mx : mn2;
            }
            if (tig == 0) {
                int row = warpM * 64 + t * 16 + rs * 8 + g;
                red[(row * 4 + warpN) * 2 + 0] = k1;
                red[(row * 4 + warpN) * 2 + 1] = k2;
            }
        }
    }
    __syncthreads();

    if (tid < 128) {
        unsigned long long b1 = ~0ull, b2 = ~0ull;
        #pragma unroll
        for (int w = 0; w < 4; ++w)
            #pragma unroll
            for (int e = 0; e < 2; ++e) {
                unsigned long long k = red[(tid * 4 + w) * 2 + e];
                if (k < b1) { b2 = b1; b1 = k; } else if (k < b2) b2 = k;
            }
        size_t ci = ((size_t)((br << 10) + rowBase + tid)) * (NTILES * 2) + ct * 2;
        g_cand[ci] = b1;
        g_cand[ci + 1] = b2;
    }
}

// ---------------- rerank (exact fp32 within delta) + update ----------------
__global__ void rerank_update_kernel(const float* __restrict__ cbAll, int step)
{
    int row = blockIdx.x, br = blockIdx.y;
    int tid = threadIdx.x, lane = tid & 31, w = tid >> 5;

    __shared__ float rsm[DD];
    __shared__ unsigned long long keys[NTILES * 2];
    __shared__ unsigned long long sBest, sExact;

    size_t rbase = ((size_t)br * ROWS + row) * DD;
    if (tid < DD) rsm[tid] = g_res[rbase + tid];
    if (tid < NTILES * 2) keys[tid] = g_cand[((size_t)((br << 10) + row)) * (NTILES * 2) + tid];
    if (tid == 0) { sBest = ~0ull; sExact = ~0ull; }
    __syncthreads();
    if (tid < NTILES * 2) atomicMin(&sBest, keys[tid]);
    __syncthreads();

    float bestA = fkey_inv((unsigned)(sBest >> 32));
    const float* cbq = cbAll + (size_t)(br * NQ + step) * VV * DD;
    const float* cnq = g_cnorm + (size_t)(br * NQ + step) * VV;

    for (int c = w; c < NTILES * 2; c += 8) {
        unsigned long long k = keys[c];
        float da = fkey_inv((unsigned)(k >> 32));
        if (da <= bestA + RERANK_DELTA) {
            int code = (int)(k & 0xFFFFFFFFull);
            const float* cr = cbq + (size_t)code * DD;
            float dot = 0.f;
            for (int d = lane; d < DD; d += 32) dot += rsm[d] * cr[d];
            #pragma unroll
            for (int o = 16; o; o >>= 1) dot += __shfl_xor_sync(0xffffffffu, dot, o);
            if (lane == 0) {
                float de = cnq[code] - 2.0f * dot;
                unsigned long long ke = ((unsigned long long)fkey(de) << 32) | (unsigned)code;
                atomicMin(&sExact, ke);
            }
        }
    }
    __syncthreads();

    int idx = (int)(sExact & 0xFFFFFFFFull);
    const float* q = cbq + (size_t)idx * DD;
    if (tid < DD) {
        float qv = q[tid];
        float r = rsm[tid] - qv;
        g_res[rbase + tid] = r;
        g_quant[rbase + tid] += qv;
        g_res_hi[((size_t)((br << 10) + row)) * KPAD + tid] = __float2bfloat16(r);
    }
    if (tid == 0) g_idx[(br * NQ + step) * ROWS + row] = idx;
}

// ---------------- final output ----------------
__global__ void final_kernel(float* __restrict__ out, int n)
{
    int i = blockIdx.x * 256 + threadIdx.x;
    if (i >= n) return;
    if (i < N_FT) {
        float f = g_feats[i];
        out[i] = f + (g_quant[i] - f);
    } else {
        int j = i - N_FT;
        out[i] = (j < N_IDX) ? (float)g_idx[j] : 0.0f;
    }
}

// ---------------- launch ----------------
extern "C" void kernel_launch(void* const* d_in, const int* in_sizes, int n_in,
                              void* d_out, int out_size)
{
    const float* x   = (const float*)d_in[0];
    const float* w11 = (const float*)d_in[1];
    const float* w12 = (const float*)d_in[2];
    const float* w13 = (const float*)d_in[3];
    const float* w14 = (const float*)d_in[4];
    const float* b1  = (const float*)d_in[5];
    const float* g1  = (const float*)d_in[6];
    const float* be1 = (const float*)d_in[7];
    const float* w21 = (const float*)d_in[8];
    const float* w22 = (const float*)d_in[9];
    const float* w23 = (const float*)d_in[10];
    const float* w24 = (const float*)d_in[11];
    const float* b2  = (const float*)d_in[12];
    const float* g2  = (const float*)d_in[13];
    const float* be2 = (const float*)d_in[14];
    const float* cb  = (const float*)d_in[15];

    int K1a = in_sizes[1] / CC,  K1b = in_sizes[2] / CC;
    int K1c = in_sizes[3] / CC,  K1d = in_sizes[4] / CC;
    int K2a = in_sizes[8] / (CC * CC),  K2b = in_sizes[9] / (CC * CC);
    int K2c = in_sizes[10] / (CC * CC), K2d = in_sizes[11] / (CC * CC);

    cudaFuncSetAttribute(gemm_step_kernel, cudaFuncAttributeMaxDynamicSharedMemorySize, DSMEM);

    conv1_kernel<<<dim3(NAA, BB, NBR), 256>>>(x, w11, w12, w13, w14, b1, K1a, K1b, K1c, K1d);
    conv2_kernel<<<dim3(NAA, BB, NBR), 256>>>(w21, w22, w23, w24, b2, g1, be1, K2a, K2b, K2c, K2d);
    feats_pack_kernel<<<dim3(NAA + 1024, BB, NBR), 256>>>(cb, g2, be2);

    for (int s = 0; s < NQ; ++s) {
        gemm_step_kernel<<<dim3(ROWS / 128, NBR, NTILES), 256, DSMEM>>>(s);
        rerank_update_kernel<<<dim3(ROWS, NBR), 256>>>(cb, s);
    }

    final_kernel<<<(out_size + 255) / 256, 256>>>((float*)d_out, out_size);
}

// round 11
// speedup vs baseline: 2.8583x; 1.2147x over previous
#include <cuda_runtime.h>
#include <cuda_bf16.h>
#include <cstdint>

// ---------------- problem constants ----------------
#define NBR 4
#define BB  8
#define CC  8
#define NAA 128
#define T0  200
#define T1  100
#define DD  200
#define VV  8192
#define NQ  8
#define ROWS (BB*NAA)        // 1024

#define N_Y1  (NBR*BB*CC*NAA*T0)
#define N_Y3  (NBR*BB*CC*NAA*T1)
#define N_FT  (NBR*ROWS*DD)
#define N_IDX (NBR*NQ*ROWS)

#define KPAD 208             // padded K (bf16): 200 data + 8 zeros, 13 x 16
#define KC   16              // K chunk (one k16 per chunk)
#define NCH  (KPAD/KC)       // 13
#define NT   128             // codes per col tile
#define NTILES (VV/NT)       // 64
#define RERANK_DELTA 0.25f   // wide exact-rerank window (>10 sigma of coarse noise)

// smem slab: 128 rows x 16 bf16 (32B) padded to 48B per row
#define SLAB_B 6144          // 128*48
#define BUF_B  (2*SLAB_B)    // a_hi, b_hi = 12288
#define NSTAGE 3
#define DSMEM  (NSTAGE*BUF_B)   // 36864

// ---------------- scratch ----------------
// Arrays touched by cp.async / vector loads are force-aligned to 16B —
// cp.async.16 faults on misaligned global addresses; base alignment of
// __device__ arrays is otherwise layout-dependent (R8 failure mode).
__device__ float g_y1[N_Y1];
__device__ float g_y3[N_Y3];
__device__ float g_part1[2*NBR*BB*4*NAA];    // [which][br,b,group][na]
__device__ float g_part2[2*NBR*BB*4*NAA];
__device__ float g_feats[N_FT];
__device__ float g_res[N_FT];
__device__ float g_quant[N_FT];
__device__ float g_cnorm[NBR*NQ*VV];
__device__ int   g_idx[N_IDX];
__device__ __align__(16) uint32_t g_cbh[(size_t)NBR*NQ*VV*(KPAD/2)];  // bf16 hi image; pads stay 0
__device__ __align__(16) __nv_bfloat16 g_res_hi[NBR*ROWS*KPAD];       // zero-init pads stay zero
__device__ __align__(16) unsigned long long g_cand[(size_t)NBR*ROWS*NTILES*2];

// ---------------- helpers ----------------
__device__ __forceinline__ float gelu_exact(float v) {
    return 0.5f * v * (1.0f + erff(v * 0.70710678118654752440f));
}
__device__ __forceinline__ unsigned fkey(float f) {
    unsigned u = __float_as_uint(f);
    return (u & 0x80000000u) ? ~u : (u | 0x80000000u);
}
__device__ __forceinline__ float fkey_inv(unsigned k) {
    unsigned u = (k & 0x80000000u) ? (k & 0x7FFFFFFFu) : ~k;
    return __uint_as_float(u);
}
__device__ __forceinline__ uint32_t smem_u32(const void* p) {
    uint32_t a;
    asm("{ .reg .u64 t; cvta.to.shared.u64 t, %1; cvt.u32.u64 %0, t; }" : "=r"(a) : "l"(p));
    return a;
}
#define CP_ASYNC16(dst, src) \
    asm volatile("cp.async.cg.shared.global [%0], [%1], 16;" :: "r"(dst), "l"(src))
#define CP_COMMIT() asm volatile("cp.async.commit_group;" ::: "memory")
#define CP_WAIT(n)  asm volatile("cp.async.wait_group %0;" :: "n"(n) : "memory")

__device__ __forceinline__ void mma_bf16(float* c,
    uint32_t a0, uint32_t a1, uint32_t a2, uint32_t a3, uint32_t b0, uint32_t b1)
{
    asm volatile("mma.sync.aligned.m16n8k16.row.col.f32.bf16.bf16.f32 "
        "{%0,%1,%2,%3}, {%4,%5,%6,%7}, {%8,%9}, {%0,%1,%2,%3};"
        : "+f"(c[0]), "+f"(c[1]), "+f"(c[2]), "+f"(c[3])
        : "r"(a0), "r"(a1), "r"(a2), "r"(a3), "r"(b0), "r"(b1));
}

// ---------------- conv1: fused group-stat partials; K-specialized ----------------
#define CONV1_BODY(KV) { \
    const int base0 = 16 + t - ((KV - 1) >> 1); \
    _Pragma("unroll") \
    for (int c = 0; c < CC; ++c) { \
        float acc = b1v[c]; \
        const float* wr = ws + c * KV; \
        _Pragma("unroll") \
        for (int k = 0; k < KV; ++k) acc += xs[base0 + k] * wr[k]; \
        y[c] = acc; \
    } }

__global__ void conv1_kernel(const float* __restrict__ x,
                             const float* __restrict__ w0, const float* __restrict__ w1,
                             const float* __restrict__ w2, const float* __restrict__ w3,
                             const float* __restrict__ b1,
                             int k0, int k1, int k2, int k3)
{
    int na = blockIdx.x, b = blockIdx.y, br = blockIdx.z;
    int tid = threadIdx.x, lane = tid & 31, wid = tid >> 5;

    const float* w; int K;
    if (br == 0)      { w = w0; K = k0; }
    else if (br == 1) { w = w1; K = k1; }
    else if (br == 2) { w = w2; K = k2; }
    else              { w = w3; K = k3; }

    __shared__ float xs[T0 + 32];
    __shared__ float ws[CC * 24];
    __shared__ float wred[8][8];

    if (tid < T0) xs[16 + tid] = x[(size_t)(b * NAA + na) * T0 + tid];
    else if (tid < T0 + 16) xs[tid - T0] = 0.f;
    else if (tid < T0 + 32) xs[tid] = 0.f;
    if (tid < CC * K) ws[tid] = w[tid];
    __syncthreads();

    bool act = tid < T0;
    int t = act ? tid : 0;
    const float* b1v = b1 + br * CC;
    float y[CC];
    if (K == 21)      CONV1_BODY(21)
    else if (K == 15) CONV1_BODY(15)
    else if (K == 9)  CONV1_BODY(9)
    else if (K == 5)  CONV1_BODY(5)
    else {
        int pad = (K - 1) >> 1;
        int base0 = 16 + t - pad;
        for (int c = 0; c < CC; ++c) {
            float acc = b1v[c];
            const float* wr = ws + c * K;
            for (int k = 0; k < K; ++k) acc += xs[base0 + k] * wr[k];
            y[c] = acc;
        }
    }
    if (act) {
        size_t outBase = (((size_t)(br * BB + b) * CC) * NAA + na) * T0 + t;
        #pragma unroll
        for (int c = 0; c < CC; ++c) g_y1[outBase + (size_t)c * NAA * T0] = y[c];
    }

    float pv[8];
    #pragma unroll
    for (int gq = 0; gq < 4; ++gq) {
        float a0 = act ? y[2 * gq] : 0.f;
        float a1 = act ? y[2 * gq + 1] : 0.f;
        pv[gq]     = a0 + a1;
        pv[4 + gq] = a0 * a0 + a1 * a1;
    }
    #pragma unroll
    for (int v = 0; v < 8; ++v)
        #pragma unroll
        for (int o = 16; o; o >>= 1) pv[v] += __shfl_xor_sync(0xffffffffu, pv[v], o);
    if (lane == 0) {
        #pragma unroll
        for (int v = 0; v < 8; ++v) wred[wid][v] = pv[v];
    }
    __syncthreads();
    if (tid < 8) {
        float s = 0.f;
        #pragma unroll
        for (int ww = 0; ww < 8; ++ww) s += wred[ww][tid];
        int gq = tid & 3, which = tid >> 2;
        g_part1[((which * (NBR * BB) + br * BB + b) * 4 + gq) * NAA + na] = s;
    }
}

// ---------------- conv2: GN1(from partials)+gelu+pool2 + conv + stat2 partials ----------------
#define CONV2_TAPS(KV) { \
    const int base0 = 8 + t - ((KV - 1) >> 1); \
    _Pragma("unroll") \
    for (int it = 0; it < 4; ++it) { \
        int co = 2 * it + hi; \
        float acc = b2[br * CC + co]; \
        _Pragma("unroll") \
        for (int ci = 0; ci < CC; ++ci) { \
            const float* wr = ws + (co * CC + ci) * KV; \
            const float* yr = &yin[ci][base0]; \
            _Pragma("unroll") \
            for (int k = 0; k < KV; ++k) acc += yr[k] * wr[k]; \
        } \
        accv[it] = acc; \
    } }

__global__ void conv2_kernel(const float* __restrict__ w0, const float* __restrict__ w1,
                             const float* __restrict__ w2, const float* __restrict__ w3,
                             const float* __restrict__ b2,
                             const float* __restrict__ g1, const float* __restrict__ be1,
                             int k0, int k1, int k2, int k3)
{
    int na = blockIdx.x, b = blockIdx.y, br = blockIdx.z;
    int tid = threadIdx.x, lane = tid & 31, wid = tid >> 5;

    const float* w; int K;
    if (br == 0)      { w = w0; K = k0; }
    else if (br == 1) { w = w1; K = k1; }
    else if (br == 2) { w = w2; K = k2; }
    else              { w = w3; K = k3; }

    __shared__ float yin[CC][T1 + 16];
    __shared__ float ws[CC * CC * 12];
    __shared__ float2 st[4];
    __shared__ float wred[8][8];

    if (wid < 4) {
        float s = 0.f, q = 0.f;
        int b0 = ((br * BB + b) * 4 + wid) * NAA;
        #pragma unroll
        for (int j = 0; j < 4; ++j) {
            s += g_part1[b0 + lane + 32 * j];
            q += g_part1[NBR * BB * 4 * NAA + b0 + lane + 32 * j];
        }
        #pragma unroll
        for (int o = 16; o; o >>= 1) {
            s += __shfl_xor_sync(0xffffffffu, s, o);
            q += __shfl_xor_sync(0xffffffffu, q, o);
        }
        if (lane == 0) {
            float n = 2.0f * NAA * T0;
            float m = s / n;
            float var = q / n - m * m;
            st[wid] = make_float2(m, rsqrtf(var + 1e-5f));
        }
    }
    for (int i = tid; i < CC * CC * K; i += 256) ws[i] = w[i];

    int hi = (tid >= 100) ? 1 : 0;
    int t  = tid - 100 * hi;
    bool act = (tid < 200);
    if (tid >= 200) {
        for (int i = tid - 200; i < 128; i += 56) {
            int ch = i >> 4, j = i & 15;
            yin[ch][(j < 8) ? j : (100 + j)] = 0.f;
        }
    }
    __syncthreads();

    #pragma unroll
    for (int it = 0; it < 4; ++it) {
        int ci = 2 * it + hi;
        if (act) {
            float m = st[ci >> 1].x, r = st[ci >> 1].y;
            float sc = r * g1[br * CC + ci];
            float sh = be1[br * CC + ci] - m * sc;
            size_t base = (((size_t)(br * BB + b) * CC + ci) * NAA + na) * T0 + 2 * t;
            float a0 = gelu_exact(g_y1[base]     * sc + sh);
            float a1 = gelu_exact(g_y1[base + 1] * sc + sh);
            yin[ci][8 + t] = 0.5f * (a0 + a1);
        }
    }
    __syncthreads();

    float accv[4] = {0.f, 0.f, 0.f, 0.f};
    if (act) {
        if (K == 9)      CONV2_TAPS(9)
        else if (K == 7) CONV2_TAPS(7)
        else if (K == 5) CONV2_TAPS(5)
        else if (K == 3) CONV2_TAPS(3)
        else {
            int base0 = 8 + t - ((K - 1) >> 1);
            for (int it = 0; it < 4; ++it) {
                int co = 2 * it + hi;
                float acc = b2[br * CC + co];
                for (int ci = 0; ci < CC; ++ci) {
                    const float* wr = ws + (co * CC + ci) * K;
                    const float* yr = &yin[ci][base0];
                    for (int k = 0; k < K; ++k) acc += yr[k] * wr[k];
                }
                accv[it] = acc;
            }
        }
        #pragma unroll
        for (int it = 0; it < 4; ++it) {
            int co = 2 * it + hi;
            g_y3[(((size_t)(br * BB + b) * CC + co) * NAA + na) * T1 + t] = accv[it];
        }
    }

    float pv[8];
    #pragma unroll
    for (int it = 0; it < 4; ++it) {
        float a = act ? accv[it] : 0.f;
        pv[it] = a;
        pv[4 + it] = a * a;
    }
    #pragma unroll
    for (int v = 0; v < 8; ++v)
        #pragma unroll
        for (int o = 16; o; o >>= 1) pv[v] += __shfl_xor_sync(0xffffffffu, pv[v], o);
    if (lane == 0) {
        #pragma unroll
        for (int v = 0; v < 8; ++v) wred[wid][v] = pv[v];
    }
    __syncthreads();
    if (tid < 8) {
        float s = 0.f;
        #pragma unroll
        for (int ww = 0; ww < 8; ++ww) s += wred[ww][tid];
        int gq = tid & 3, which = tid >> 2;
        g_part2[((which * (NBR * BB) + br * BB + b) * 4 + gq) * NAA + na] = s;
    }
}

// ---------------- feats (GN2+gelu+pool4+transpose) fused with codebook pack+cnorm ----------------
__global__ void feats_pack_kernel(const float* __restrict__ cbAll,
                                  const float* __restrict__ g2, const float* __restrict__ be2)
{
    int bx = blockIdx.x, b = blockIdx.y, br = blockIdx.z;
    int tid = threadIdx.x, lane = tid & 31, wid = tid >> 5;

    if (bx >= NAA) {
        // ---- pack part: warp per code (bf16 hi only) + exact fp32 norms ----
        int px = bx - NAA;
        int cid = (px * BB + b) * 8 + wid;
        size_t gcode = (size_t)br * (NQ * VV) + cid;
        const float* src = cbAll + gcode * DD;
        uint32_t* dh = g_cbh + gcode * (KPAD / 2);
        float s = 0.f;
        #pragma unroll
        for (int p = lane; p < DD / 2; p += 32) {
            float v0 = src[2 * p], v1 = src[2 * p + 1];
            s += v0 * v0 + v1 * v1;
            __nv_bfloat16 h0 = __float2bfloat16(v0), h1 = __float2bfloat16(v1);
            dh[p] = ((uint32_t)__bfloat16_as_ushort(h1) << 16) | __bfloat16_as_ushort(h0);
        }
        #pragma unroll
        for (int o = 16; o; o >>= 1) s += __shfl_xor_sync(0xffffffffu, s, o);
        if (lane == 0) g_cnorm[gcode] = s;
        return;
    }

    // ---- feats part ----
    int na = bx;
    __shared__ float2 st[4];
    if (wid < 4) {
        float s = 0.f, q = 0.f;
        int b0 = ((br * BB + b) * 4 + wid) * NAA;
        #pragma unroll
        for (int j = 0; j < 4; ++j) {
            s += g_part2[b0 + lane + 32 * j];
            q += g_part2[NBR * BB * 4 * NAA + b0 + lane + 32 * j];
        }
        #pragma unroll
        for (int o = 16; o; o >>= 1) {
            s += __shfl_xor_sync(0xffffffffu, s, o);
            q += __shfl_xor_sync(0xffffffffu, q, o);
        }
        if (lane == 0) {
            float n = 2.0f * NAA * T1;
            float m = s / n;
            float var = q / n - m * m;
            st[wid] = make_float2(m, rsqrtf(var + 1e-5f));
        }
    }
    __syncthreads();

    int d = tid;
    if (d >= DD) return;
    int t = d >> 3;
    int c = d & 7;
    float m = st[c >> 1].x, r = st[c >> 1].y;
    float sc = r * g2[br * CC + c];
    float sh = be2[br * CC + c] - m * sc;

    size_t base = (((size_t)(br * BB + b) * CC + c) * NAA + na) * T1 + 4 * t;
    float v = 0.25f * (gelu_exact(g_y3[base]     * sc + sh) +
                       gelu_exact(g_y3[base + 1] * sc + sh) +
                       gelu_exact(g_y3[base + 2] * sc + sh) +
                       gelu_exact(g_y3[base + 3] * sc + sh));
    int row = b * NAA + na;
    size_t fi = ((size_t)br * ROWS + row) * DD + d;
    g_feats[fi] = v;
    g_res[fi]   = v;
    g_quant[fi] = 0.0f;
    g_res_hi[((size_t)((br << 10) + row)) * KPAD + d] = __float2bfloat16(v);
}

// ---------------- mma.sync distance GEMM + per-tile top-2 epilogue ----------------
// grid (8 rowtiles, 4 br, 64 coltiles), block 256 (8 warps, 2x4), warp tile 64x32.
// Single-term coarse distance hi_a·hi_b (sigma ~0.02); exact fp32 rerank over
// top-2/tile within RERANK_DELTA recovers indices. 3-stage cp.async pipeline.
__global__ void __launch_bounds__(256, 2) gemm_step_kernel(int step)
{
    extern __shared__ char dsm[];
    __shared__ float cns[NT];

    int tid = threadIdx.x;
    int lane = tid & 31;
    int wid = tid >> 5;
    int warpM = wid & 1;
    int warpN = wid >> 1;
    int g  = lane >> 2;
    int tig = lane & 3;

    int rowBase = blockIdx.x * 128;
    int br = blockIdx.y;
    int ct = blockIdx.z;
    int brq = br * NQ + step;

    const __nv_bfloat16* aH = g_res_hi + (size_t)((br << 10) + rowBase) * KPAD;
    const __nv_bfloat16* bH = (const __nv_bfloat16*)g_cbh + ((size_t)brq * VV + (size_t)ct * NT) * KPAD;

    if (tid < NT) cns[tid] = g_cnorm[(size_t)brq * VV + ct * NT + tid];

    // one 16B cp.async per thread per slab; slabs: aH, bH
    auto load_chunk = [&](int buf, int k0) {
        char* base = dsm + buf * BUF_B;
        int row = tid >> 1, seg = tid & 1;
        uint32_t d0 = smem_u32(base + row * 48 + seg * 16);
        CP_ASYNC16(d0,          aH + (size_t)row * KPAD + k0 + seg * 8);
        CP_ASYNC16(d0 + SLAB_B, bH + (size_t)row * KPAD + k0 + seg * 8);
        CP_COMMIT();
    };

    float acc[4][4][4];
    #pragma unroll
    for (int t = 0; t < 4; ++t)
        #pragma unroll
        for (int n = 0; n < 4; ++n)
            #pragma unroll
            for (int e = 0; e < 4; ++e) acc[t][n][e] = 0.f;

    load_chunk(0, 0);
    load_chunk(1, KC);

    #pragma unroll 1
    for (int c = 0; c < NCH; ++c) {
        if (c + 2 < NCH) CP_WAIT(1);   // chunk c done; c+1 may be in flight
        else             CP_WAIT(0);   // drain at the tail
        __syncthreads();               // chunk c visible; buf (c+2)%3 free
        if (c + 2 < NCH) load_chunk((c + 2) % NSTAGE, (c + 2) * KC);

        const char* base = dsm + (c % NSTAGE) * BUF_B;
        const char* aHs = base;
        const char* bHs = base + SLAB_B;

        uint32_t bh[4][2];
        #pragma unroll
        for (int n = 0; n < 4; ++n) {
            int c0 = warpN * 32 + n * 8 + g;
            const char* pb = bHs + c0 * 48 + tig * 4;
            bh[n][0] = *(const uint32_t*)pb;
            bh[n][1] = *(const uint32_t*)(pb + 16);
        }
        #pragma unroll
        for (int t = 0; t < 4; ++t) {
            int r0 = warpM * 64 + t * 16 + g;
            const char* pa = aHs + r0 * 48 + tig * 4;
            uint32_t a0 = *(const uint32_t*)pa;
            uint32_t a1 = *(const uint32_t*)(pa + 8 * 48);
            uint32_t a2 = *(const uint32_t*)(pa + 16);
            uint32_t a3 = *(const uint32_t*)(pa + 8 * 48 + 16);
            #pragma unroll
            for (int n = 0; n < 4; ++n)
                mma_bf16(acc[t][n], a0, a1, a2, a3, bh[n][0], bh[n][1]);
        }
    }
    __syncthreads();   // all compute done before epilogue reuses smem

    // ---- epilogue: per-row top-2 across the 128-code tile ----
    unsigned long long* red = (unsigned long long*)dsm;   // [128][4][2]

    #pragma unroll
    for (int t = 0; t < 4; ++t) {
        #pragma unroll
        for (int rs = 0; rs < 2; ++rs) {
            unsigned long long k1 = ~0ull, k2 = ~0ull;
            #pragma unroll
            for (int n = 0; n < 4; ++n) {
                int lc = warpN * 32 + n * 8 + tig * 2;
                int gc = ct * NT + lc;
                float d0 = cns[lc]     - 2.0f * acc[t][n][rs * 2 + 0];
                float d1 = cns[lc + 1] - 2.0f * acc[t][n][rs * 2 + 1];
                unsigned long long ka = ((unsigned long long)fkey(d0) << 32) | (unsigned)gc;
                unsigned long long kb = ((unsigned long long)fkey(d1) << 32) | (unsigned)(gc + 1);
                if (ka < k1) { k2 = k1; k1 = ka; } else if (ka < k2) k2 = ka;
                if (kb < k1) { k2 = k1; k1 = kb; } else if (kb < k2) k2 = kb;
            }
            #pragma unroll
            for (int off = 1; off <= 2; off <<= 1) {
                unsigned long long o1 = __shfl_xor_sync(0xffffffffu, k1, off);
                unsigned long long o2 = __shfl_xor_sync(0xffffffffu, k2, off);
                unsigned long long n1 = (k1 < o1) ? k1 : o1;
                unsigned long long mx = (k1 < o1) ? o1 : k1;
                unsigned long long mn2 = (k2 < o2) ? k2 : o2;
                k1 = n1;
                k2 = (mx < mn2) ? mx : mn2;
            }
            if (tig == 0) {
                int row = warpM * 64 + t * 16 + rs * 8 + g;
                red[(row * 4 + warpN) * 2 + 0] = k1;
                red[(row * 4 + warpN) * 2 + 1] = k2;
            }
        }
    }
    __syncthreads();

    if (tid < 128) {
        unsigned long long b1 = ~0ull, b2 = ~0ull;
        #pragma unroll
        for (int w = 0; w < 4; ++w)
            #pragma unroll
            for (int e = 0; e < 2; ++e) {
                unsigned long long k = red[(tid * 4 + w) * 2 + e];
                if (k < b1) { b2 = b1; b1 = k; } else if (k < b2) b2 = k;
            }
        size_t ci = ((size_t)((br << 10) + rowBase + tid)) * (NTILES * 2) + ct * 2;
        g_cand[ci] = b1;
        g_cand[ci + 1] = b2;
    }
}

// ---------------- rerank (exact fp32 within delta) + update ----------------
__global__ void rerank_update_kernel(const float* __restrict__ cbAll, int step)
{
    int row = blockIdx.x, br = blockIdx.y;
    int tid = threadIdx.x, lane = tid & 31, w = tid >> 5;

    __shared__ float rsm[DD];
    __shared__ unsigned long long keys[NTILES * 2];
    __shared__ unsigned long long sBest, sExact;

    size_t rbase = ((size_t)br * ROWS + row) * DD;
    if (tid < DD) rsm[tid] = g_res[rbase + tid];
    if (tid < NTILES * 2) keys[tid] = g_cand[((size_t)((br << 10) + row)) * (NTILES * 2) + tid];
    if (tid == 0) { sBest = ~0ull; sExact = ~0ull; }
    __syncthreads();
    if (tid < NTILES * 2) atomicMin(&sBest, keys[tid]);
    __syncthreads();

    float bestA = fkey_inv((unsigned)(sBest >> 32));
    const float* cbq = cbAll + (size_t)(br * NQ + step) * VV * DD;
    const float* cnq = g_cnorm + (size_t)(br * NQ + step) * VV;

    for (int c = w; c < NTILES * 2; c += 8) {
        unsigned long long k = keys[c];
        float da = fkey_inv((unsigned)(k >> 32));
        if (da <= bestA + RERANK_DELTA) {
            int code = (int)(k & 0xFFFFFFFFull);
            const float* cr = cbq + (size_t)code * DD;
            float dot = 0.f;
            for (int d = lane; d < DD; d += 32) dot += rsm[d] * cr[d];
            #pragma unroll
            for (int o = 16; o; o >>= 1) dot += __shfl_xor_sync(0xffffffffu, dot, o);
            if (lane == 0) {
                float de = cnq[code] - 2.0f * dot;
                unsigned long long ke = ((unsigned long long)fkey(de) << 32) | (unsigned)code;
                atomicMin(&sExact, ke);
            }
        }
    }
    __syncthreads();

    int idx = (int)(sExact & 0xFFFFFFFFull);
    const float* q = cbq + (size_t)idx * DD;
    if (tid < DD) {
        float qv = q[tid];
        float r = rsm[tid] - qv;
        g_res[rbase + tid] = r;
        g_quant[rbase + tid] += qv;
        g_res_hi[((size_t)((br << 10) + row)) * KPAD + tid] = __float2bfloat16(r);
    }
    if (tid == 0) g_idx[(br * NQ + step) * ROWS + row] = idx;
}

// ---------------- final output ----------------
__global__ void final_kernel(float* __restrict__ out, int n)
{
    int i = blockIdx.x * 256 + threadIdx.x;
    if (i >= n) return;
    if (i < N_FT) {
        float f = g_feats[i];
        out[i] = f + (g_quant[i] - f);
    } else {
        int j = i - N_FT;
        out[i] = (j < N_IDX) ? (float)g_idx[j] : 0.0f;
    }
}

// ---------------- launch ----------------
extern "C" void kernel_launch(void* const* d_in, const int* in_sizes, int n_in,
                              void* d_out, int out_size)
{
    const float* x   = (const float*)d_in[0];
    const float* w11 = (const float*)d_in[1];
    const float* w12 = (const float*)d_in[2];
    const float* w13 = (const float*)d_in[3];
    const float* w14 = (const float*)d_in[4];
    const float* b1  = (const float*)d_in[5];
    const float* g1  = (const float*)d_in[6];
    const float* be1 = (const float*)d_in[7];
    const float* w21 = (const float*)d_in[8];
    const float* w22 = (const float*)d_in[9];
    const float* w23 = (const float*)d_in[10];
    const float* w24 = (const float*)d_in[11];
    const float* b2  = (const float*)d_in[12];
    const float* g2  = (const float*)d_in[13];
    const float* be2 = (const float*)d_in[14];
    const float* cb  = (const float*)d_in[15];

    int K1a = in_sizes[1] / CC,  K1b = in_sizes[2] / CC;
    int K1c = in_sizes[3] / CC,  K1d = in_sizes[4] / CC;
    int K2a = in_sizes[8] / (CC * CC),  K2b = in_sizes[9] / (CC * CC);
    int K2c = in_sizes[10] / (CC * CC), K2d = in_sizes[11] / (CC * CC);

    cudaFuncSetAttribute(gemm_step_kernel, cudaFuncAttributeMaxDynamicSharedMemorySize, DSMEM);

    conv1_kernel<<<dim3(NAA, BB, NBR), 256>>>(x, w11, w12, w13, w14, b1, K1a, K1b, K1c, K1d);
    conv2_kernel<<<dim3(NAA, BB, NBR), 256>>>(w21, w22, w23, w24, b2, g1, be1, K2a, K2b, K2c, K2d);
    feats_pack_kernel<<<dim3(NAA + 1024, BB, NBR), 256>>>(cb, g2, be2);

    for (int s = 0; s < NQ; ++s) {
        gemm_step_kernel<<<dim3(ROWS / 128, NBR, NTILES), 256, DSMEM>>>(s);
        rerank_update_kernel<<<dim3(ROWS, NBR), 256>>>(cb, s);
    }

    final_kernel<<<(out_size + 255) / 256, 256>>>((float*)d_out, out_size);
}

// round 12
// speedup vs baseline: 3.0902x; 1.0811x over previous
#include <cuda_runtime.h>
#include <cuda_bf16.h>
#include <cstdint>

// ---------------- problem constants ----------------
#define NBR 4
#define BB  8
#define CC  8
#define NAA 128
#define T0  200
#define T1  100
#define DD  200
#define VV  8192
#define NQ  8
#define ROWS (BB*NAA)        // 1024

#define N_Y1  (NBR*BB*CC*NAA*T0)
#define N_Y3  (NBR*BB*CC*NAA*T1)
#define N_FT  (NBR*ROWS*DD)
#define N_IDX (NBR*NQ*ROWS)

#define KPAD 208             // padded K (bf16): 200 data + 8 zeros, 13 x 16
#define KC   16              // K chunk (one k16 per chunk)
#define NCH  (KPAD/KC)       // 13
#define NT   128             // codes per col tile
#define NTILES (VV/NT)       // 64
#define RERANK_DELTA 0.25f   // wide exact-rerank window (>10 sigma of coarse noise)

// smem slab: 128 rows x 16 bf16 (32B) padded to 48B per row
#define SLAB_B 6144          // 128*48
#define BUF_B  (2*SLAB_B)    // a_hi, b_hi = 12288
#define NSTAGE 3
#define DSMEM  (NSTAGE*BUF_B)   // 36864

// ---------------- scratch ----------------
// Arrays touched by cp.async / vector loads are force-aligned to 16B —
// cp.async.16 faults on misaligned global addresses; base alignment of
// __device__ arrays is otherwise layout-dependent (R8 failure mode).
__device__ float g_y1[N_Y1];
__device__ float g_y3[N_Y3];
__device__ float g_part1[2*NBR*BB*4*NAA];    // [which][br,b,group][na]
__device__ float g_part2[2*NBR*BB*4*NAA];
__device__ float g_feats[N_FT];
__device__ float g_res[N_FT];
__device__ float g_quant[N_FT];
__device__ float g_cnorm[NBR*NQ*VV];
__device__ int   g_idx[N_IDX];
__device__ __align__(16) uint32_t g_cbh[(size_t)NBR*NQ*VV*(KPAD/2)];  // bf16 hi image; pads stay 0
__device__ __align__(16) __nv_bfloat16 g_res_hi[NBR*ROWS*KPAD];       // zero-init pads stay zero
__device__ __align__(16) unsigned long long g_cand[(size_t)NBR*ROWS*NTILES*2];

// ---------------- helpers ----------------
__device__ __forceinline__ float gelu_exact(float v) {
    return 0.5f * v * (1.0f + erff(v * 0.70710678118654752440f));
}
__device__ __forceinline__ unsigned fkey(float f) {
    unsigned u = __float_as_uint(f);
    return (u & 0x80000000u) ? ~u : (u | 0x80000000u);
}
__device__ __forceinline__ float fkey_inv(unsigned k) {
    unsigned u = (k & 0x80000000u) ? (k & 0x7FFFFFFFu) : ~k;
    return __uint_as_float(u);
}
__device__ __forceinline__ uint32_t smem_u32(const void* p) {
    uint32_t a;
    asm("{ .reg .u64 t; cvta.to.shared.u64 t, %1; cvt.u32.u64 %0, t; }" : "=r"(a) : "l"(p));
    return a;
}
#define CP_ASYNC16(dst, src) \
    asm volatile("cp.async.cg.shared.global [%0], [%1], 16;" :: "r"(dst), "l"(src))
#define CP_COMMIT() asm volatile("cp.async.commit_group;" ::: "memory")
#define CP_WAIT(n)  asm volatile("cp.async.wait_group %0;" :: "n"(n) : "memory")

__device__ __forceinline__ void mma_bf16(float* c,
    uint32_t a0, uint32_t a1, uint32_t a2, uint32_t a3, uint32_t b0, uint32_t b1)
{
    asm volatile("mma.sync.aligned.m16n8k16.row.col.f32.bf16.bf16.f32 "
        "{%0,%1,%2,%3}, {%4,%5,%6,%7}, {%8,%9}, {%0,%1,%2,%3};"
        : "+f"(c[0]), "+f"(c[1]), "+f"(c[2]), "+f"(c[3])
        : "r"(a0), "r"(a1), "r"(a2), "r"(a3), "r"(b0), "r"(b1));
}
__device__ __forceinline__ void ldmatrix_x4(uint32_t& r0, uint32_t& r1,
                                            uint32_t& r2, uint32_t& r3, uint32_t addr)
{
    asm volatile("ldmatrix.sync.aligned.m8n8.x4.shared.b16 {%0,%1,%2,%3}, [%4];"
        : "=r"(r0), "=r"(r1), "=r"(r2), "=r"(r3) : "r"(addr));
}

// ---------------- conv1: fused group-stat partials; K-specialized ----------------
#define CONV1_BODY(KV) { \
    const int base0 = 16 + t - ((KV - 1) >> 1); \
    _Pragma("unroll") \
    for (int c = 0; c < CC; ++c) { \
        float acc = b1v[c]; \
        const float* wr = ws + c * KV; \
        _Pragma("unroll") \
        for (int k = 0; k < KV; ++k) acc += xs[base0 + k] * wr[k]; \
        y[c] = acc; \
    } }

__global__ void conv1_kernel(const float* __restrict__ x,
                             const float* __restrict__ w0, const float* __restrict__ w1,
                             const float* __restrict__ w2, const float* __restrict__ w3,
                             const float* __restrict__ b1,
                             int k0, int k1, int k2, int k3)
{
    int na = blockIdx.x, b = blockIdx.y, br = blockIdx.z;
    int tid = threadIdx.x, lane = tid & 31, wid = tid >> 5;

    const float* w; int K;
    if (br == 0)      { w = w0; K = k0; }
    else if (br == 1) { w = w1; K = k1; }
    else if (br == 2) { w = w2; K = k2; }
    else              { w = w3; K = k3; }

    __shared__ float xs[T0 + 32];
    __shared__ float ws[CC * 24];
    __shared__ float wred[8][8];

    if (tid < T0) xs[16 + tid] = x[(size_t)(b * NAA + na) * T0 + tid];
    else if (tid < T0 + 16) xs[tid - T0] = 0.f;
    else if (tid < T0 + 32) xs[tid] = 0.f;
    if (tid < CC * K) ws[tid] = w[tid];
    __syncthreads();

    bool act = tid < T0;
    int t = act ? tid : 0;
    const float* b1v = b1 + br * CC;
    float y[CC];
    if (K == 21)      CONV1_BODY(21)
    else if (K == 15) CONV1_BODY(15)
    else if (K == 9)  CONV1_BODY(9)
    else if (K == 5)  CONV1_BODY(5)
    else {
        int pad = (K - 1) >> 1;
        int base0 = 16 + t - pad;
        for (int c = 0; c < CC; ++c) {
            float acc = b1v[c];
            const float* wr = ws + c * K;
            for (int k = 0; k < K; ++k) acc += xs[base0 + k] * wr[k];
            y[c] = acc;
        }
    }
    if (act) {
        size_t outBase = (((size_t)(br * BB + b) * CC) * NAA + na) * T0 + t;
        #pragma unroll
        for (int c = 0; c < CC; ++c) g_y1[outBase + (size_t)c * NAA * T0] = y[c];
    }

    float pv[8];
    #pragma unroll
    for (int gq = 0; gq < 4; ++gq) {
        float a0 = act ? y[2 * gq] : 0.f;
        float a1 = act ? y[2 * gq + 1] : 0.f;
        pv[gq]     = a0 + a1;
        pv[4 + gq] = a0 * a0 + a1 * a1;
    }
    #pragma unroll
    for (int v = 0; v < 8; ++v)
        #pragma unroll
        for (int o = 16; o; o >>= 1) pv[v] += __shfl_xor_sync(0xffffffffu, pv[v], o);
    if (lane == 0) {
        #pragma unroll
        for (int v = 0; v < 8; ++v) wred[wid][v] = pv[v];
    }
    __syncthreads();
    if (tid < 8) {
        float s = 0.f;
        #pragma unroll
        for (int ww = 0; ww < 8; ++ww) s += wred[ww][tid];
        int gq = tid & 3, which = tid >> 2;
        g_part1[((which * (NBR * BB) + br * BB + b) * 4 + gq) * NAA + na] = s;
    }
}

// ---------------- conv2: GN1(from partials)+gelu+pool2 + conv + stat2 partials ----------------
#define CONV2_TAPS(KV) { \
    const int base0 = 8 + t - ((KV - 1) >> 1); \
    _Pragma("unroll") \
    for (int it = 0; it < 4; ++it) { \
        int co = 2 * it + hi; \
        float acc = b2[br * CC + co]; \
        _Pragma("unroll") \
        for (int ci = 0; ci < CC; ++ci) { \
            const float* wr = ws + (co * CC + ci) * KV; \
            const float* yr = &yin[ci][base0]; \
            _Pragma("unroll") \
            for (int k = 0; k < KV; ++k) acc += yr[k] * wr[k]; \
        } \
        accv[it] = acc; \
    } }

__global__ void conv2_kernel(const float* __restrict__ w0, const float* __restrict__ w1,
                             const float* __restrict__ w2, const float* __restrict__ w3,
                             const float* __restrict__ b2,
                             const float* __restrict__ g1, const float* __restrict__ be1,
                             int k0, int k1, int k2, int k3)
{
    int na = blockIdx.x, b = blockIdx.y, br = blockIdx.z;
    int tid = threadIdx.x, lane = tid & 31, wid = tid >> 5;

    const float* w; int K;
    if (br == 0)      { w = w0; K = k0; }
    else if (br == 1) { w = w1; K = k1; }
    else if (br == 2) { w = w2; K = k2; }
    else              { w = w3; K = k3; }

    __shared__ float yin[CC][T1 + 16];
    __shared__ float ws[CC * CC * 12];
    __shared__ float2 st[4];
    __shared__ float wred[8][8];

    if (wid < 4) {
        float s = 0.f, q = 0.f;
        int b0 = ((br * BB + b) * 4 + wid) * NAA;
        #pragma unroll
        for (int j = 0; j < 4; ++j) {
            s += g_part1[b0 + lane + 32 * j];
            q += g_part1[NBR * BB * 4 * NAA + b0 + lane + 32 * j];
        }
        #pragma unroll
        for (int o = 16; o; o >>= 1) {
            s += __shfl_xor_sync(0xffffffffu, s, o);
            q += __shfl_xor_sync(0xffffffffu, q, o);
        }
        if (lane == 0) {
            float n = 2.0f * NAA * T0;
            float m = s / n;
            float var = q / n - m * m;
            st[wid] = make_float2(m, rsqrtf(var + 1e-5f));
        }
    }
    for (int i = tid; i < CC * CC * K; i += 256) ws[i] = w[i];

    int hi = (tid >= 100) ? 1 : 0;
    int t  = tid - 100 * hi;
    bool act = (tid < 200);
    if (tid >= 200) {
        for (int i = tid - 200; i < 128; i += 56) {
            int ch = i >> 4, j = i & 15;
            yin[ch][(j < 8) ? j : (100 + j)] = 0.f;
        }
    }
    __syncthreads();

    #pragma unroll
    for (int it = 0; it < 4; ++it) {
        int ci = 2 * it + hi;
        if (act) {
            float m = st[ci >> 1].x, r = st[ci >> 1].y;
            float sc = r * g1[br * CC + ci];
            float sh = be1[br * CC + ci] - m * sc;
            size_t base = (((size_t)(br * BB + b) * CC + ci) * NAA + na) * T0 + 2 * t;
            float a0 = gelu_exact(g_y1[base]     * sc + sh);
            float a1 = gelu_exact(g_y1[base + 1] * sc + sh);
            yin[ci][8 + t] = 0.5f * (a0 + a1);
        }
    }
    __syncthreads();

    float accv[4] = {0.f, 0.f, 0.f, 0.f};
    if (act) {
        if (K == 9)      CONV2_TAPS(9)
        else if (K == 7) CONV2_TAPS(7)
        else if (K == 5) CONV2_TAPS(5)
        else if (K == 3) CONV2_TAPS(3)
        else {
            int base0 = 8 + t - ((K - 1) >> 1);
            for (int it = 0; it < 4; ++it) {
                int co = 2 * it + hi;
                float acc = b2[br * CC + co];
                for (int ci = 0; ci < CC; ++ci) {
                    const float* wr = ws + (co * CC + ci) * K;
                    const float* yr = &yin[ci][base0];
                    for (int k = 0; k < K; ++k) acc += yr[k] * wr[k];
                }
                accv[it] = acc;
            }
        }
        #pragma unroll
        for (int it = 0; it < 4; ++it) {
            int co = 2 * it + hi;
            g_y3[(((size_t)(br * BB + b) * CC + co) * NAA + na) * T1 + t] = accv[it];
        }
    }

    float pv[8];
    #pragma unroll
    for (int it = 0; it < 4; ++it) {
        float a = act ? accv[it] : 0.f;
        pv[it] = a;
        pv[4 + it] = a * a;
    }
    #pragma unroll
    for (int v = 0; v < 8; ++v)
        #pragma unroll
        for (int o = 16; o; o >>= 1) pv[v] += __shfl_xor_sync(0xffffffffu, pv[v], o);
    if (lane == 0) {
        #pragma unroll
        for (int v = 0; v < 8; ++v) wred[wid][v] = pv[v];
    }
    __syncthreads();
    if (tid < 8) {
        float s = 0.f;
        #pragma unroll
        for (int ww = 0; ww < 8; ++ww) s += wred[ww][tid];
        int gq = tid & 3, which = tid >> 2;
        g_part2[((which * (NBR * BB) + br * BB + b) * 4 + gq) * NAA + na] = s;
    }
}

// ---------------- feats (GN2+gelu+pool4+transpose) fused with codebook pack+cnorm ----------------
__global__ void feats_pack_kernel(const float* __restrict__ cbAll,
                                  const float* __restrict__ g2, const float* __restrict__ be2)
{
    int bx = blockIdx.x, b = blockIdx.y, br = blockIdx.z;
    int tid = threadIdx.x, lane = tid & 31, wid = tid >> 5;

    if (bx >= NAA) {
        // ---- pack part: warp per code (bf16 hi only) + exact fp32 norms ----
        int px = bx - NAA;
        int cid = (px * BB + b) * 8 + wid;
        size_t gcode = (size_t)br * (NQ * VV) + cid;
        const float* src = cbAll + gcode * DD;
        uint32_t* dh = g_cbh + gcode * (KPAD / 2);
        float s = 0.f;
        #pragma unroll
        for (int p = lane; p < DD / 2; p += 32) {
            float v0 = src[2 * p], v1 = src[2 * p + 1];
            s += v0 * v0 + v1 * v1;
            __nv_bfloat16 h0 = __float2bfloat16(v0), h1 = __float2bfloat16(v1);
            dh[p] = ((uint32_t)__bfloat16_as_ushort(h1) << 16) | __bfloat16_as_ushort(h0);
        }
        #pragma unroll
        for (int o = 16; o; o >>= 1) s += __shfl_xor_sync(0xffffffffu, s, o);
        if (lane == 0) g_cnorm[gcode] = s;
        return;
    }

    // ---- feats part ----
    int na = bx;
    __shared__ float2 st[4];
    if (wid < 4) {
        float s = 0.f, q = 0.f;
        int b0 = ((br * BB + b) * 4 + wid) * NAA;
        #pragma unroll
        for (int j = 0; j < 4; ++j) {
            s += g_part2[b0 + lane + 32 * j];
            q += g_part2[NBR * BB * 4 * NAA + b0 + lane + 32 * j];
        }
        #pragma unroll
        for (int o = 16; o; o >>= 1) {
            s += __shfl_xor_sync(0xffffffffu, s, o);
            q += __shfl_xor_sync(0xffffffffu, q, o);
        }
        if (lane == 0) {
            float n = 2.0f * NAA * T1;
            float m = s / n;
            float var = q / n - m * m;
            st[wid] = make_float2(m, rsqrtf(var + 1e-5f));
        }
    }
    __syncthreads();

    int d = tid;
    if (d >= DD) return;
    int t = d >> 3;
    int c = d & 7;
    float m = st[c >> 1].x, r = st[c >> 1].y;
    float sc = r * g2[br * CC + c];
    float sh = be2[br * CC + c] - m * sc;

    size_t base = (((size_t)(br * BB + b) * CC + c) * NAA + na) * T1 + 4 * t;
    float v = 0.25f * (gelu_exact(g_y3[base]     * sc + sh) +
                       gelu_exact(g_y3[base + 1] * sc + sh) +
                       gelu_exact(g_y3[base + 2] * sc + sh) +
                       gelu_exact(g_y3[base + 3] * sc + sh));
    int row = b * NAA + na;
    size_t fi = ((size_t)br * ROWS + row) * DD + d;
    g_feats[fi] = v;
    g_res[fi]   = v;
    g_quant[fi] = 0.0f;
    g_res_hi[((size_t)((br << 10) + row)) * KPAD + d] = __float2bfloat16(v);
}

// ---------------- mma.sync distance GEMM + per-tile top-2 epilogue ----------------
// grid (8 rowtiles, 4 br, 64 coltiles), block 256 (8 warps, 2x4), warp tile 64x32.
// Single-term coarse distance hi_a·hi_b; exact fp32 rerank recovers indices.
// Fragments via ldmatrix.x4 (6 per chunk vs 24 scalar LDS). 3-stage cp.async pipeline.
__global__ void __launch_bounds__(256, 2) gemm_step_kernel(int step)
{
    extern __shared__ char dsm[];
    __shared__ float cns[NT];

    int tid = threadIdx.x;
    int lane = tid & 31;
    int wid = tid >> 5;
    int warpM = wid & 1;
    int warpN = wid >> 1;
    int g  = lane >> 2;
    int tig = lane & 3;

    int rowBase = blockIdx.x * 128;
    int br = blockIdx.y;
    int ct = blockIdx.z;
    int brq = br * NQ + step;

    const __nv_bfloat16* aH = g_res_hi + (size_t)((br << 10) + rowBase) * KPAD;
    const __nv_bfloat16* bH = (const __nv_bfloat16*)g_cbh + ((size_t)brq * VV + (size_t)ct * NT) * KPAD;

    if (tid < NT) cns[tid] = g_cnorm[(size_t)brq * VV + ct * NT + tid];

    uint32_t dbase = smem_u32(dsm);
    // ldmatrix lane-offsets (fixed per thread, relative to buffer base):
    // A tile t: matrices {rows0-7 k0-7, rows8-15 k0-7, rows0-7 k8-15, rows8-15 k8-15}
    uint32_t aoff = (uint32_t)(warpM * 64 + (lane & 15)) * 48u + (uint32_t)(lane >> 4) * 16u;
    // B pair p (two n8 tiles): matrices {codes0-7 k0-7, codes0-7 k8-15, codes8-15 k0-7, codes8-15 k8-15}
    uint32_t boff = (uint32_t)SLAB_B
                  + (uint32_t)(warpN * 32 + ((lane >> 4) << 3) + (lane & 7)) * 48u
                  + (uint32_t)((lane >> 3) & 1) * 16u;

    // one 16B cp.async per thread per slab; slabs: aH, bH
    auto load_chunk = [&](int buf, int k0) {
        char* base = dsm + buf * BUF_B;
        int row = tid >> 1, seg = tid & 1;
        uint32_t d0 = smem_u32(base + row * 48 + seg * 16);
        CP_ASYNC16(d0,          aH + (size_t)row * KPAD + k0 + seg * 8);
        CP_ASYNC16(d0 + SLAB_B, bH + (size_t)row * KPAD + k0 + seg * 8);
        CP_COMMIT();
    };

    float acc[4][4][4];
    #pragma unroll
    for (int t = 0; t < 4; ++t)
        #pragma unroll
        for (int n = 0; n < 4; ++n)
            #pragma unroll
            for (int e = 0; e < 4; ++e) acc[t][n][e] = 0.f;

    load_chunk(0, 0);
    load_chunk(1, KC);

    #pragma unroll 1
    for (int c = 0; c < NCH; ++c) {
        if (c + 2 < NCH) CP_WAIT(1);   // chunk c done; c+1 may be in flight
        else             CP_WAIT(0);   // drain at the tail
        __syncthreads();               // chunk c visible; buf (c+2)%3 free
        if (c + 2 < NCH) load_chunk((c + 2) % NSTAGE, (c + 2) * KC);

        uint32_t bufb = dbase + (uint32_t)(c % NSTAGE) * BUF_B;

        uint32_t bh[4][2];
        #pragma unroll
        for (int p = 0; p < 2; ++p) {
            uint32_t r0, r1, r2, r3;
            ldmatrix_x4(r0, r1, r2, r3, bufb + boff + (uint32_t)p * (16u * 48u));
            bh[2 * p][0] = r0;     bh[2 * p][1] = r1;
            bh[2 * p + 1][0] = r2; bh[2 * p + 1][1] = r3;
        }
        #pragma unroll
        for (int t = 0; t < 4; ++t) {
            uint32_t a0, a1, a2, a3;
            ldmatrix_x4(a0, a1, a2, a3, bufb + aoff + (uint32_t)t * (16u * 48u));
            #pragma unroll
            for (int n = 0; n < 4; ++n)
                mma_bf16(acc[t][n], a0, a1, a2, a3, bh[n][0], bh[n][1]);
        }
    }
    __syncthreads();   // all compute done before epilogue reuses smem

    // ---- epilogue: per-row top-2 across the 128-code tile ----
    unsigned long long* red = (unsigned long long*)dsm;   // [128][4][2]

    #pragma unroll
    for (int t = 0; t < 4; ++t) {
        #pragma unroll
        for (int rs = 0; rs < 2; ++rs) {
            unsigned long long k1 = ~0ull, k2 = ~0ull;
            #pragma unroll
            for (int n = 0; n < 4; ++n) {
                int lc = warpN * 32 + n * 8 + tig * 2;
                int gc = ct * NT + lc;
                float d0 = cns[lc]     - 2.0f * acc[t][n][rs * 2 + 0];
                float d1 = cns[lc + 1] - 2.0f * acc[t][n][rs * 2 + 1];
                unsigned long long ka = ((unsigned long long)fkey(d0) << 32) | (unsigned)gc;
                unsigned long long kb = ((unsigned long long)fkey(d1) << 32) | (unsigned)(gc + 1);
                if (ka < k1) { k2 = k1; k1 = ka; } else if (ka < k2) k2 = ka;
                if (kb < k1) { k2 = k1; k1 = kb; } else if (kb < k2) k2 = kb;
            }
            #pragma unroll
            for (int off = 1; off <= 2; off <<= 1) {
                unsigned long long o1 = __shfl_xor_sync(0xffffffffu, k1, off);
                unsigned long long o2 = __shfl_xor_sync(0xffffffffu, k2, off);
                unsigned long long n1 = (k1 < o1) ? k1 : o1;
                unsigned long long mx = (k1 < o1) ? o1 : k1;
                unsigned long long mn2 = (k2 < o2) ? k2 : o2;
                k1 = n1;
                k2 = (mx < mn2) ? mx : mn2;
            }
            if (tig == 0) {
                int row = warpM * 64 + t * 16 + rs * 8 + g;
                red[(row * 4 + warpN) * 2 + 0] = k1;
                red[(row * 4 + warpN) * 2 + 1] = k2;
            }
        }
    }
    __syncthreads();

    if (tid < 128) {
        unsigned long long b1 = ~0ull, b2 = ~0ull;
        #pragma unroll
        for (int w = 0; w < 4; ++w)
            #pragma unroll
            for (int e = 0; e < 2; ++e) {
                unsigned long long k = red[(tid * 4 + w) * 2 + e];
                if (k < b1) { b2 = b1; b1 = k; } else if (k < b2) b2 = k;
            }
        size_t ci = ((size_t)((br << 10) + rowBase + tid)) * (NTILES * 2) + ct * 2;
        g_cand[ci] = b1;
        g_cand[ci + 1] = b2;
    }
}

// ---------------- rerank (exact fp32 within delta) + update ----------------
__global__ void rerank_update_kernel(const float* __restrict__ cbAll, int step)
{
    int row = blockIdx.x, br = blockIdx.y;
    int tid = threadIdx.x, lane = tid & 31, w = tid >> 5;

    __shared__ float rsm[DD];
    __shared__ unsigned long long keys[NTILES * 2];
    __shared__ unsigned long long sBest, sExact;

    size_t rbase = ((size_t)br * ROWS + row) * DD;
    if (tid < DD) rsm[tid] = g_res[rbase + tid];
    if (tid < NTILES * 2) keys[tid] = g_cand[((size_t)((br << 10) + row)) * (NTILES * 2) + tid];
    if (tid == 0) { sBest = ~0ull; sExact = ~0ull; }
    __syncthreads();
    if (tid < NTILES * 2) atomicMin(&sBest, keys[tid]);
    __syncthreads();

    float bestA = fkey_inv((unsigned)(sBest >> 32));
    const float* cbq = cbAll + (size_t)(br * NQ + step) * VV * DD;
    const float* cnq = g_cnorm + (size_t)(br * NQ + step) * VV;

    for (int c = w; c < NTILES * 2; c += 8) {
        unsigned long long k = keys[c];
        float da = fkey_inv((unsigned)(k >> 32));
        if (da <= bestA + RERANK_DELTA) {
            int code = (int)(k & 0xFFFFFFFFull);
            const float* cr = cbq + (size_t)code * DD;
            float dot = 0.f;
            for (int d = lane; d < DD; d += 32) dot += rsm[d] * cr[d];
            #pragma unroll
            for (int o = 16; o; o >>= 1) dot += __shfl_xor_sync(0xffffffffu, dot, o);
            if (lane == 0) {
                float de = cnq[code] - 2.0f * dot;
                unsigned long long ke = ((unsigned long long)fkey(de) << 32) | (unsigned)code;
                atomicMin(&sExact, ke);
            }
        }
    }
    __syncthreads();

    int idx = (int)(sExact & 0xFFFFFFFFull);
    const float* q = cbq + (size_t)idx * DD;
    if (tid < DD) {
        float qv = q[tid];
        float r = rsm[tid] - qv;
        g_res[rbase + tid] = r;
        g_quant[rbase + tid] += qv;
        g_res_hi[((size_t)((br << 10) + row)) * KPAD + tid] = __float2bfloat16(r);
    }
    if (tid == 0) g_idx[(br * NQ + step) * ROWS + row] = idx;
}

// ---------------- final output ----------------
__global__ void final_kernel(float* __restrict__ out, int n)
{
    int i = blockIdx.x * 256 + threadIdx.x;
    if (i >= n) return;
    if (i < N_FT) {
        float f = g_feats[i];
        out[i] = f + (g_quant[i] - f);
    } else {
        int j = i - N_FT;
        out[i] = (j < N_IDX) ? (float)g_idx[j] : 0.0f;
    }
}

// ---------------- launch ----------------
extern "C" void kernel_launch(void* const* d_in, const int* in_sizes, int n_in,
                              void* d_out, int out_size)
{
    const float* x   = (const float*)d_in[0];
    const float* w11 = (const float*)d_in[1];
    const float* w12 = (const float*)d_in[2];
    const float* w13 = (const float*)d_in[3];
    const float* w14 = (const float*)d_in[4];
    const float* b1  = (const float*)d_in[5];
    const float* g1  = (const float*)d_in[6];
    const float* be1 = (const float*)d_in[7];
    const float* w21 = (const float*)d_in[8];
    const float* w22 = (const float*)d_in[9];
    const float* w23 = (const float*)d_in[10];
    const float* w24 = (const float*)d_in[11];
    const float* b2  = (const float*)d_in[12];
    const float* g2  = (const float*)d_in[13];
    const float* be2 = (const float*)d_in[14];
    const float* cb  = (const float*)d_in[15];

    int K1a = in_sizes[1] / CC,  K1b = in_sizes[2] / CC;
    int K1c = in_sizes[3] / CC,  K1d = in_sizes[4] / CC;
    int K2a = in_sizes[8] / (CC * CC),  K2b = in_sizes[9] / (CC * CC);
    int K2c = in_sizes[10] / (CC * CC), K2d = in_sizes[11] / (CC * CC);

    cudaFuncSetAttribute(gemm_step_kernel, cudaFuncAttributeMaxDynamicSharedMemorySize, DSMEM);

    conv1_kernel<<<dim3(NAA, BB, NBR), 256>>>(x, w11, w12, w13, w14, b1, K1a, K1b, K1c, K1d);
    conv2_kernel<<<dim3(NAA, BB, NBR), 256>>>(w21, w22, w23, w24, b2, g1, be1, K2a, K2b, K2c, K2d);
    feats_pack_kernel<<<dim3(NAA + 1024, BB, NBR), 256>>>(cb, g2, be2);

    for (int s = 0; s < NQ; ++s) {
        gemm_step_kernel<<<dim3(ROWS / 128, NBR, NTILES), 256, DSMEM>>>(s);
        rerank_update_kernel<<<dim3(ROWS, NBR), 256>>>(cb, s);
    }

    final_kernel<<<(out_size + 255) / 256, 256>>>((float*)d_out, out_size);
}